// round 1
// baseline (speedup 1.0000x reference)
#include <cuda_runtime.h>
#include <cstdint>

typedef unsigned long long ull;

#define B_    2
#define T_    2048
#define C_    2048
#define NH_   16
#define KVH_  4
#define HD_   128
#define QKVD_ 3072
#define BT_   (B_*T_)

// ---------------- scratch (no allocations allowed) ----------------
__device__ float g_qkv[(size_t)BT_ * QKVD_];
__device__ float g_q[(size_t)B_ * NH_ * T_ * HD_];
__device__ float g_k[(size_t)B_ * KVH_ * T_ * HD_];
__device__ float g_v[(size_t)B_ * KVH_ * T_ * HD_];
__device__ float g_y[(size_t)BT_ * C_];

// ---------------- packed f32x2 helpers (Blackwell FFMA2 path) ----------------
__device__ __forceinline__ ull pack2(float lo, float hi) {
    ull r; asm("mov.b64 %0, {%1,%2};" : "=l"(r) : "f"(lo), "f"(hi)); return r;
}
__device__ __forceinline__ void fma2(ull &acc, ull a, ull b) {
    asm("fma.rn.f32x2 %0, %1, %2, %0;" : "+l"(acc) : "l"(a), "l"(b));
}
__device__ __forceinline__ void mul2(ull &acc, ull a) {
    asm("mul.rn.f32x2 %0, %0, %1;" : "+l"(acc) : "l"(a));
}
__device__ __forceinline__ float2 unpack2(ull v) {
    float lo, hi; asm("mov.b64 {%0,%1}, %2;" : "=f"(lo), "=f"(hi) : "l"(v));
    return make_float2(lo, hi);
}

// ---------------- NT SGEMM: C[M,N] = A[M,K] * B[N,K]^T ----------------
// BM=BN=128, BK=16, 256 threads, 8x8 per-thread micro-tile, f32x2 FMAs.
__global__ __launch_bounds__(256) void sgemm_nt(
    const float* __restrict__ A, const float* __restrict__ Bm,
    float* __restrict__ Cm, int M, int N, int K)
{
    __shared__ float As[16][132];   // [k][m], transposed store
    __shared__ float Bs[16][132];   // [k][n]
    const int tid = threadIdx.x;
    const int ty = tid >> 4, tx = tid & 15;
    const size_t bm = (size_t)blockIdx.y * 128;
    const size_t bn = (size_t)blockIdx.x * 128;

    ull acc[4][8];
#pragma unroll
    for (int i = 0; i < 4; i++)
#pragma unroll
        for (int j = 0; j < 8; j++) acc[i][j] = 0ull;

    for (int k0 = 0; k0 < K; k0 += 16) {
#pragma unroll
        for (int u = 0; u < 2; u++) {
            int idx = tid + u * 256;           // 0..511
            int row = idx >> 2;                // 0..127
            int kg  = (idx & 3) << 2;          // 0,4,8,12
            float4 va = *(const float4*)(A + (bm + row) * (size_t)K + k0 + kg);
            As[kg + 0][row] = va.x; As[kg + 1][row] = va.y;
            As[kg + 2][row] = va.z; As[kg + 3][row] = va.w;
            float4 vb = *(const float4*)(Bm + (bn + row) * (size_t)K + k0 + kg);
            Bs[kg + 0][row] = vb.x; Bs[kg + 1][row] = vb.y;
            Bs[kg + 2][row] = vb.z; Bs[kg + 3][row] = vb.w;
        }
        __syncthreads();
#pragma unroll
        for (int kk = 0; kk < 16; kk++) {
            ulonglong2 a01 = *(const ulonglong2*)&As[kk][ty * 8];
            ulonglong2 a23 = *(const ulonglong2*)&As[kk][ty * 8 + 4];
            float4 b0 = *(const float4*)&Bs[kk][tx * 8];
            float4 b1 = *(const float4*)&Bs[kk][tx * 8 + 4];
            ull a2[4] = { a01.x, a01.y, a23.x, a23.y };
            ull bd[8] = { pack2(b0.x, b0.x), pack2(b0.y, b0.y),
                          pack2(b0.z, b0.z), pack2(b0.w, b0.w),
                          pack2(b1.x, b1.x), pack2(b1.y, b1.y),
                          pack2(b1.z, b1.z), pack2(b1.w, b1.w) };
#pragma unroll
            for (int i = 0; i < 4; i++)
#pragma unroll
                for (int j = 0; j < 8; j++) fma2(acc[i][j], a2[i], bd[j]);
        }
        __syncthreads();
    }

#pragma unroll
    for (int i2 = 0; i2 < 4; i2++) {
        float lo[8], hi[8];
#pragma unroll
        for (int j = 0; j < 8; j++) {
            float2 t = unpack2(acc[i2][j]); lo[j] = t.x; hi[j] = t.y;
        }
        size_t r0 = bm + ty * 8 + 2 * i2;
        float* p0 = Cm + r0 * (size_t)N + bn + tx * 8;
        float* p1 = Cm + (r0 + 1) * (size_t)N + bn + tx * 8;
        *(float4*)p0       = make_float4(lo[0], lo[1], lo[2], lo[3]);
        *(float4*)(p0 + 4) = make_float4(lo[4], lo[5], lo[6], lo[7]);
        *(float4*)p1       = make_float4(hi[0], hi[1], hi[2], hi[3]);
        *(float4*)(p1 + 4) = make_float4(hi[4], hi[5], hi[6], hi[7]);
    }
}

// ---------------- RoPE + RMSNorm transform, split into per-head layout ----------------
// grid (BT, 24): hh 0..15 -> q heads, 16..19 -> k heads, 20..23 -> v heads (copy only)
__global__ __launch_bounds__(128) void qkv_transform(
    const float* __restrict__ qkv, const float* __restrict__ qw,
    const float* __restrict__ kw, const float* __restrict__ fcos,
    const float* __restrict__ fsin, float* __restrict__ q,
    float* __restrict__ k, float* __restrict__ v)
{
    const int bt = blockIdx.x, hh = blockIdx.y;
    const int b = bt >> 11, t = bt & (T_ - 1);
    const int d = threadIdx.x;
    const size_t rowoff = (size_t)bt * QKVD_;

    if (hh >= NH_ + KVH_) {     // v: copy
        int hv = hh - (NH_ + KVH_);
        v[(((size_t)(b * KVH_ + hv)) * T_ + t) * HD_ + d] =
            qkv[rowoff + (size_t)(NH_ + KVH_) * HD_ + hv * HD_ + d];
        return;
    }
    const float* w; float* dst; size_t srcoff;
    if (hh < NH_) {
        w = qw; srcoff = (size_t)hh * HD_;
        dst = q + (((size_t)(b * NH_ + hh)) * T_ + t) * HD_;
    } else {
        int hk = hh - NH_;
        w = kw; srcoff = (size_t)NH_ * HD_ + hk * HD_;
        dst = k + (((size_t)(b * KVH_ + hk)) * T_ + t) * HD_;
    }
    float xv = qkv[rowoff + srcoff + d];
    float other = __shfl_xor_sync(0xffffffffu, xv, 1);
    int i = d >> 1;
    float c = fcos[t * (HD_ / 2) + i];
    float s = fsin[t * (HD_ / 2) + i];
    float val = (d & 1) ? (other * s + xv * c) : (xv * c - other * s);

    float ss = val * val;
#pragma unroll
    for (int off = 16; off; off >>= 1) ss += __shfl_xor_sync(0xffffffffu, ss, off);
    __shared__ float wsum[4];
    if ((d & 31) == 0) wsum[d >> 5] = ss;
    __syncthreads();
    ss = wsum[0] + wsum[1] + wsum[2] + wsum[3];
    float rinv = rsqrtf(ss * (1.0f / HD_) + 1e-6f);
    dst[d] = w[d] * val * rinv;
}

// ---------------- causal flash attention (fp32, f32x2 FMAs) ----------------
// grid (T/64, NH, B), 256 threads. 64 q-rows x 64 k-cols per tile, D=128.
// smem: Qts[128][68] (d-major), Kts[128][68] (d-major, aliased by Ps[64][68]), Vs[64][128]
__global__ __launch_bounds__(256) void flash_attn(
    const float* __restrict__ Qg, const float* __restrict__ Kg,
    const float* __restrict__ Vg, float* __restrict__ Y)
{
    extern __shared__ float sm[];
    float* Qts = sm;                  // 128*68
    float* Kts = sm + 128 * 68;       // 128*68
    float* Vs  = sm + 2 * 128 * 68;   // 64*128
    float* Ps  = Kts;                 // alias (64*68 <= 128*68)

    const int qt = blockIdx.x, h = blockIdx.y, b = blockIdx.z;
    const int tid = threadIdx.x, ty = tid >> 4, tx = tid & 15;
    const int q0 = qt * 64;
    const float* Qp = Qg + (((size_t)(b * NH_ + h)) * T_ + q0) * HD_;
    const float* Kb = Kg + ((size_t)(b * KVH_ + (h >> 2))) * T_ * HD_;
    const float* Vb = Vg + ((size_t)(b * KVH_ + (h >> 2))) * T_ * HD_;
    const float scale = 0.08838834764831845f;   // 1/sqrt(128)

    // load Q tile transposed (d-major), pre-scaled.
    // index map: lanes split (dlow 0..15, r, r+1) -> 2-way max STS conflicts
#pragma unroll 4
    for (int it = 0; it < 32; it++) {
        int idx = it * 256 + tid;
        int dl = idx & 15, r = (idx >> 4) & 63, dh = idx >> 10;
        int d = dh * 16 + dl;
        Qts[d * 68 + r] = Qp[(size_t)r * HD_ + d] * scale;
    }

    float m[4] = { -1e30f, -1e30f, -1e30f, -1e30f };
    float l[4] = { 0.f, 0.f, 0.f, 0.f };
    ull o2[4][4];
#pragma unroll
    for (int i = 0; i < 4; i++)
#pragma unroll
        for (int j = 0; j < 4; j++) o2[i][j] = 0ull;

    for (int kt = 0; kt <= qt; kt++) {
        __syncthreads();   // prev PV done (Ps/Vs free), Qts visible on first iter
        const float* Kp = Kb + (size_t)kt * 64 * HD_;
        const float* Vp = Vb + (size_t)kt * 64 * HD_;
#pragma unroll 4
        for (int it = 0; it < 32; it++) {
            int idx = it * 256 + tid;
            int dl = idx & 15, r = (idx >> 4) & 63, dh = idx >> 10;
            int d = dh * 16 + dl;
            Kts[d * 68 + r] = Kp[(size_t)r * HD_ + d];
            Vs[idx] = Vp[idx];
        }
        __syncthreads();

        // S = Q K^T : s2[i][j2] pairs over k-columns
        ull s2[4][2];
#pragma unroll
        for (int i = 0; i < 4; i++) { s2[i][0] = 0ull; s2[i][1] = 0ull; }
#pragma unroll 4
        for (int kk = 0; kk < 128; kk++) {
            float4 qa = *(const float4*)&Qts[kk * 68 + ty * 4];
            ulonglong2 kb = *(const ulonglong2*)&Kts[kk * 68 + tx * 4];
            ull d0 = pack2(qa.x, qa.x), d1 = pack2(qa.y, qa.y);
            ull d2 = pack2(qa.z, qa.z), d3 = pack2(qa.w, qa.w);
            fma2(s2[0][0], d0, kb.x); fma2(s2[0][1], d0, kb.y);
            fma2(s2[1][0], d1, kb.x); fma2(s2[1][1], d1, kb.y);
            fma2(s2[2][0], d2, kb.x); fma2(s2[2][1], d2, kb.y);
            fma2(s2[3][0], d3, kb.x); fma2(s2[3][1], d3, kb.y);
        }
        float s[4][4];
#pragma unroll
        for (int i = 0; i < 4; i++) {
            float2 t0 = unpack2(s2[i][0]), t1 = unpack2(s2[i][1]);
            s[i][0] = t0.x; s[i][1] = t0.y; s[i][2] = t1.x; s[i][3] = t1.y;
        }
        if (kt == qt) {     // causal mask on diagonal tile
#pragma unroll
            for (int i = 0; i < 4; i++)
#pragma unroll
                for (int j = 0; j < 4; j++)
                    if (tx * 4 + j > ty * 4 + i) s[i][j] = -1e30f;
        }
        __syncthreads();    // everyone done reading Kts before Ps overwrite

        // streaming softmax per row (16 lanes share a row: shfl over half-warp)
#pragma unroll
        for (int i = 0; i < 4; i++) {
            float mx = fmaxf(fmaxf(s[i][0], s[i][1]), fmaxf(s[i][2], s[i][3]));
#pragma unroll
            for (int off = 8; off; off >>= 1)
                mx = fmaxf(mx, __shfl_xor_sync(0xffffffffu, mx, off));
            float mn = fmaxf(m[i], mx);
            float alpha = __expf(m[i] - mn);
            m[i] = mn;
            float p0 = __expf(s[i][0] - mn), p1 = __expf(s[i][1] - mn);
            float p2 = __expf(s[i][2] - mn), p3 = __expf(s[i][3] - mn);
            float ls = p0 + p1 + p2 + p3;
#pragma unroll
            for (int off = 8; off; off >>= 1)
                ls += __shfl_xor_sync(0xffffffffu, ls, off);
            l[i] = l[i] * alpha + ls;
            ull av = pack2(alpha, alpha);
#pragma unroll
            for (int j = 0; j < 4; j++) mul2(o2[i][j], av);
            *(float4*)&Ps[(ty * 4 + i) * 68 + tx * 4] = make_float4(p0, p1, p2, p3);
        }
        __syncthreads();

        // O += P @ V
#pragma unroll 4
        for (int kk = 0; kk < 64; kk++) {
            ulonglong2 va = *(const ulonglong2*)&Vs[kk * 128 + tx * 8];
            ulonglong2 vb = *(const ulonglong2*)&Vs[kk * 128 + tx * 8 + 4];
#pragma unroll
            for (int i = 0; i < 4; i++) {
                float p = Ps[(ty * 4 + i) * 68 + kk];
                ull pd = pack2(p, p);
                fma2(o2[i][0], pd, va.x); fma2(o2[i][1], pd, va.y);
                fma2(o2[i][2], pd, vb.x); fma2(o2[i][3], pd, vb.y);
            }
        }
    }

    // epilogue: normalize and write y[b][t][h*128+c]
#pragma unroll
    for (int i = 0; i < 4; i++) {
        float rl = 1.0f / l[i];
        float ov[8];
#pragma unroll
        for (int j = 0; j < 4; j++) {
            float2 t = unpack2(o2[i][j]);
            ov[2 * j] = t.x * rl; ov[2 * j + 1] = t.y * rl;
        }
        float* yp = Y + ((size_t)(b * T_ + q0 + ty * 4 + i)) * C_ + h * HD_ + tx * 8;
        *(float4*)yp       = make_float4(ov[0], ov[1], ov[2], ov[3]);
        *(float4*)(yp + 4) = make_float4(ov[4], ov[5], ov[6], ov[7]);
    }
}

// ---------------- launch ----------------
extern "C" void kernel_launch(void* const* d_in, const int* in_sizes, int n_in,
                              void* d_out, int out_size)
{
    const float* x      = (const float*)d_in[0];
    const float* w_qkv  = (const float*)d_in[1];
    const float* w_proj = (const float*)d_in[2];
    const float* qw     = (const float*)d_in[3];
    const float* kw     = (const float*)d_in[4];
    const float* fcos   = (const float*)d_in[5];
    const float* fsin   = (const float*)d_in[6];
    float* out = (float*)d_out;

    float *p_qkv, *p_q, *p_k, *p_v, *p_y;
    cudaGetSymbolAddress((void**)&p_qkv, g_qkv);
    cudaGetSymbolAddress((void**)&p_q,   g_q);
    cudaGetSymbolAddress((void**)&p_k,   g_k);
    cudaGetSymbolAddress((void**)&p_v,   g_v);
    cudaGetSymbolAddress((void**)&p_y,   g_y);

    // 1) qkv = x @ w_qkv^T    [4096 x 3072]
    sgemm_nt<<<dim3(QKVD_ / 128, BT_ / 128), 256>>>(x, w_qkv, p_qkv, BT_, QKVD_, C_);

    // 2) RoPE + RMSNorm + head split
    qkv_transform<<<dim3(BT_, NH_ + 2 * KVH_), 128>>>(p_qkv, qw, kw, fcos, fsin,
                                                       p_q, p_k, p_v);

    // 3) causal flash attention -> y [4096 x 2048]
    const int SMEM = (2 * 128 * 68 + 64 * 128) * 4;   // 102400 B
    cudaFuncSetAttribute(flash_attn, cudaFuncAttributeMaxDynamicSharedMemorySize, SMEM);
    flash_attn<<<dim3(T_ / 64, NH_, B_), 256, SMEM>>>(p_q, p_k, p_v, p_y);

    // 4) out = y @ w_proj^T   [4096 x 2048]
    sgemm_nt<<<dim3(C_ / 128, BT_ / 128), 256>>>(p_y, w_proj, out, BT_, C_, C_);
}

// round 5
// speedup vs baseline: 1.6025x; 1.6025x over previous
#include <cuda_runtime.h>
#include <cuda_bf16.h>
#include <cstdint>

typedef unsigned long long ull;

#define B_    2
#define T_    2048
#define C_    2048
#define NH_   16
#define KVH_  4
#define HD_   128
#define QKVD_ 3072
#define BT_   (B_*T_)
#define K_    2048
#define LD2_  4096          // bf16 hi|lo row length

// ---------------- scratch ----------------
__device__ float g_qkv[(size_t)BT_ * QKVD_];
__device__ float g_q[(size_t)B_ * NH_ * T_ * HD_];
__device__ float g_k[(size_t)B_ * KVH_ * T_ * HD_];
__device__ float g_v[(size_t)B_ * KVH_ * T_ * HD_];
__device__ float g_y[(size_t)BT_ * C_];
__device__ __nv_bfloat16 g_xs[(size_t)BT_ * LD2_];      // x hi|lo
__device__ __nv_bfloat16 g_wqkvs[(size_t)QKVD_ * LD2_]; // w_qkv hi|lo
__device__ __nv_bfloat16 g_wprojs[(size_t)C_ * LD2_];   // w_proj hi|lo
__device__ __nv_bfloat16 g_ys[(size_t)BT_ * LD2_];      // y hi|lo

// ---------------- packed f32x2 helpers ----------------
__device__ __forceinline__ ull pack2(float lo, float hi) {
    ull r; asm("mov.b64 %0, {%1,%2};" : "=l"(r) : "f"(lo), "f"(hi)); return r;
}
__device__ __forceinline__ void fma2(ull &acc, ull a, ull b) {
    asm("fma.rn.f32x2 %0, %1, %2, %0;" : "+l"(acc) : "l"(a), "l"(b));
}
__device__ __forceinline__ void mul2(ull &acc, ull a) {
    asm("mul.rn.f32x2 %0, %0, %1;" : "+l"(acc) : "l"(a));
}
__device__ __forceinline__ float2 unpack2(ull v) {
    float lo, hi; asm("mov.b64 {%0,%1}, %2;" : "=f"(lo), "=f"(hi) : "l"(v));
    return make_float2(lo, hi);
}

// ---------------- PTX helpers (sm_80-baseline: cp.async / ldmatrix / mma) ----------------
__device__ __forceinline__ uint32_t smem_u32(const void* p) {
    uint32_t a;
    asm("{ .reg .u64 t; cvta.to.shared.u64 t, %1; cvt.u32.u64 %0, t; }" : "=r"(a) : "l"(p));
    return a;
}
__device__ __forceinline__ void cp16(uint32_t saddr, const void* g) {
    asm volatile("cp.async.cg.shared.global [%0], [%1], 16;" :: "r"(saddr), "l"(g) : "memory");
}
__device__ __forceinline__ void cp_commit() { asm volatile("cp.async.commit_group;" ::: "memory"); }
#define CP_WAIT(n) asm volatile("cp.async.wait_group %0;" :: "n"(n) : "memory")

__device__ __forceinline__ void ldm4(uint32_t* r, uint32_t addr) {
    asm volatile("ldmatrix.sync.aligned.m8n8.x4.shared.b16 {%0,%1,%2,%3}, [%4];"
                 : "=r"(r[0]), "=r"(r[1]), "=r"(r[2]), "=r"(r[3]) : "r"(addr));
}
__device__ __forceinline__ void mma16816(float* c, const uint32_t* a, const uint32_t* b) {
    asm volatile(
        "mma.sync.aligned.m16n8k16.row.col.f32.bf16.bf16.f32 "
        "{%0,%1,%2,%3}, {%4,%5,%6,%7}, {%8,%9}, {%0,%1,%2,%3};"
        : "+f"(c[0]), "+f"(c[1]), "+f"(c[2]), "+f"(c[3])
        : "r"(a[0]), "r"(a[1]), "r"(a[2]), "r"(a[3]), "r"(b[0]), "r"(b[1]));
}

// ---------------- fp32 -> bf16 hi|lo split conversion ----------------
__global__ __launch_bounds__(256) void conv_hilo(
    const float* __restrict__ in, __nv_bfloat16* __restrict__ out, int R)
{
    int i = blockIdx.x * 256 + threadIdx.x;
    int total = R * 512;
    if (i >= total) return;
    int r = i >> 9, c4 = (i & 511) << 2;
    float4 v = *(const float4*)(in + (size_t)r * K_ + c4);
    float f[4] = { v.x, v.y, v.z, v.w };
    __nv_bfloat16 h[4], l[4];
#pragma unroll
    for (int j = 0; j < 4; j++) {
        h[j] = __float2bfloat16_rn(f[j]);
        l[j] = __float2bfloat16_rn(f[j] - __bfloat162float(h[j]));
    }
    __nv_bfloat16* ob = out + (size_t)r * LD2_;
    *(__nv_bfloat162*)(ob + c4)          = __nv_bfloat162(h[0], h[1]);
    *(__nv_bfloat162*)(ob + c4 + 2)      = __nv_bfloat162(h[2], h[3]);
    *(__nv_bfloat162*)(ob + K_ + c4)     = __nv_bfloat162(l[0], l[1]);
    *(__nv_bfloat162*)(ob + K_ + c4 + 2) = __nv_bfloat162(l[2], l[3]);
}

// ---------------- mma.sync bf16-split NT GEMM ----------------
// C[M,N] fp32 = A x B^T with A,B stored as bf16 hi|lo rows of LD2_.
// Tile 128x128, BK=32, 8 warps (2m x 4n), warp tile 64x32 = 4 m16 x 4 n8.
// Smem per stage: Ahi/Alo/Bhi/Blo each [128][40] bf16 (pitch 80B, conflict-free ldmatrix).
#define TILE_A_HI 0
#define TILE_A_LO 10240
#define TILE_B_HI 20480
#define TILE_B_LO 30720
#define STAGE_BYTES 40960
#define NCHUNK_G (K_ / 32)

__device__ __forceinline__ void g_load_stage(
    uint32_t st, const __nv_bfloat16* Ag, const __nv_bfloat16* Bg,
    size_t bm, size_t bn, int kc, int tid)
{
#pragma unroll
    for (int j = 0; j < 2; j++) {
        int idx = tid + j * 256;          // 0..511
        int r = idx >> 2;                 // 0..127
        int c16 = (idx & 3) * 16;         // byte col in smem
        int c = (idx & 3) * 8;            // bf16 col in gmem
        uint32_t d = (uint32_t)r * 80 + c16;
        cp16(st + TILE_A_HI + d, Ag + (bm + r) * LD2_ + kc + c);
        cp16(st + TILE_A_LO + d, Ag + (bm + r) * LD2_ + K_ + kc + c);
        cp16(st + TILE_B_HI + d, Bg + (bn + r) * LD2_ + kc + c);
        cp16(st + TILE_B_LO + d, Bg + (bn + r) * LD2_ + K_ + kc + c);
    }
}

__global__ __launch_bounds__(256) void gemm_mma(
    const __nv_bfloat16* __restrict__ Ag, const __nv_bfloat16* __restrict__ Bg,
    float* __restrict__ Cm, int N)
{
    extern __shared__ char sm[];
    const uint32_t sb = smem_u32(sm);
    const int tid = threadIdx.x;
    const int wid = tid >> 5, lane = tid & 31;
    const size_t bm = (size_t)blockIdx.y * 128;
    const size_t bn = (size_t)blockIdx.x * 128;
    const int wm = (wid & 1) * 64;      // warp m offset
    const int wn = (wid >> 1) * 32;     // warp n offset

    float acc[4][4][4];
#pragma unroll
    for (int i = 0; i < 4; i++)
#pragma unroll
        for (int j = 0; j < 4; j++)
#pragma unroll
            for (int q = 0; q < 4; q++) acc[i][j][q] = 0.f;

    g_load_stage(sb, Ag, Bg, bm, bn, 0, tid);
    cp_commit();

    const int a_row = lane & 15, a_kh = lane >> 4;
    const int b_row = (lane & 7) | ((lane >> 1) & 8);
    const int b_kh = (lane >> 3) & 1;

    for (int ch = 0; ch < NCHUNK_G; ch++) {
        if (ch + 1 < NCHUNK_G) {
            g_load_stage(sb + ((ch + 1) & 1) * STAGE_BYTES, Ag, Bg, bm, bn,
                         (ch + 1) * 32, tid);
            cp_commit();
            CP_WAIT(1);
        } else {
            CP_WAIT(0);
        }
        __syncthreads();

        uint32_t st = sb + (ch & 1) * STAGE_BYTES;
#pragma unroll
        for (int ks = 0; ks < 2; ks++) {
            uint32_t ah[4][4], al[4][4], bh[2][4], bl[2][4];
#pragma unroll
            for (int mt = 0; mt < 4; mt++) {
                uint32_t off = (uint32_t)(wm + mt * 16 + a_row) * 80 + ks * 32 + a_kh * 16;
                ldm4(ah[mt], st + TILE_A_HI + off);
                ldm4(al[mt], st + TILE_A_LO + off);
            }
#pragma unroll
            for (int ng = 0; ng < 2; ng++) {
                uint32_t off = (uint32_t)(wn + ng * 16 + b_row) * 80 + ks * 32 + b_kh * 16;
                ldm4(bh[ng], st + TILE_B_HI + off);
                ldm4(bl[ng], st + TILE_B_LO + off);
            }
#pragma unroll
            for (int mt = 0; mt < 4; mt++)
#pragma unroll
                for (int nt = 0; nt < 4; nt++) {
                    const uint32_t* bhp = &bh[nt >> 1][(nt & 1) * 2];
                    const uint32_t* blp = &bl[nt >> 1][(nt & 1) * 2];
                    mma16816(acc[mt][nt], ah[mt], bhp);
                    mma16816(acc[mt][nt], ah[mt], blp);
                    mma16816(acc[mt][nt], al[mt], bhp);
                }
        }
        __syncthreads();
    }

    // epilogue: c0,c1 -> (row, col..col+1); c2,c3 -> (row+8, ...)
    const int er = lane >> 2, ec = (lane & 3) * 2;
#pragma unroll
    for (int mt = 0; mt < 4; mt++)
#pragma unroll
        for (int nt = 0; nt < 4; nt++) {
            size_t row = bm + wm + mt * 16 + er;
            size_t col = bn + wn + nt * 8 + ec;
            *(float2*)(Cm + row * (size_t)N + col) =
                make_float2(acc[mt][nt][0], acc[mt][nt][1]);
            *(float2*)(Cm + (row + 8) * (size_t)N + col) =
                make_float2(acc[mt][nt][2], acc[mt][nt][3]);
        }
}

// ---------------- RoPE + RMSNorm transform ----------------
__global__ __launch_bounds__(128) void qkv_transform(
    const float* __restrict__ qkv, const float* __restrict__ qw,
    const float* __restrict__ kw, const float* __restrict__ fcos,
    const float* __restrict__ fsin, float* __restrict__ q,
    float* __restrict__ k, float* __restrict__ v)
{
    const int bt = blockIdx.x, hh = blockIdx.y;
    const int b = bt >> 11, t = bt & (T_ - 1);
    const int d = threadIdx.x;
    const size_t rowoff = (size_t)bt * QKVD_;

    if (hh >= NH_ + KVH_) {
        int hv = hh - (NH_ + KVH_);
        v[(((size_t)(b * KVH_ + hv)) * T_ + t) * HD_ + d] =
            qkv[rowoff + (size_t)(NH_ + KVH_) * HD_ + hv * HD_ + d];
        return;
    }
    const float* w; float* dst; size_t srcoff;
    if (hh < NH_) {
        w = qw; srcoff = (size_t)hh * HD_;
        dst = q + (((size_t)(b * NH_ + hh)) * T_ + t) * HD_;
    } else {
        int hk = hh - NH_;
        w = kw; srcoff = (size_t)NH_ * HD_ + hk * HD_;
        dst = k + (((size_t)(b * KVH_ + hk)) * T_ + t) * HD_;
    }
    float xv = qkv[rowoff + srcoff + d];
    float other = __shfl_xor_sync(0xffffffffu, xv, 1);
    int i = d >> 1;
    float c = fcos[t * (HD_ / 2) + i];
    float s = fsin[t * (HD_ / 2) + i];
    float val = (d & 1) ? (other * s + xv * c) : (xv * c - other * s);

    float ss = val * val;
#pragma unroll
    for (int off = 16; off; off >>= 1) ss += __shfl_xor_sync(0xffffffffu, ss, off);
    __shared__ float wsum[4];
    if ((d & 31) == 0) wsum[d >> 5] = ss;
    __syncthreads();
    ss = wsum[0] + wsum[1] + wsum[2] + wsum[3];
    float rinv = rsqrtf(ss * (1.0f / HD_) + 1e-6f);
    dst[d] = w[d] * val * rinv;
}

// ---------------- causal flash attention (fp32, f32x2 FMAs) ----------------
__global__ __launch_bounds__(256) void flash_attn(
    const float* __restrict__ Qg, const float* __restrict__ Kg,
    const float* __restrict__ Vg, float* __restrict__ Y)
{
    extern __shared__ float smf[];
    float* Qts = smf;
    float* Kts = smf + 128 * 68;
    float* Vs  = smf + 2 * 128 * 68;
    float* Ps  = Kts;

    const int qt = blockIdx.x, h = blockIdx.y, b = blockIdx.z;
    const int tid = threadIdx.x, ty = tid >> 4, tx = tid & 15;
    const int q0 = qt * 64;
    const float* Qp = Qg + (((size_t)(b * NH_ + h)) * T_ + q0) * HD_;
    const float* Kb = Kg + ((size_t)(b * KVH_ + (h >> 2))) * T_ * HD_;
    const float* Vb = Vg + ((size_t)(b * KVH_ + (h >> 2))) * T_ * HD_;
    const float scale = 0.08838834764831845f;

#pragma unroll 4
    for (int it = 0; it < 32; it++) {
        int idx = it * 256 + tid;
        int dl = idx & 15, r = (idx >> 4) & 63, dh = idx >> 10;
        int d = dh * 16 + dl;
        Qts[d * 68 + r] = Qp[(size_t)r * HD_ + d] * scale;
    }

    float m[4] = { -1e30f, -1e30f, -1e30f, -1e30f };
    float l[4] = { 0.f, 0.f, 0.f, 0.f };
    ull o2[4][4];
#pragma unroll
    for (int i = 0; i < 4; i++)
#pragma unroll
        for (int j = 0; j < 4; j++) o2[i][j] = 0ull;

    for (int kt = 0; kt <= qt; kt++) {
        __syncthreads();
        const float* Kp = Kb + (size_t)kt * 64 * HD_;
        const float* Vp = Vb + (size_t)kt * 64 * HD_;
#pragma unroll 4
        for (int it = 0; it < 32; it++) {
            int idx = it * 256 + tid;
            int dl = idx & 15, r = (idx >> 4) & 63, dh = idx >> 10;
            int d = dh * 16 + dl;
            Kts[d * 68 + r] = Kp[(size_t)r * HD_ + d];
            Vs[idx] = Vp[idx];
        }
        __syncthreads();

        ull s2[4][2];
#pragma unroll
        for (int i = 0; i < 4; i++) { s2[i][0] = 0ull; s2[i][1] = 0ull; }
#pragma unroll 4
        for (int kk = 0; kk < 128; kk++) {
            float4 qa = *(const float4*)&Qts[kk * 68 + ty * 4];
            ulonglong2 kb = *(const ulonglong2*)&Kts[kk * 68 + tx * 4];
            ull d0 = pack2(qa.x, qa.x), d1 = pack2(qa.y, qa.y);
            ull d2 = pack2(qa.z, qa.z), d3 = pack2(qa.w, qa.w);
            fma2(s2[0][0], d0, kb.x); fma2(s2[0][1], d0, kb.y);
            fma2(s2[1][0], d1, kb.x); fma2(s2[1][1], d1, kb.y);
            fma2(s2[2][0], d2, kb.x); fma2(s2[2][1], d2, kb.y);
            fma2(s2[3][0], d3, kb.x); fma2(s2[3][1], d3, kb.y);
        }
        float s[4][4];
#pragma unroll
        for (int i = 0; i < 4; i++) {
            float2 t0 = unpack2(s2[i][0]), t1 = unpack2(s2[i][1]);
            s[i][0] = t0.x; s[i][1] = t0.y; s[i][2] = t1.x; s[i][3] = t1.y;
        }
        if (kt == qt) {
#pragma unroll
            for (int i = 0; i < 4; i++)
#pragma unroll
                for (int j = 0; j < 4; j++)
                    if (tx * 4 + j > ty * 4 + i) s[i][j] = -1e30f;
        }
        __syncthreads();

#pragma unroll
        for (int i = 0; i < 4; i++) {
            float mx = fmaxf(fmaxf(s[i][0], s[i][1]), fmaxf(s[i][2], s[i][3]));
#pragma unroll
            for (int off = 8; off; off >>= 1)
                mx = fmaxf(mx, __shfl_xor_sync(0xffffffffu, mx, off));
            float mn = fmaxf(m[i], mx);
            float alpha = __expf(m[i] - mn);
            m[i] = mn;
            float p0 = __expf(s[i][0] - mn), p1 = __expf(s[i][1] - mn);
            float p2 = __expf(s[i][2] - mn), p3 = __expf(s[i][3] - mn);
            float ls = p0 + p1 + p2 + p3;
#pragma unroll
            for (int off = 8; off; off >>= 1)
                ls += __shfl_xor_sync(0xffffffffu, ls, off);
            l[i] = l[i] * alpha + ls;
            ull av = pack2(alpha, alpha);
#pragma unroll
            for (int j = 0; j < 4; j++) mul2(o2[i][j], av);
            *(float4*)&Ps[(ty * 4 + i) * 68 + tx * 4] = make_float4(p0, p1, p2, p3);
        }
        __syncthreads();

#pragma unroll 4
        for (int kk = 0; kk < 64; kk++) {
            ulonglong2 va = *(const ulonglong2*)&Vs[kk * 128 + tx * 8];
            ulonglong2 vb = *(const ulonglong2*)&Vs[kk * 128 + tx * 8 + 4];
#pragma unroll
            for (int i = 0; i < 4; i++) {
                float p = Ps[(ty * 4 + i) * 68 + kk];
                ull pd = pack2(p, p);
                fma2(o2[i][0], pd, va.x); fma2(o2[i][1], pd, va.y);
                fma2(o2[i][2], pd, vb.x); fma2(o2[i][3], pd, vb.y);
            }
        }
    }

#pragma unroll
    for (int i = 0; i < 4; i++) {
        float rl = 1.0f / l[i];
        float ov[8];
#pragma unroll
        for (int j = 0; j < 4; j++) {
            float2 t = unpack2(o2[i][j]);
            ov[2 * j] = t.x * rl; ov[2 * j + 1] = t.y * rl;
        }
        float* yp = Y + ((size_t)(b * T_ + q0 + ty * 4 + i)) * C_ + h * HD_ + tx * 8;
        *(float4*)yp       = make_float4(ov[0], ov[1], ov[2], ov[3]);
        *(float4*)(yp + 4) = make_float4(ov[4], ov[5], ov[6], ov[7]);
    }
}

// ---------------- launch ----------------
extern "C" void kernel_launch(void* const* d_in, const int* in_sizes, int n_in,
                              void* d_out, int out_size)
{
    const float* x      = (const float*)d_in[0];
    const float* w_qkv  = (const float*)d_in[1];
    const float* w_proj = (const float*)d_in[2];
    const float* qw     = (const float*)d_in[3];
    const float* kw     = (const float*)d_in[4];
    const float* fcos   = (const float*)d_in[5];
    const float* fsin   = (const float*)d_in[6];
    float* out = (float*)d_out;

    float *p_qkv, *p_q, *p_k, *p_v, *p_y;
    __nv_bfloat16 *p_xs, *p_wqkvs, *p_wprojs, *p_ys;
    cudaGetSymbolAddress((void**)&p_qkv, g_qkv);
    cudaGetSymbolAddress((void**)&p_q,   g_q);
    cudaGetSymbolAddress((void**)&p_k,   g_k);
    cudaGetSymbolAddress((void**)&p_v,   g_v);
    cudaGetSymbolAddress((void**)&p_y,   g_y);
    cudaGetSymbolAddress((void**)&p_xs,     g_xs);
    cudaGetSymbolAddress((void**)&p_wqkvs,  g_wqkvs);
    cudaGetSymbolAddress((void**)&p_wprojs, g_wprojs);
    cudaGetSymbolAddress((void**)&p_ys,     g_ys);

    const int GEMM_SMEM = 2 * STAGE_BYTES;   // 81920
    cudaFuncSetAttribute(gemm_mma, cudaFuncAttributeMaxDynamicSharedMemorySize, GEMM_SMEM);
    const int FA_SMEM = (2 * 128 * 68 + 64 * 128) * 4;
    cudaFuncSetAttribute(flash_attn, cudaFuncAttributeMaxDynamicSharedMemorySize, FA_SMEM);

    // 0) bf16 hi|lo splits
    conv_hilo<<<(BT_ * 512 + 255) / 256, 256>>>(x, p_xs, BT_);
    conv_hilo<<<(QKVD_ * 512 + 255) / 256, 256>>>(w_qkv, p_wqkvs, QKVD_);
    conv_hilo<<<(C_ * 512 + 255) / 256, 256>>>(w_proj, p_wprojs, C_);

    // 1) qkv = x @ w_qkv^T   [4096 x 3072]
    gemm_mma<<<dim3(QKVD_ / 128, BT_ / 128), 256, GEMM_SMEM>>>(p_xs, p_wqkvs, p_qkv, QKVD_);

    // 2) RoPE + RMSNorm + head split
    qkv_transform<<<dim3(BT_, NH_ + 2 * KVH_), 128>>>(p_qkv, qw, kw, fcos, fsin,
                                                       p_q, p_k, p_v);

    // 3) causal flash attention -> y
    flash_attn<<<dim3(T_ / 64, NH_, B_), 256, FA_SMEM>>>(p_q, p_k, p_v, p_y);

    // 4) out = y @ w_proj^T  [4096 x 2048]
    conv_hilo<<<(BT_ * 512 + 255) / 256, 256>>>(p_y, p_ys, BT_);
    gemm_mma<<<dim3(C_ / 128, BT_ / 128), 256, GEMM_SMEM>>>(p_ys, p_wprojs, out, C_);
}

// round 6
// speedup vs baseline: 1.6030x; 1.0003x over previous
#include <cuda_runtime.h>
#include <cuda_bf16.h>
#include <cstdint>

typedef unsigned long long ull;

#define B_    2
#define T_    2048
#define C_    2048
#define NH_   16
#define KVH_  4
#define HD_   128
#define QKVD_ 3072
#define BT_   (B_*T_)
#define K_    2048
#define LD2_  4096          // bf16 hi|lo row length

// ---------------- scratch ----------------
__device__ float g_qkv[(size_t)BT_ * QKVD_];
__device__ float g_q[(size_t)B_ * NH_ * T_ * HD_];
__device__ float g_k[(size_t)B_ * KVH_ * T_ * HD_];
__device__ float g_v[(size_t)B_ * KVH_ * T_ * HD_];
__device__ float g_y[(size_t)BT_ * C_];
__device__ __nv_bfloat16 g_xs[(size_t)BT_ * LD2_];      // x hi|lo
__device__ __nv_bfloat16 g_wqkvs[(size_t)QKVD_ * LD2_]; // w_qkv hi|lo
__device__ __nv_bfloat16 g_wprojs[(size_t)C_ * LD2_];   // w_proj hi|lo
__device__ __nv_bfloat16 g_ys[(size_t)BT_ * LD2_];      // y hi|lo

// ---------------- packed f32x2 helpers ----------------
__device__ __forceinline__ ull pack2(float lo, float hi) {
    ull r; asm("mov.b64 %0, {%1,%2};" : "=l"(r) : "f"(lo), "f"(hi)); return r;
}
__device__ __forceinline__ void fma2(ull &acc, ull a, ull b) {
    asm("fma.rn.f32x2 %0, %1, %2, %0;" : "+l"(acc) : "l"(a), "l"(b));
}
__device__ __forceinline__ void mul2(ull &acc, ull a) {
    asm("mul.rn.f32x2 %0, %0, %1;" : "+l"(acc) : "l"(a));
}
__device__ __forceinline__ float2 unpack2(ull v) {
    float lo, hi; asm("mov.b64 {%0,%1}, %2;" : "=f"(lo), "=f"(hi) : "l"(v));
    return make_float2(lo, hi);
}

// ---------------- PTX helpers (sm_80-baseline: cp.async / ldmatrix / mma) ----------------
__device__ __forceinline__ uint32_t smem_u32(const void* p) {
    uint32_t a;
    asm("{ .reg .u64 t; cvta.to.shared.u64 t, %1; cvt.u32.u64 %0, t; }" : "=r"(a) : "l"(p));
    return a;
}
__device__ __forceinline__ void cp16(uint32_t saddr, const void* g) {
    asm volatile("cp.async.cg.shared.global [%0], [%1], 16;" :: "r"(saddr), "l"(g) : "memory");
}
__device__ __forceinline__ void cp_commit() { asm volatile("cp.async.commit_group;" ::: "memory"); }
#define CP_WAIT(n) asm volatile("cp.async.wait_group %0;" :: "n"(n) : "memory")

__device__ __forceinline__ void ldm4(uint32_t* r, uint32_t addr) {
    asm volatile("ldmatrix.sync.aligned.m8n8.x4.shared.b16 {%0,%1,%2,%3}, [%4];"
                 : "=r"(r[0]), "=r"(r[1]), "=r"(r[2]), "=r"(r[3]) : "r"(addr));
}
__device__ __forceinline__ void mma16816(float* c, const uint32_t* a, const uint32_t* b) {
    asm volatile(
        "mma.sync.aligned.m16n8k16.row.col.f32.bf16.bf16.f32 "
        "{%0,%1,%2,%3}, {%4,%5,%6,%7}, {%8,%9}, {%0,%1,%2,%3};"
        : "+f"(c[0]), "+f"(c[1]), "+f"(c[2]), "+f"(c[3])
        : "r"(a[0]), "r"(a[1]), "r"(a[2]), "r"(a[3]), "r"(b[0]), "r"(b[1]));
}

// ---------------- fp32 -> bf16 hi|lo split conversion ----------------
__global__ __launch_bounds__(256) void conv_hilo(
    const float* __restrict__ in, __nv_bfloat16* __restrict__ out, int R)
{
    int i = blockIdx.x * 256 + threadIdx.x;
    int total = R * 512;
    if (i >= total) return;
    int r = i >> 9, c4 = (i & 511) << 2;
    float4 v = *(const float4*)(in + (size_t)r * K_ + c4);
    float f[4] = { v.x, v.y, v.z, v.w };
    __nv_bfloat16 h[4], l[4];
#pragma unroll
    for (int j = 0; j < 4; j++) {
        h[j] = __float2bfloat16_rn(f[j]);
        l[j] = __float2bfloat16_rn(f[j] - __bfloat162float(h[j]));
    }
    __nv_bfloat16* ob = out + (size_t)r * LD2_;
    *(__nv_bfloat162*)(ob + c4)          = __nv_bfloat162(h[0], h[1]);
    *(__nv_bfloat162*)(ob + c4 + 2)      = __nv_bfloat162(h[2], h[3]);
    *(__nv_bfloat162*)(ob + K_ + c4)     = __nv_bfloat162(l[0], l[1]);
    *(__nv_bfloat162*)(ob + K_ + c4 + 2) = __nv_bfloat162(l[2], l[3]);
}

// ---------------- mma.sync bf16-split NT GEMM ----------------
// C[M,N] fp32 = A x B^T with A,B stored as bf16 hi|lo rows of LD2_.
// Tile 128x128, BK=32, 8 warps (2m x 4n), warp tile 64x32 = 4 m16 x 4 n8.
// Smem per stage: Ahi/Alo/Bhi/Blo each [128][40] bf16 (pitch 80B, conflict-free ldmatrix).
#define TILE_A_HI 0
#define TILE_A_LO 10240
#define TILE_B_HI 20480
#define TILE_B_LO 30720
#define STAGE_BYTES 40960
#define NCHUNK_G (K_ / 32)

__device__ __forceinline__ void g_load_stage(
    uint32_t st, const __nv_bfloat16* Ag, const __nv_bfloat16* Bg,
    size_t bm, size_t bn, int kc, int tid)
{
#pragma unroll
    for (int j = 0; j < 2; j++) {
        int idx = tid + j * 256;          // 0..511
        int r = idx >> 2;                 // 0..127
        int c16 = (idx & 3) * 16;         // byte col in smem
        int c = (idx & 3) * 8;            // bf16 col in gmem
        uint32_t d = (uint32_t)r * 80 + c16;
        cp16(st + TILE_A_HI + d, Ag + (bm + r) * LD2_ + kc + c);
        cp16(st + TILE_A_LO + d, Ag + (bm + r) * LD2_ + K_ + kc + c);
        cp16(st + TILE_B_HI + d, Bg + (bn + r) * LD2_ + kc + c);
        cp16(st + TILE_B_LO + d, Bg + (bn + r) * LD2_ + K_ + kc + c);
    }
}

__global__ __launch_bounds__(256) void gemm_mma(
    const __nv_bfloat16* __restrict__ Ag, const __nv_bfloat16* __restrict__ Bg,
    float* __restrict__ Cm, int N)
{
    extern __shared__ char sm[];
    const uint32_t sb = smem_u32(sm);
    const int tid = threadIdx.x;
    const int wid = tid >> 5, lane = tid & 31;
    const size_t bm = (size_t)blockIdx.y * 128;
    const size_t bn = (size_t)blockIdx.x * 128;
    const int wm = (wid & 1) * 64;      // warp m offset
    const int wn = (wid >> 1) * 32;     // warp n offset

    float acc[4][4][4];
#pragma unroll
    for (int i = 0; i < 4; i++)
#pragma unroll
        for (int j = 0; j < 4; j++)
#pragma unroll
            for (int q = 0; q < 4; q++) acc[i][j][q] = 0.f;

    g_load_stage(sb, Ag, Bg, bm, bn, 0, tid);
    cp_commit();

    const int a_row = lane & 15, a_kh = lane >> 4;
    const int b_row = (lane & 7) | ((lane >> 1) & 8);
    const int b_kh = (lane >> 3) & 1;

    for (int ch = 0; ch < NCHUNK_G; ch++) {
        if (ch + 1 < NCHUNK_G) {
            g_load_stage(sb + ((ch + 1) & 1) * STAGE_BYTES, Ag, Bg, bm, bn,
                         (ch + 1) * 32, tid);
            cp_commit();
            CP_WAIT(1);
        } else {
            CP_WAIT(0);
        }
        __syncthreads();

        uint32_t st = sb + (ch & 1) * STAGE_BYTES;
#pragma unroll
        for (int ks = 0; ks < 2; ks++) {
            uint32_t ah[4][4], al[4][4], bh[2][4], bl[2][4];
#pragma unroll
            for (int mt = 0; mt < 4; mt++) {
                uint32_t off = (uint32_t)(wm + mt * 16 + a_row) * 80 + ks * 32 + a_kh * 16;
                ldm4(ah[mt], st + TILE_A_HI + off);
                ldm4(al[mt], st + TILE_A_LO + off);
            }
#pragma unroll
            for (int ng = 0; ng < 2; ng++) {
                uint32_t off = (uint32_t)(wn + ng * 16 + b_row) * 80 + ks * 32 + b_kh * 16;
                ldm4(bh[ng], st + TILE_B_HI + off);
                ldm4(bl[ng], st + TILE_B_LO + off);
            }
#pragma unroll
            for (int mt = 0; mt < 4; mt++)
#pragma unroll
                for (int nt = 0; nt < 4; nt++) {
                    const uint32_t* bhp = &bh[nt >> 1][(nt & 1) * 2];
                    const uint32_t* blp = &bl[nt >> 1][(nt & 1) * 2];
                    mma16816(acc[mt][nt], ah[mt], bhp);
                    mma16816(acc[mt][nt], ah[mt], blp);
                    mma16816(acc[mt][nt], al[mt], bhp);
                }
        }
        __syncthreads();
    }

    // epilogue: c0,c1 -> (row, col..col+1); c2,c3 -> (row+8, ...)
    const int er = lane >> 2, ec = (lane & 3) * 2;
#pragma unroll
    for (int mt = 0; mt < 4; mt++)
#pragma unroll
        for (int nt = 0; nt < 4; nt++) {
            size_t row = bm + wm + mt * 16 + er;
            size_t col = bn + wn + nt * 8 + ec;
            *(float2*)(Cm + row * (size_t)N + col) =
                make_float2(acc[mt][nt][0], acc[mt][nt][1]);
            *(float2*)(Cm + (row + 8) * (size_t)N + col) =
                make_float2(acc[mt][nt][2], acc[mt][nt][3]);
        }
}

// ---------------- RoPE + RMSNorm transform ----------------
__global__ __launch_bounds__(128) void qkv_transform(
    const float* __restrict__ qkv, const float* __restrict__ qw,
    const float* __restrict__ kw, const float* __restrict__ fcos,
    const float* __restrict__ fsin, float* __restrict__ q,
    float* __restrict__ k, float* __restrict__ v)
{
    const int bt = blockIdx.x, hh = blockIdx.y;
    const int b = bt >> 11, t = bt & (T_ - 1);
    const int d = threadIdx.x;
    const size_t rowoff = (size_t)bt * QKVD_;

    if (hh >= NH_ + KVH_) {
        int hv = hh - (NH_ + KVH_);
        v[(((size_t)(b * KVH_ + hv)) * T_ + t) * HD_ + d] =
            qkv[rowoff + (size_t)(NH_ + KVH_) * HD_ + hv * HD_ + d];
        return;
    }
    const float* w; float* dst; size_t srcoff;
    if (hh < NH_) {
        w = qw; srcoff = (size_t)hh * HD_;
        dst = q + (((size_t)(b * NH_ + hh)) * T_ + t) * HD_;
    } else {
        int hk = hh - NH_;
        w = kw; srcoff = (size_t)NH_ * HD_ + hk * HD_;
        dst = k + (((size_t)(b * KVH_ + hk)) * T_ + t) * HD_;
    }
    float xv = qkv[rowoff + srcoff + d];
    float other = __shfl_xor_sync(0xffffffffu, xv, 1);
    int i = d >> 1;
    float c = fcos[t * (HD_ / 2) + i];
    float s = fsin[t * (HD_ / 2) + i];
    float val = (d & 1) ? (other * s + xv * c) : (xv * c - other * s);

    float ss = val * val;
#pragma unroll
    for (int off = 16; off; off >>= 1) ss += __shfl_xor_sync(0xffffffffu, ss, off);
    __shared__ float wsum[4];
    if ((d & 31) == 0) wsum[d >> 5] = ss;
    __syncthreads();
    ss = wsum[0] + wsum[1] + wsum[2] + wsum[3];
    float rinv = rsqrtf(ss * (1.0f / HD_) + 1e-6f);
    dst[d] = w[d] * val * rinv;
}

// ---------------- causal flash attention (fp32, f32x2 FMAs) ----------------
__global__ __launch_bounds__(256) void flash_attn(
    const float* __restrict__ Qg, const float* __restrict__ Kg,
    const float* __restrict__ Vg, float* __restrict__ Y)
{
    extern __shared__ float smf[];
    float* Qts = smf;
    float* Kts = smf + 128 * 68;
    float* Vs  = smf + 2 * 128 * 68;
    float* Ps  = Kts;

    const int qt = blockIdx.x, h = blockIdx.y, b = blockIdx.z;
    const int tid = threadIdx.x, ty = tid >> 4, tx = tid & 15;
    const int q0 = qt * 64;
    const float* Qp = Qg + (((size_t)(b * NH_ + h)) * T_ + q0) * HD_;
    const float* Kb = Kg + ((size_t)(b * KVH_ + (h >> 2))) * T_ * HD_;
    const float* Vb = Vg + ((size_t)(b * KVH_ + (h >> 2))) * T_ * HD_;
    const float scale = 0.08838834764831845f;

#pragma unroll 4
    for (int it = 0; it < 32; it++) {
        int idx = it * 256 + tid;
        int dl = idx & 15, r = (idx >> 4) & 63, dh = idx >> 10;
        int d = dh * 16 + dl;
        Qts[d * 68 + r] = Qp[(size_t)r * HD_ + d] * scale;
    }

    float m[4] = { -1e30f, -1e30f, -1e30f, -1e30f };
    float l[4] = { 0.f, 0.f, 0.f, 0.f };
    ull o2[4][4];
#pragma unroll
    for (int i = 0; i < 4; i++)
#pragma unroll
        for (int j = 0; j < 4; j++) o2[i][j] = 0ull;

    for (int kt = 0; kt <= qt; kt++) {
        __syncthreads();
        const float* Kp = Kb + (size_t)kt * 64 * HD_;
        const float* Vp = Vb + (size_t)kt * 64 * HD_;
#pragma unroll 4
        for (int it = 0; it < 32; it++) {
            int idx = it * 256 + tid;
            int dl = idx & 15, r = (idx >> 4) & 63, dh = idx >> 10;
            int d = dh * 16 + dl;
            Kts[d * 68 + r] = Kp[(size_t)r * HD_ + d];
            Vs[idx] = Vp[idx];
        }
        __syncthreads();

        ull s2[4][2];
#pragma unroll
        for (int i = 0; i < 4; i++) { s2[i][0] = 0ull; s2[i][1] = 0ull; }
#pragma unroll 4
        for (int kk = 0; kk < 128; kk++) {
            float4 qa = *(const float4*)&Qts[kk * 68 + ty * 4];
            ulonglong2 kb = *(const ulonglong2*)&Kts[kk * 68 + tx * 4];
            ull d0 = pack2(qa.x, qa.x), d1 = pack2(qa.y, qa.y);
            ull d2 = pack2(qa.z, qa.z), d3 = pack2(qa.w, qa.w);
            fma2(s2[0][0], d0, kb.x); fma2(s2[0][1], d0, kb.y);
            fma2(s2[1][0], d1, kb.x); fma2(s2[1][1], d1, kb.y);
            fma2(s2[2][0], d2, kb.x); fma2(s2[2][1], d2, kb.y);
            fma2(s2[3][0], d3, kb.x); fma2(s2[3][1], d3, kb.y);
        }
        float s[4][4];
#pragma unroll
        for (int i = 0; i < 4; i++) {
            float2 t0 = unpack2(s2[i][0]), t1 = unpack2(s2[i][1]);
            s[i][0] = t0.x; s[i][1] = t0.y; s[i][2] = t1.x; s[i][3] = t1.y;
        }
        if (kt == qt) {
#pragma unroll
            for (int i = 0; i < 4; i++)
#pragma unroll
                for (int j = 0; j < 4; j++)
                    if (tx * 4 + j > ty * 4 + i) s[i][j] = -1e30f;
        }
        __syncthreads();

#pragma unroll
        for (int i = 0; i < 4; i++) {
            float mx = fmaxf(fmaxf(s[i][0], s[i][1]), fmaxf(s[i][2], s[i][3]));
#pragma unroll
            for (int off = 8; off; off >>= 1)
                mx = fmaxf(mx, __shfl_xor_sync(0xffffffffu, mx, off));
            float mn = fmaxf(m[i], mx);
            float alpha = __expf(m[i] - mn);
            m[i] = mn;
            float p0 = __expf(s[i][0] - mn), p1 = __expf(s[i][1] - mn);
            float p2 = __expf(s[i][2] - mn), p3 = __expf(s[i][3] - mn);
            float ls = p0 + p1 + p2 + p3;
#pragma unroll
            for (int off = 8; off; off >>= 1)
                ls += __shfl_xor_sync(0xffffffffu, ls, off);
            l[i] = l[i] * alpha + ls;
            ull av = pack2(alpha, alpha);
#pragma unroll
            for (int j = 0; j < 4; j++) mul2(o2[i][j], av);
            *(float4*)&Ps[(ty * 4 + i) * 68 + tx * 4] = make_float4(p0, p1, p2, p3);
        }
        __syncthreads();

#pragma unroll 4
        for (int kk = 0; kk < 64; kk++) {
            ulonglong2 va = *(const ulonglong2*)&Vs[kk * 128 + tx * 8];
            ulonglong2 vb = *(const ulonglong2*)&Vs[kk * 128 + tx * 8 + 4];
#pragma unroll
            for (int i = 0; i < 4; i++) {
                float p = Ps[(ty * 4 + i) * 68 + kk];
                ull pd = pack2(p, p);
                fma2(o2[i][0], pd, va.x); fma2(o2[i][1], pd, va.y);
                fma2(o2[i][2], pd, vb.x); fma2(o2[i][3], pd, vb.y);
            }
        }
    }

#pragma unroll
    for (int i = 0; i < 4; i++) {
        float rl = 1.0f / l[i];
        float ov[8];
#pragma unroll
        for (int j = 0; j < 4; j++) {
            float2 t = unpack2(o2[i][j]);
            ov[2 * j] = t.x * rl; ov[2 * j + 1] = t.y * rl;
        }
        float* yp = Y + ((size_t)(b * T_ + q0 + ty * 4 + i)) * C_ + h * HD_ + tx * 8;
        *(float4*)yp       = make_float4(ov[0], ov[1], ov[2], ov[3]);
        *(float4*)(yp + 4) = make_float4(ov[4], ov[5], ov[6], ov[7]);
    }
}

// ---------------- launch ----------------
extern "C" void kernel_launch(void* const* d_in, const int* in_sizes, int n_in,
                              void* d_out, int out_size)
{
    const float* x      = (const float*)d_in[0];
    const float* w_qkv  = (const float*)d_in[1];
    const float* w_proj = (const float*)d_in[2];
    const float* qw     = (const float*)d_in[3];
    const float* kw     = (const float*)d_in[4];
    const float* fcos   = (const float*)d_in[5];
    const float* fsin   = (const float*)d_in[6];
    float* out = (float*)d_out;

    float *p_qkv, *p_q, *p_k, *p_v, *p_y;
    __nv_bfloat16 *p_xs, *p_wqkvs, *p_wprojs, *p_ys;
    cudaGetSymbolAddress((void**)&p_qkv, g_qkv);
    cudaGetSymbolAddress((void**)&p_q,   g_q);
    cudaGetSymbolAddress((void**)&p_k,   g_k);
    cudaGetSymbolAddress((void**)&p_v,   g_v);
    cudaGetSymbolAddress((void**)&p_y,   g_y);
    cudaGetSymbolAddress((void**)&p_xs,     g_xs);
    cudaGetSymbolAddress((void**)&p_wqkvs,  g_wqkvs);
    cudaGetSymbolAddress((void**)&p_wprojs, g_wprojs);
    cudaGetSymbolAddress((void**)&p_ys,     g_ys);

    const int GEMM_SMEM = 2 * STAGE_BYTES;   // 81920
    cudaFuncSetAttribute(gemm_mma, cudaFuncAttributeMaxDynamicSharedMemorySize, GEMM_SMEM);
    const int FA_SMEM = (2 * 128 * 68 + 64 * 128) * 4;
    cudaFuncSetAttribute(flash_attn, cudaFuncAttributeMaxDynamicSharedMemorySize, FA_SMEM);

    // 0) bf16 hi|lo splits
    conv_hilo<<<(BT_ * 512 + 255) / 256, 256>>>(x, p_xs, BT_);
    conv_hilo<<<(QKVD_ * 512 + 255) / 256, 256>>>(w_qkv, p_wqkvs, QKVD_);
    conv_hilo<<<(C_ * 512 + 255) / 256, 256>>>(w_proj, p_wprojs, C_);

    // 1) qkv = x @ w_qkv^T   [4096 x 3072]
    gemm_mma<<<dim3(QKVD_ / 128, BT_ / 128), 256, GEMM_SMEM>>>(p_xs, p_wqkvs, p_qkv, QKVD_);

    // 2) RoPE + RMSNorm + head split
    qkv_transform<<<dim3(BT_, NH_ + 2 * KVH_), 128>>>(p_qkv, qw, kw, fcos, fsin,
                                                       p_q, p_k, p_v);

    // 3) causal flash attention -> y
    flash_attn<<<dim3(T_ / 64, NH_, B_), 256, FA_SMEM>>>(p_q, p_k, p_v, p_y);

    // 4) out = y @ w_proj^T  [4096 x 2048]
    conv_hilo<<<(BT_ * 512 + 255) / 256, 256>>>(p_y, p_ys, BT_);
    gemm_mma<<<dim3(C_ / 128, BT_ / 128), 256, GEMM_SMEM>>>(p_ys, p_wprojs, out, C_);
}

// round 7
// speedup vs baseline: 2.7574x; 1.7201x over previous
#include <cuda_runtime.h>
#include <cuda_bf16.h>
#include <cstdint>

typedef unsigned long long ull;

#define B_    2
#define T_    2048
#define C_    2048
#define NH_   16
#define KVH_  4
#define HD_   128
#define QKVD_ 3072
#define BT_   (B_*T_)
#define K_    2048
#define LD2_  4096          // bf16 hi|lo row length

// ---------------- scratch ----------------
__device__ float g_qkv[(size_t)BT_ * QKVD_];
__device__ __nv_bfloat16 g_xs[(size_t)BT_ * LD2_];        // x hi|lo
__device__ __nv_bfloat16 g_wqkvs[(size_t)QKVD_ * LD2_];   // w_qkv hi|lo
__device__ __nv_bfloat16 g_wprojs[(size_t)C_ * LD2_];     // w_proj hi|lo
__device__ __nv_bfloat16 g_ys[(size_t)BT_ * LD2_];        // y hi|lo (flash output)
__device__ __nv_bfloat16 g_qs[(size_t)B_ * NH_ * T_ * 256];   // q rows: hi[128]|lo[128]
__device__ __nv_bfloat16 g_ks[(size_t)B_ * KVH_ * T_ * 256];  // k rows: hi|lo
__device__ __nv_bfloat16 g_vthi[(size_t)B_ * KVH_ * HD_ * T_]; // v^T hi  [d][t]
__device__ __nv_bfloat16 g_vtlo[(size_t)B_ * KVH_ * HD_ * T_]; // v^T lo

// ---------------- PTX helpers ----------------
__device__ __forceinline__ uint32_t smem_u32(const void* p) {
    uint32_t a;
    asm("{ .reg .u64 t; cvta.to.shared.u64 t, %1; cvt.u32.u64 %0, t; }" : "=r"(a) : "l"(p));
    return a;
}
__device__ __forceinline__ void cp16(uint32_t saddr, const void* g) {
    asm volatile("cp.async.cg.shared.global [%0], [%1], 16;" :: "r"(saddr), "l"(g) : "memory");
}
__device__ __forceinline__ void cp_commit() { asm volatile("cp.async.commit_group;" ::: "memory"); }
#define CP_WAIT(n) asm volatile("cp.async.wait_group %0;" :: "n"(n) : "memory")

__device__ __forceinline__ void ldm4(uint32_t* r, uint32_t addr) {
    asm volatile("ldmatrix.sync.aligned.m8n8.x4.shared.b16 {%0,%1,%2,%3}, [%4];"
                 : "=r"(r[0]), "=r"(r[1]), "=r"(r[2]), "=r"(r[3]) : "r"(addr));
}
__device__ __forceinline__ void mma16816(float* c, const uint32_t* a, const uint32_t* b) {
    asm volatile(
        "mma.sync.aligned.m16n8k16.row.col.f32.bf16.bf16.f32 "
        "{%0,%1,%2,%3}, {%4,%5,%6,%7}, {%8,%9}, {%0,%1,%2,%3};"
        : "+f"(c[0]), "+f"(c[1]), "+f"(c[2]), "+f"(c[3])
        : "r"(a[0]), "r"(a[1]), "r"(a[2]), "r"(a[3]), "r"(b[0]), "r"(b[1]));
}
// pack two fp32 -> bf16x2 reg; 'lo' element goes to low half
__device__ __forceinline__ uint32_t pack_bf(float lo, float hi) {
    uint32_t r;
    asm("cvt.rn.bf16x2.f32 %0, %1, %2;" : "=r"(r) : "f"(hi), "f"(lo));
    return r;
}
__device__ __forceinline__ float bf_hi_part(float v) {
    return __bfloat162float(__float2bfloat16_rn(v));
}

// ---------------- fp32 -> bf16 hi|lo split conversion ----------------
__global__ __launch_bounds__(256) void conv_hilo(
    const float* __restrict__ in, __nv_bfloat16* __restrict__ out, int R)
{
    int i = blockIdx.x * 256 + threadIdx.x;
    int total = R * 512;
    if (i >= total) return;
    int r = i >> 9, c4 = (i & 511) << 2;
    float4 v = *(const float4*)(in + (size_t)r * K_ + c4);
    float f[4] = { v.x, v.y, v.z, v.w };
    __nv_bfloat16 h[4], l[4];
#pragma unroll
    for (int j = 0; j < 4; j++) {
        h[j] = __float2bfloat16_rn(f[j]);
        l[j] = __float2bfloat16_rn(f[j] - __bfloat162float(h[j]));
    }
    __nv_bfloat16* ob = out + (size_t)r * LD2_;
    *(__nv_bfloat162*)(ob + c4)          = __nv_bfloat162(h[0], h[1]);
    *(__nv_bfloat162*)(ob + c4 + 2)      = __nv_bfloat162(h[2], h[3]);
    *(__nv_bfloat162*)(ob + K_ + c4)     = __nv_bfloat162(l[0], l[1]);
    *(__nv_bfloat162*)(ob + K_ + c4 + 2) = __nv_bfloat162(l[2], l[3]);
}

// ---------------- mma.sync bf16-split NT GEMM (unchanged from R6) ----------------
#define TILE_A_HI 0
#define TILE_A_LO 10240
#define TILE_B_HI 20480
#define TILE_B_LO 30720
#define STAGE_BYTES 40960
#define NCHUNK_G (K_ / 32)

__device__ __forceinline__ void g_load_stage(
    uint32_t st, const __nv_bfloat16* Ag, const __nv_bfloat16* Bg,
    size_t bm, size_t bn, int kc, int tid)
{
#pragma unroll
    for (int j = 0; j < 2; j++) {
        int idx = tid + j * 256;
        int r = idx >> 2;
        int c16 = (idx & 3) * 16;
        int c = (idx & 3) * 8;
        uint32_t d = (uint32_t)r * 80 + c16;
        cp16(st + TILE_A_HI + d, Ag + (bm + r) * LD2_ + kc + c);
        cp16(st + TILE_A_LO + d, Ag + (bm + r) * LD2_ + K_ + kc + c);
        cp16(st + TILE_B_HI + d, Bg + (bn + r) * LD2_ + kc + c);
        cp16(st + TILE_B_LO + d, Bg + (bn + r) * LD2_ + K_ + kc + c);
    }
}

__global__ __launch_bounds__(256) void gemm_mma(
    const __nv_bfloat16* __restrict__ Ag, const __nv_bfloat16* __restrict__ Bg,
    float* __restrict__ Cm, int N)
{
    extern __shared__ char sm[];
    const uint32_t sb = smem_u32(sm);
    const int tid = threadIdx.x;
    const int wid = tid >> 5, lane = tid & 31;
    const size_t bm = (size_t)blockIdx.y * 128;
    const size_t bn = (size_t)blockIdx.x * 128;
    const int wm = (wid & 1) * 64;
    const int wn = (wid >> 1) * 32;

    float acc[4][4][4];
#pragma unroll
    for (int i = 0; i < 4; i++)
#pragma unroll
        for (int j = 0; j < 4; j++)
#pragma unroll
            for (int q = 0; q < 4; q++) acc[i][j][q] = 0.f;

    g_load_stage(sb, Ag, Bg, bm, bn, 0, tid);
    cp_commit();

    const int a_row = lane & 15, a_kh = lane >> 4;
    const int b_row = (lane & 7) | ((lane >> 1) & 8);
    const int b_kh = (lane >> 3) & 1;

    for (int ch = 0; ch < NCHUNK_G; ch++) {
        if (ch + 1 < NCHUNK_G) {
            g_load_stage(sb + ((ch + 1) & 1) * STAGE_BYTES, Ag, Bg, bm, bn,
                         (ch + 1) * 32, tid);
            cp_commit();
            CP_WAIT(1);
        } else {
            CP_WAIT(0);
        }
        __syncthreads();

        uint32_t st = sb + (ch & 1) * STAGE_BYTES;
#pragma unroll
        for (int ks = 0; ks < 2; ks++) {
            uint32_t ah[4][4], al[4][4], bh[2][4], bl[2][4];
#pragma unroll
            for (int mt = 0; mt < 4; mt++) {
                uint32_t off = (uint32_t)(wm + mt * 16 + a_row) * 80 + ks * 32 + a_kh * 16;
                ldm4(ah[mt], st + TILE_A_HI + off);
                ldm4(al[mt], st + TILE_A_LO + off);
            }
#pragma unroll
            for (int ng = 0; ng < 2; ng++) {
                uint32_t off = (uint32_t)(wn + ng * 16 + b_row) * 80 + ks * 32 + b_kh * 16;
                ldm4(bh[ng], st + TILE_B_HI + off);
                ldm4(bl[ng], st + TILE_B_LO + off);
            }
#pragma unroll
            for (int mt = 0; mt < 4; mt++)
#pragma unroll
                for (int nt = 0; nt < 4; nt++) {
                    const uint32_t* bhp = &bh[nt >> 1][(nt & 1) * 2];
                    const uint32_t* blp = &bl[nt >> 1][(nt & 1) * 2];
                    mma16816(acc[mt][nt], ah[mt], bhp);
                    mma16816(acc[mt][nt], ah[mt], blp);
                    mma16816(acc[mt][nt], al[mt], bhp);
                }
        }
        __syncthreads();
    }

    const int er = lane >> 2, ec = (lane & 3) * 2;
#pragma unroll
    for (int mt = 0; mt < 4; mt++)
#pragma unroll
        for (int nt = 0; nt < 4; nt++) {
            size_t row = bm + wm + mt * 16 + er;
            size_t col = bn + wn + nt * 8 + ec;
            *(float2*)(Cm + row * (size_t)N + col) =
                make_float2(acc[mt][nt][0], acc[mt][nt][1]);
            *(float2*)(Cm + (row + 8) * (size_t)N + col) =
                make_float2(acc[mt][nt][2], acc[mt][nt][3]);
        }
}

// ---------------- RoPE + RMSNorm transform -> bf16 hi/lo outputs ----------------
// q: pre-scaled by 1/sqrt(HD), rows [t][hi128|lo128]; k same (unscaled); v transposed [d][t] hi/lo
__global__ __launch_bounds__(128) void qkv_transform(
    const float* __restrict__ qkv, const float* __restrict__ qw,
    const float* __restrict__ kw, const float* __restrict__ fcos,
    const float* __restrict__ fsin,
    __nv_bfloat16* __restrict__ Qs, __nv_bfloat16* __restrict__ Ks,
    __nv_bfloat16* __restrict__ VThi, __nv_bfloat16* __restrict__ VTlo)
{
    const int bt = blockIdx.x, hh = blockIdx.y;
    const int b = bt >> 11, t = bt & (T_ - 1);
    const int d = threadIdx.x;
    const size_t rowoff = (size_t)bt * QKVD_;

    if (hh >= NH_ + KVH_) {     // v: transpose + hi/lo split
        int hv = hh - (NH_ + KVH_);
        float val = qkv[rowoff + (size_t)(NH_ + KVH_) * HD_ + hv * HD_ + d];
        __nv_bfloat16 hi = __float2bfloat16_rn(val);
        __nv_bfloat16 lo = __float2bfloat16_rn(val - __bfloat162float(hi));
        size_t off = ((size_t)(b * KVH_ + hv) * HD_ + d) * T_ + t;
        VThi[off] = hi; VTlo[off] = lo;
        return;
    }
    const float* w; __nv_bfloat16* dst; size_t srcoff; float post;
    if (hh < NH_) {
        w = qw; srcoff = (size_t)hh * HD_;
        dst = Qs + (((size_t)(b * NH_ + hh)) * T_ + t) * 256;
        post = 0.08838834764831845f;   // 1/sqrt(128)
    } else {
        int hk = hh - NH_;
        w = kw; srcoff = (size_t)NH_ * HD_ + hk * HD_;
        dst = Ks + (((size_t)(b * KVH_ + hk)) * T_ + t) * 256;
        post = 1.0f;
    }
    float xv = qkv[rowoff + srcoff + d];
    float other = __shfl_xor_sync(0xffffffffu, xv, 1);
    int i = d >> 1;
    float c = fcos[t * (HD_ / 2) + i];
    float s = fsin[t * (HD_ / 2) + i];
    float val = (d & 1) ? (other * s + xv * c) : (xv * c - other * s);

    float ss = val * val;
#pragma unroll
    for (int off = 16; off; off >>= 1) ss += __shfl_xor_sync(0xffffffffu, ss, off);
    __shared__ float wsum[4];
    if ((d & 31) == 0) wsum[d >> 5] = ss;
    __syncthreads();
    ss = wsum[0] + wsum[1] + wsum[2] + wsum[3];
    float rinv = rsqrtf(ss * (1.0f / HD_) + 1e-6f);
    float outv = w[d] * val * rinv * post;
    __nv_bfloat16 hi = __float2bfloat16_rn(outv);
    __nv_bfloat16 lo = __float2bfloat16_rn(outv - __bfloat162float(hi));
    dst[d] = hi;
    dst[128 + d] = lo;
}

// ---------------- flash attention via mma.sync bf16 hi/lo ----------------
// CTA: 128 q-rows x (b,h). 8 warps, warp w owns rows [w*16, w*16+16).
// K-tiles of 64, double-buffered. P kept in registers (acc-frag -> A-frag repack).
#define QPITCH 272        // bytes per 128-bf16 row (+8 pad)
#define VPITCH 144        // bytes per 64-bf16 row (+8 pad)
#define SM_Q_HI 0
#define SM_Q_LO 34816
#define SM_STAGE0 69632
#define KV_STAGE 71680
#define OFF_KHI 0
#define OFF_KLO 17408
#define OFF_VHI 34816
#define OFF_VLO 53248
#define FA_SMEM 212992

__device__ __forceinline__ void fa_load_kv(
    uint32_t st, const __nv_bfloat16* Kg, const __nv_bfloat16* Vhg,
    const __nv_bfloat16* Vlg, int kt, int tid)
{
#pragma unroll
    for (int j = 0; j < 4; j++) {
        int idx = tid + j * 256;            // 0..1023
        int r = idx >> 4, c = idx & 15;     // K: 64 rows x 16 chunks
        const __nv_bfloat16* krow = Kg + ((size_t)(kt * 64 + r)) * 256 + c * 8;
        cp16(st + OFF_KHI + (uint32_t)r * QPITCH + c * 16, krow);
        cp16(st + OFF_KLO + (uint32_t)r * QPITCH + c * 16, krow + 128);
        int rv = idx >> 3, cv = idx & 7;    // V^T: 128 rows x 8 chunks
        cp16(st + OFF_VHI + (uint32_t)rv * VPITCH + cv * 16,
             Vhg + (size_t)rv * T_ + kt * 64 + cv * 8);
        cp16(st + OFF_VLO + (uint32_t)rv * VPITCH + cv * 16,
             Vlg + (size_t)rv * T_ + kt * 64 + cv * 8);
    }
}

__global__ __launch_bounds__(256, 1) void flash_mma(
    const __nv_bfloat16* __restrict__ Qs, const __nv_bfloat16* __restrict__ Ks,
    const __nv_bfloat16* __restrict__ VThi, const __nv_bfloat16* __restrict__ VTlo,
    __nv_bfloat16* __restrict__ Ys)
{
    extern __shared__ char sm[];
    const uint32_t sb = smem_u32(sm);
    const int tid = threadIdx.x, w = tid >> 5, lane = tid & 31;
    const int qt = blockIdx.x, h = blockIdx.y, b = blockIdx.z;
    const int q0 = qt * 128;
    const int hk = h >> 2;
    const __nv_bfloat16* Qg = Qs + ((size_t)(b * NH_ + h) * T_ + q0) * 256;
    const __nv_bfloat16* Kg = Ks + (size_t)(b * KVH_ + hk) * T_ * 256;
    const __nv_bfloat16* Vhg = VThi + (size_t)(b * KVH_ + hk) * HD_ * T_;
    const __nv_bfloat16* Vlg = VTlo + (size_t)(b * KVH_ + hk) * HD_ * T_;

    // load Q tile (hi+lo) + first KV tile, one cp.async group
#pragma unroll
    for (int j = 0; j < 8; j++) {
        int idx = tid + j * 256;            // 0..2047
        int r = idx >> 4, c = idx & 15;
        const __nv_bfloat16* qrow = Qg + (size_t)r * 256 + c * 8;
        cp16(sb + SM_Q_HI + (uint32_t)r * QPITCH + c * 16, qrow);
        cp16(sb + SM_Q_LO + (uint32_t)r * QPITCH + c * 16, qrow + 128);
    }
    fa_load_kv(sb + SM_STAGE0, Kg, Vhg, Vlg, 0, tid);
    cp_commit();

    float O[16][4];
#pragma unroll
    for (int i = 0; i < 16; i++)
#pragma unroll
        for (int j = 0; j < 4; j++) O[i][j] = 0.f;
    float m0 = -1e30f, m1 = -1e30f, l0 = 0.f, l1 = 0.f;

    const int er = lane >> 2, ec2 = (lane & 3) * 2;
    const int a_row = lane & 15, a_kh = lane >> 4;
    const int b_row = (lane & 7) | ((lane >> 1) & 8), b_kh = (lane >> 3) & 1;
    const int row0 = q0 + w * 16 + er;
    const int nkt = 2 * qt + 2;

    for (int kt = 0; kt < nkt; kt++) {
        if (kt + 1 < nkt) {
            fa_load_kv(sb + SM_STAGE0 + ((kt + 1) & 1) * KV_STAGE, Kg, Vhg, Vlg,
                       kt + 1, tid);
            cp_commit();
            CP_WAIT(1);
        } else {
            CP_WAIT(0);
        }
        __syncthreads();

        const bool full_mask = (kt * 64) > (q0 + w * 16 + 15);   // warp-uniform
        if (!full_mask) {
            const uint32_t st = sb + SM_STAGE0 + (kt & 1) * KV_STAGE;

            // ---- S = Q K^T (3-term hi/lo) ----
            float s[8][4];
#pragma unroll
            for (int i = 0; i < 8; i++)
#pragma unroll
                for (int j = 0; j < 4; j++) s[i][j] = 0.f;
#pragma unroll
            for (int ks = 0; ks < 8; ks++) {
                uint32_t ah[4], al[4];
                uint32_t qoff = (uint32_t)(w * 16 + a_row) * QPITCH + ks * 32 + a_kh * 16;
                ldm4(ah, sb + SM_Q_HI + qoff);
                ldm4(al, sb + SM_Q_LO + qoff);
#pragma unroll
                for (int ng = 0; ng < 4; ng++) {
                    uint32_t bh[4], bl[4];
                    uint32_t koff = (uint32_t)(ng * 16 + b_row) * QPITCH + ks * 32 + b_kh * 16;
                    ldm4(bh, st + OFF_KHI + koff);
                    ldm4(bl, st + OFF_KLO + koff);
                    mma16816(s[2 * ng],     ah, &bh[0]);
                    mma16816(s[2 * ng + 1], ah, &bh[2]);
                    mma16816(s[2 * ng],     ah, &bl[0]);
                    mma16816(s[2 * ng + 1], ah, &bl[2]);
                    mma16816(s[2 * ng],     al, &bh[0]);
                    mma16816(s[2 * ng + 1], al, &bh[2]);
                }
            }

            // ---- causal mask ----
            if ((kt * 64 + 63) > (q0 + w * 16)) {
#pragma unroll
                for (int nf = 0; nf < 8; nf++) {
                    int c0 = kt * 64 + nf * 8 + ec2;
                    if (c0     > row0)     s[nf][0] = -1e30f;
                    if (c0 + 1 > row0)     s[nf][1] = -1e30f;
                    if (c0     > row0 + 8) s[nf][2] = -1e30f;
                    if (c0 + 1 > row0 + 8) s[nf][3] = -1e30f;
                }
            }

            // ---- streaming softmax (quad-local) ----
            float mx0 = -1e30f, mx1 = -1e30f;
#pragma unroll
            for (int nf = 0; nf < 8; nf++) {
                mx0 = fmaxf(mx0, fmaxf(s[nf][0], s[nf][1]));
                mx1 = fmaxf(mx1, fmaxf(s[nf][2], s[nf][3]));
            }
            mx0 = fmaxf(mx0, __shfl_xor_sync(0xffffffffu, mx0, 1));
            mx0 = fmaxf(mx0, __shfl_xor_sync(0xffffffffu, mx0, 2));
            mx1 = fmaxf(mx1, __shfl_xor_sync(0xffffffffu, mx1, 1));
            mx1 = fmaxf(mx1, __shfl_xor_sync(0xffffffffu, mx1, 2));
            float mn0 = fmaxf(m0, mx0), mn1 = fmaxf(m1, mx1);
            float al0 = __expf(m0 - mn0), al1 = __expf(m1 - mn1);
            m0 = mn0; m1 = mn1;

            float ls0 = 0.f, ls1 = 0.f;
            uint32_t pah[4][4], pal[4][4];
#pragma unroll
            for (int nf = 0; nf < 8; nf++) {
                float p0 = __expf(s[nf][0] - mn0);
                float p1 = __expf(s[nf][1] - mn0);
                float p2 = __expf(s[nf][2] - mn1);
                float p3 = __expf(s[nf][3] - mn1);
                ls0 += p0 + p1; ls1 += p2 + p3;
                float h0 = bf_hi_part(p0), h1 = bf_hi_part(p1);
                float h2 = bf_hi_part(p2), h3 = bf_hi_part(p3);
                int q = nf >> 1, base = (nf & 1) * 2;
                pah[q][base]     = pack_bf(h0, h1);
                pah[q][base + 1] = pack_bf(h2, h3);
                pal[q][base]     = pack_bf(p0 - h0, p1 - h1);
                pal[q][base + 1] = pack_bf(p2 - h2, p3 - h3);
            }
            ls0 += __shfl_xor_sync(0xffffffffu, ls0, 1);
            ls0 += __shfl_xor_sync(0xffffffffu, ls0, 2);
            ls1 += __shfl_xor_sync(0xffffffffu, ls1, 1);
            ls1 += __shfl_xor_sync(0xffffffffu, ls1, 2);
            l0 = l0 * al0 + ls0;
            l1 = l1 * al1 + ls1;
#pragma unroll
            for (int df = 0; df < 16; df++) {
                O[df][0] *= al0; O[df][1] *= al0;
                O[df][2] *= al1; O[df][3] *= al1;
            }

            // ---- O += P V (3-term hi/lo), P from registers ----
#pragma unroll
            for (int q = 0; q < 4; q++) {
#pragma unroll
                for (int ng = 0; ng < 8; ng++) {
                    uint32_t vh[4], vl[4];
                    uint32_t voff = (uint32_t)(ng * 16 + b_row) * VPITCH + q * 32 + b_kh * 16;
                    ldm4(vh, st + OFF_VHI + voff);
                    ldm4(vl, st + OFF_VLO + voff);
                    mma16816(O[2 * ng],     pah[q], &vh[0]);
                    mma16816(O[2 * ng + 1], pah[q], &vh[2]);
                    mma16816(O[2 * ng],     pah[q], &vl[0]);
                    mma16816(O[2 * ng + 1], pah[q], &vl[2]);
                    mma16816(O[2 * ng],     pal[q], &vh[0]);
                    mma16816(O[2 * ng + 1], pal[q], &vh[2]);
                }
            }
        }
        __syncthreads();
    }

    // ---- epilogue: normalize, hi/lo split, write y in GEMM-A format ----
    float il0 = 1.0f / l0, il1 = 1.0f / l1;
    size_t r0 = (size_t)(b * T_ + q0 + w * 16 + er);
    __nv_bfloat16* y0 = Ys + r0 * LD2_ + h * HD_;
    __nv_bfloat16* y1 = Ys + (r0 + 8) * LD2_ + h * HD_;
#pragma unroll
    for (int nf = 0; nf < 16; nf++) {
        float v0 = O[nf][0] * il0, v1 = O[nf][1] * il0;
        float v2 = O[nf][2] * il1, v3 = O[nf][3] * il1;
        float h0 = bf_hi_part(v0), h1 = bf_hi_part(v1);
        float h2 = bf_hi_part(v2), h3 = bf_hi_part(v3);
        int co = nf * 8 + ec2;
        *(uint32_t*)(y0 + co)        = pack_bf(h0, h1);
        *(uint32_t*)(y0 + K_ + co)   = pack_bf(v0 - h0, v1 - h1);
        *(uint32_t*)(y1 + co)        = pack_bf(h2, h3);
        *(uint32_t*)(y1 + K_ + co)   = pack_bf(v2 - h2, v3 - h3);
    }
}

// ---------------- launch ----------------
extern "C" void kernel_launch(void* const* d_in, const int* in_sizes, int n_in,
                              void* d_out, int out_size)
{
    const float* x      = (const float*)d_in[0];
    const float* w_qkv  = (const float*)d_in[1];
    const float* w_proj = (const float*)d_in[2];
    const float* qw     = (const float*)d_in[3];
    const float* kw     = (const float*)d_in[4];
    const float* fcos   = (const float*)d_in[5];
    const float* fsin   = (const float*)d_in[6];
    float* out = (float*)d_out;

    float* p_qkv;
    __nv_bfloat16 *p_xs, *p_wqkvs, *p_wprojs, *p_ys, *p_qs, *p_ks, *p_vthi, *p_vtlo;
    cudaGetSymbolAddress((void**)&p_qkv,    g_qkv);
    cudaGetSymbolAddress((void**)&p_xs,     g_xs);
    cudaGetSymbolAddress((void**)&p_wqkvs,  g_wqkvs);
    cudaGetSymbolAddress((void**)&p_wprojs, g_wprojs);
    cudaGetSymbolAddress((void**)&p_ys,     g_ys);
    cudaGetSymbolAddress((void**)&p_qs,     g_qs);
    cudaGetSymbolAddress((void**)&p_ks,     g_ks);
    cudaGetSymbolAddress((void**)&p_vthi,   g_vthi);
    cudaGetSymbolAddress((void**)&p_vtlo,   g_vtlo);

    const int GEMM_SMEM = 2 * STAGE_BYTES;
    cudaFuncSetAttribute(gemm_mma, cudaFuncAttributeMaxDynamicSharedMemorySize, GEMM_SMEM);
    cudaFuncSetAttribute(flash_mma, cudaFuncAttributeMaxDynamicSharedMemorySize, FA_SMEM);

    // 0) bf16 hi|lo splits of GEMM inputs
    conv_hilo<<<(BT_ * 512 + 255) / 256, 256>>>(x, p_xs, BT_);
    conv_hilo<<<(QKVD_ * 512 + 255) / 256, 256>>>(w_qkv, p_wqkvs, QKVD_);
    conv_hilo<<<(C_ * 512 + 255) / 256, 256>>>(w_proj, p_wprojs, C_);

    // 1) qkv = x @ w_qkv^T
    gemm_mma<<<dim3(QKVD_ / 128, BT_ / 128), 256, GEMM_SMEM>>>(p_xs, p_wqkvs, p_qkv, QKVD_);

    // 2) RoPE + RMSNorm -> bf16 hi/lo Q (pre-scaled), K, V^T
    qkv_transform<<<dim3(BT_, NH_ + 2 * KVH_), 128>>>(p_qkv, qw, kw, fcos, fsin,
                                                       p_qs, p_ks, p_vthi, p_vtlo);

    // 3) causal flash attention (tensor cores) -> y hi/lo
    flash_mma<<<dim3(T_ / 128, NH_, B_), 256, FA_SMEM>>>(p_qs, p_ks, p_vthi, p_vtlo, p_ys);

    // 4) out = y @ w_proj^T
    gemm_mma<<<dim3(C_ / 128, BT_ / 128), 256, GEMM_SMEM>>>(p_ys, p_wprojs, out, C_);
}

// round 8
// speedup vs baseline: 2.7942x; 1.0134x over previous
#include <cuda_runtime.h>
#include <cuda_bf16.h>
#include <cstdint>

typedef unsigned long long ull;

#define B_    2
#define T_    2048
#define C_    2048
#define NH_   16
#define KVH_  4
#define HD_   128
#define QKVD_ 3072
#define BT_   (B_*T_)
#define K_    2048
#define LD2_  4096          // bf16 hi|lo row length

// ---------------- scratch ----------------
__device__ float g_qkv[(size_t)BT_ * QKVD_];
__device__ __nv_bfloat16 g_xs[(size_t)BT_ * LD2_];        // x hi|lo
__device__ __nv_bfloat16 g_wqkvs[(size_t)QKVD_ * LD2_];   // w_qkv hi|lo
__device__ __nv_bfloat16 g_wprojs[(size_t)C_ * LD2_];     // w_proj hi|lo
__device__ __nv_bfloat16 g_ys[(size_t)BT_ * LD2_];        // y hi|lo (flash output)
__device__ __nv_bfloat16 g_qs[(size_t)B_ * NH_ * T_ * 256];   // q rows: hi[128]|lo[128]
__device__ __nv_bfloat16 g_ks[(size_t)B_ * KVH_ * T_ * 256];  // k rows: hi|lo
__device__ __nv_bfloat16 g_vthi[(size_t)B_ * KVH_ * HD_ * T_]; // v^T hi  [d][t]
__device__ __nv_bfloat16 g_vtlo[(size_t)B_ * KVH_ * HD_ * T_]; // v^T lo

// ---------------- PTX helpers ----------------
__device__ __forceinline__ uint32_t smem_u32(const void* p) {
    uint32_t a;
    asm("{ .reg .u64 t; cvta.to.shared.u64 t, %1; cvt.u32.u64 %0, t; }" : "=r"(a) : "l"(p));
    return a;
}
__device__ __forceinline__ void cp16(uint32_t saddr, const void* g) {
    asm volatile("cp.async.cg.shared.global [%0], [%1], 16;" :: "r"(saddr), "l"(g) : "memory");
}
__device__ __forceinline__ void cp_commit() { asm volatile("cp.async.commit_group;" ::: "memory"); }
#define CP_WAIT(n) asm volatile("cp.async.wait_group %0;" :: "n"(n) : "memory")

__device__ __forceinline__ void ldm4(uint32_t* r, uint32_t addr) {
    asm volatile("ldmatrix.sync.aligned.m8n8.x4.shared.b16 {%0,%1,%2,%3}, [%4];"
                 : "=r"(r[0]), "=r"(r[1]), "=r"(r[2]), "=r"(r[3]) : "r"(addr));
}
__device__ __forceinline__ void mma16816(float* c, const uint32_t* a, const uint32_t* b) {
    asm volatile(
        "mma.sync.aligned.m16n8k16.row.col.f32.bf16.bf16.f32 "
        "{%0,%1,%2,%3}, {%4,%5,%6,%7}, {%8,%9}, {%0,%1,%2,%3};"
        : "+f"(c[0]), "+f"(c[1]), "+f"(c[2]), "+f"(c[3])
        : "r"(a[0]), "r"(a[1]), "r"(a[2]), "r"(a[3]), "r"(b[0]), "r"(b[1]));
}
// pack two fp32 -> bf16x2 reg; 'lo' element goes to low half
__device__ __forceinline__ uint32_t pack_bf(float lo, float hi) {
    uint32_t r;
    asm("cvt.rn.bf16x2.f32 %0, %1, %2;" : "=r"(r) : "f"(hi), "f"(lo));
    return r;
}
__device__ __forceinline__ float bf_hi_part(float v) {
    return __bfloat162float(__float2bfloat16_rn(v));
}

// ---------------- fp32 -> bf16 hi|lo split conversion ----------------
__global__ __launch_bounds__(256) void conv_hilo(
    const float* __restrict__ in, __nv_bfloat16* __restrict__ out, int R)
{
    int i = blockIdx.x * 256 + threadIdx.x;
    int total = R * 512;
    if (i >= total) return;
    int r = i >> 9, c4 = (i & 511) << 2;
    float4 v = *(const float4*)(in + (size_t)r * K_ + c4);
    float f[4] = { v.x, v.y, v.z, v.w };
    __nv_bfloat16 h[4], l[4];
#pragma unroll
    for (int j = 0; j < 4; j++) {
        h[j] = __float2bfloat16_rn(f[j]);
        l[j] = __float2bfloat16_rn(f[j] - __bfloat162float(h[j]));
    }
    __nv_bfloat16* ob = out + (size_t)r * LD2_;
    *(__nv_bfloat162*)(ob + c4)          = __nv_bfloat162(h[0], h[1]);
    *(__nv_bfloat162*)(ob + c4 + 2)      = __nv_bfloat162(h[2], h[3]);
    *(__nv_bfloat162*)(ob + K_ + c4)     = __nv_bfloat162(l[0], l[1]);
    *(__nv_bfloat162*)(ob + K_ + c4 + 2) = __nv_bfloat162(l[2], l[3]);
}

// ---------------- mma.sync bf16-split NT GEMM, 128x256 CTA / 64x64 warp ----------------
// C[M,N] fp32 = A x B^T; A,B rows are [hi(2048)|lo(2048)] bf16.
// 8 warps: wm = (wid&1)*64, wn = (wid>>1)*64. BK=32, 3-stage cp.async pipeline.
#define GT_A_HI 0
#define GT_A_LO 10240
#define GT_B_HI 20480
#define GT_B_LO 40960
#define GSTAGE  61440
#define NSTAGE  3
#define NCHUNK_G (K_ / 32)

__device__ __forceinline__ void g_load_stage(
    uint32_t st, const __nv_bfloat16* Ag, const __nv_bfloat16* Bg,
    size_t bm, size_t bn, int kc, int tid)
{
    // A: 128 rows x 32 bf16 (hi+lo)
#pragma unroll
    for (int j = 0; j < 2; j++) {
        int idx = tid + j * 256;           // 0..511
        int r = idx >> 2;                  // 0..127
        int c = idx & 3;                   // 16B chunk
        uint32_t d = (uint32_t)r * 80 + c * 16;
        const __nv_bfloat16* arow = Ag + (bm + r) * LD2_ + kc + c * 8;
        cp16(st + GT_A_HI + d, arow);
        cp16(st + GT_A_LO + d, arow + K_);
    }
    // B: 256 rows x 32 bf16 (hi+lo)
#pragma unroll
    for (int j = 0; j < 4; j++) {
        int idx = tid + j * 256;           // 0..1023
        int r = idx >> 2;                  // 0..255
        int c = idx & 3;
        uint32_t d = (uint32_t)r * 80 + c * 16;
        const __nv_bfloat16* brow = Bg + (bn + r) * LD2_ + kc + c * 8;
        cp16(st + GT_B_HI + d, brow);
        cp16(st + GT_B_LO + d, brow + K_);
    }
}

__global__ __launch_bounds__(256, 1) void gemm_mma(
    const __nv_bfloat16* __restrict__ Ag, const __nv_bfloat16* __restrict__ Bg,
    float* __restrict__ Cm, int N)
{
    extern __shared__ char sm[];
    const uint32_t sb = smem_u32(sm);
    const int tid = threadIdx.x;
    const int wid = tid >> 5, lane = tid & 31;
    const size_t bm = (size_t)blockIdx.y * 128;
    const size_t bn = (size_t)blockIdx.x * 256;
    const int wm = (wid & 1) * 64;
    const int wn = (wid >> 1) * 64;

    float acc[4][8][4];
#pragma unroll
    for (int i = 0; i < 4; i++)
#pragma unroll
        for (int j = 0; j < 8; j++)
#pragma unroll
            for (int q = 0; q < 4; q++) acc[i][j][q] = 0.f;

    // prologue: prefetch 2 stages
    g_load_stage(sb, Ag, Bg, bm, bn, 0, tid);
    cp_commit();
    g_load_stage(sb + GSTAGE, Ag, Bg, bm, bn, 32, tid);
    cp_commit();

    const int a_row = lane & 15, a_kh = lane >> 4;
    const int b_row = (lane & 7) | ((lane >> 1) & 8);
    const int b_kh = (lane >> 3) & 1;

    int stg = 0;
    for (int ch = 0; ch < NCHUNK_G; ch++) {
        CP_WAIT(1);
        __syncthreads();

        // prefetch chunk ch+2 into the stage consumed at ch-1 (free after the barrier)
        if (ch + 2 < NCHUNK_G) {
            int ps = stg + 2 >= NSTAGE ? stg + 2 - NSTAGE : stg + 2;
            g_load_stage(sb + ps * GSTAGE, Ag, Bg, bm, bn, (ch + 2) * 32, tid);
        }
        cp_commit();

        const uint32_t st = sb + stg * GSTAGE;
#pragma unroll
        for (int ks = 0; ks < 2; ks++) {
            uint32_t ah[4][4], al[4][4];
#pragma unroll
            for (int mt = 0; mt < 4; mt++) {
                uint32_t off = (uint32_t)(wm + mt * 16 + a_row) * 80 + ks * 32 + a_kh * 16;
                ldm4(ah[mt], st + GT_A_HI + off);
                ldm4(al[mt], st + GT_A_LO + off);
            }
#pragma unroll
            for (int ng = 0; ng < 4; ng++) {
                uint32_t bh[4], bl[4];
                uint32_t off = (uint32_t)(wn + ng * 16 + b_row) * 80 + ks * 32 + b_kh * 16;
                ldm4(bh, st + GT_B_HI + off);
                ldm4(bl, st + GT_B_LO + off);
#pragma unroll
                for (int mt = 0; mt < 4; mt++) {
                    float* a0 = acc[mt][2 * ng];
                    float* a1 = acc[mt][2 * ng + 1];
                    mma16816(a0, ah[mt], &bh[0]);
                    mma16816(a1, ah[mt], &bh[2]);
                    mma16816(a0, ah[mt], &bl[0]);
                    mma16816(a1, ah[mt], &bl[2]);
                    mma16816(a0, al[mt], &bh[0]);
                    mma16816(a1, al[mt], &bh[2]);
                }
            }
        }
        stg = stg + 1 >= NSTAGE ? 0 : stg + 1;
    }

    const int er = lane >> 2, ec = (lane & 3) * 2;
#pragma unroll
    for (int mt = 0; mt < 4; mt++)
#pragma unroll
        for (int nf = 0; nf < 8; nf++) {
            size_t row = bm + wm + mt * 16 + er;
            size_t col = bn + wn + nf * 8 + ec;
            *(float2*)(Cm + row * (size_t)N + col) =
                make_float2(acc[mt][nf][0], acc[mt][nf][1]);
            *(float2*)(Cm + (row + 8) * (size_t)N + col) =
                make_float2(acc[mt][nf][2], acc[mt][nf][3]);
        }
}

// ---------------- RoPE + RMSNorm transform -> bf16 hi/lo outputs ----------------
__global__ __launch_bounds__(128) void qkv_transform(
    const float* __restrict__ qkv, const float* __restrict__ qw,
    const float* __restrict__ kw, const float* __restrict__ fcos,
    const float* __restrict__ fsin,
    __nv_bfloat16* __restrict__ Qs, __nv_bfloat16* __restrict__ Ks,
    __nv_bfloat16* __restrict__ VThi, __nv_bfloat16* __restrict__ VTlo)
{
    const int bt = blockIdx.x, hh = blockIdx.y;
    const int b = bt >> 11, t = bt & (T_ - 1);
    const int d = threadIdx.x;
    const size_t rowoff = (size_t)bt * QKVD_;

    if (hh >= NH_ + KVH_) {     // v: transpose + hi/lo split
        int hv = hh - (NH_ + KVH_);
        float val = qkv[rowoff + (size_t)(NH_ + KVH_) * HD_ + hv * HD_ + d];
        __nv_bfloat16 hi = __float2bfloat16_rn(val);
        __nv_bfloat16 lo = __float2bfloat16_rn(val - __bfloat162float(hi));
        size_t off = ((size_t)(b * KVH_ + hv) * HD_ + d) * T_ + t;
        VThi[off] = hi; VTlo[off] = lo;
        return;
    }
    const float* w; __nv_bfloat16* dst; size_t srcoff; float post;
    if (hh < NH_) {
        w = qw; srcoff = (size_t)hh * HD_;
        dst = Qs + (((size_t)(b * NH_ + hh)) * T_ + t) * 256;
        post = 0.08838834764831845f;   // 1/sqrt(128)
    } else {
        int hk = hh - NH_;
        w = kw; srcoff = (size_t)NH_ * HD_ + hk * HD_;
        dst = Ks + (((size_t)(b * KVH_ + hk)) * T_ + t) * 256;
        post = 1.0f;
    }
    float xv = qkv[rowoff + srcoff + d];
    float other = __shfl_xor_sync(0xffffffffu, xv, 1);
    int i = d >> 1;
    float c = fcos[t * (HD_ / 2) + i];
    float s = fsin[t * (HD_ / 2) + i];
    float val = (d & 1) ? (other * s + xv * c) : (xv * c - other * s);

    float ss = val * val;
#pragma unroll
    for (int off = 16; off; off >>= 1) ss += __shfl_xor_sync(0xffffffffu, ss, off);
    __shared__ float wsum[4];
    if ((d & 31) == 0) wsum[d >> 5] = ss;
    __syncthreads();
    ss = wsum[0] + wsum[1] + wsum[2] + wsum[3];
    float rinv = rsqrtf(ss * (1.0f / HD_) + 1e-6f);
    float outv = w[d] * val * rinv * post;
    __nv_bfloat16 hi = __float2bfloat16_rn(outv);
    __nv_bfloat16 lo = __float2bfloat16_rn(outv - __bfloat162float(hi));
    dst[d] = hi;
    dst[128 + d] = lo;
}

// ---------------- flash attention via mma.sync bf16 hi/lo (unchanged, R7) ----------------
#define QPITCH 272        // bytes per 128-bf16 row (+8 pad)
#define VPITCH 144        // bytes per 64-bf16 row (+8 pad)
#define SM_Q_HI 0
#define SM_Q_LO 34816
#define SM_STAGE0 69632
#define KV_STAGE 71680
#define OFF_KHI 0
#define OFF_KLO 17408
#define OFF_VHI 34816
#define OFF_VLO 53248
#define FA_SMEM 212992

__device__ __forceinline__ void fa_load_kv(
    uint32_t st, const __nv_bfloat16* Kg, const __nv_bfloat16* Vhg,
    const __nv_bfloat16* Vlg, int kt, int tid)
{
#pragma unroll
    for (int j = 0; j < 4; j++) {
        int idx = tid + j * 256;            // 0..1023
        int r = idx >> 4, c = idx & 15;     // K: 64 rows x 16 chunks
        const __nv_bfloat16* krow = Kg + ((size_t)(kt * 64 + r)) * 256 + c * 8;
        cp16(st + OFF_KHI + (uint32_t)r * QPITCH + c * 16, krow);
        cp16(st + OFF_KLO + (uint32_t)r * QPITCH + c * 16, krow + 128);
        int rv = idx >> 3, cv = idx & 7;    // V^T: 128 rows x 8 chunks
        cp16(st + OFF_VHI + (uint32_t)rv * VPITCH + cv * 16,
             Vhg + (size_t)rv * T_ + kt * 64 + cv * 8);
        cp16(st + OFF_VLO + (uint32_t)rv * VPITCH + cv * 16,
             Vlg + (size_t)rv * T_ + kt * 64 + cv * 8);
    }
}

__global__ __launch_bounds__(256, 1) void flash_mma(
    const __nv_bfloat16* __restrict__ Qs, const __nv_bfloat16* __restrict__ Ks,
    const __nv_bfloat16* __restrict__ VThi, const __nv_bfloat16* __restrict__ VTlo,
    __nv_bfloat16* __restrict__ Ys)
{
    extern __shared__ char sm[];
    const uint32_t sb = smem_u32(sm);
    const int tid = threadIdx.x, w = tid >> 5, lane = tid & 31;
    const int qt = blockIdx.x, h = blockIdx.y, b = blockIdx.z;
    const int q0 = qt * 128;
    const int hk = h >> 2;
    const __nv_bfloat16* Qg = Qs + ((size_t)(b * NH_ + h) * T_ + q0) * 256;
    const __nv_bfloat16* Kg = Ks + (size_t)(b * KVH_ + hk) * T_ * 256;
    const __nv_bfloat16* Vhg = VThi + (size_t)(b * KVH_ + hk) * HD_ * T_;
    const __nv_bfloat16* Vlg = VTlo + (size_t)(b * KVH_ + hk) * HD_ * T_;

#pragma unroll
    for (int j = 0; j < 8; j++) {
        int idx = tid + j * 256;            // 0..2047
        int r = idx >> 4, c = idx & 15;
        const __nv_bfloat16* qrow = Qg + (size_t)r * 256 + c * 8;
        cp16(sb + SM_Q_HI + (uint32_t)r * QPITCH + c * 16, qrow);
        cp16(sb + SM_Q_LO + (uint32_t)r * QPITCH + c * 16, qrow + 128);
    }
    fa_load_kv(sb + SM_STAGE0, Kg, Vhg, Vlg, 0, tid);
    cp_commit();

    float O[16][4];
#pragma unroll
    for (int i = 0; i < 16; i++)
#pragma unroll
        for (int j = 0; j < 4; j++) O[i][j] = 0.f;
    float m0 = -1e30f, m1 = -1e30f, l0 = 0.f, l1 = 0.f;

    const int er = lane >> 2, ec2 = (lane & 3) * 2;
    const int a_row = lane & 15, a_kh = lane >> 4;
    const int b_row = (lane & 7) | ((lane >> 1) & 8), b_kh = (lane >> 3) & 1;
    const int row0 = q0 + w * 16 + er;
    const int nkt = 2 * qt + 2;

    for (int kt = 0; kt < nkt; kt++) {
        if (kt + 1 < nkt) {
            fa_load_kv(sb + SM_STAGE0 + ((kt + 1) & 1) * KV_STAGE, Kg, Vhg, Vlg,
                       kt + 1, tid);
            cp_commit();
            CP_WAIT(1);
        } else {
            CP_WAIT(0);
        }
        __syncthreads();

        const bool full_mask = (kt * 64) > (q0 + w * 16 + 15);   // warp-uniform
        if (!full_mask) {
            const uint32_t st = sb + SM_STAGE0 + (kt & 1) * KV_STAGE;

            float s[8][4];
#pragma unroll
            for (int i = 0; i < 8; i++)
#pragma unroll
                for (int j = 0; j < 4; j++) s[i][j] = 0.f;
#pragma unroll
            for (int ks = 0; ks < 8; ks++) {
                uint32_t ah[4], al[4];
                uint32_t qoff = (uint32_t)(w * 16 + a_row) * QPITCH + ks * 32 + a_kh * 16;
                ldm4(ah, sb + SM_Q_HI + qoff);
                ldm4(al, sb + SM_Q_LO + qoff);
#pragma unroll
                for (int ng = 0; ng < 4; ng++) {
                    uint32_t bh[4], bl[4];
                    uint32_t koff = (uint32_t)(ng * 16 + b_row) * QPITCH + ks * 32 + b_kh * 16;
                    ldm4(bh, st + OFF_KHI + koff);
                    ldm4(bl, st + OFF_KLO + koff);
                    mma16816(s[2 * ng],     ah, &bh[0]);
                    mma16816(s[2 * ng + 1], ah, &bh[2]);
                    mma16816(s[2 * ng],     ah, &bl[0]);
                    mma16816(s[2 * ng + 1], ah, &bl[2]);
                    mma16816(s[2 * ng],     al, &bh[0]);
                    mma16816(s[2 * ng + 1], al, &bh[2]);
                }
            }

            if ((kt * 64 + 63) > (q0 + w * 16)) {
#pragma unroll
                for (int nf = 0; nf < 8; nf++) {
                    int c0 = kt * 64 + nf * 8 + ec2;
                    if (c0     > row0)     s[nf][0] = -1e30f;
                    if (c0 + 1 > row0)     s[nf][1] = -1e30f;
                    if (c0     > row0 + 8) s[nf][2] = -1e30f;
                    if (c0 + 1 > row0 + 8) s[nf][3] = -1e30f;
                }
            }

            float mx0 = -1e30f, mx1 = -1e30f;
#pragma unroll
            for (int nf = 0; nf < 8; nf++) {
                mx0 = fmaxf(mx0, fmaxf(s[nf][0], s[nf][1]));
                mx1 = fmaxf(mx1, fmaxf(s[nf][2], s[nf][3]));
            }
            mx0 = fmaxf(mx0, __shfl_xor_sync(0xffffffffu, mx0, 1));
            mx0 = fmaxf(mx0, __shfl_xor_sync(0xffffffffu, mx0, 2));
            mx1 = fmaxf(mx1, __shfl_xor_sync(0xffffffffu, mx1, 1));
            mx1 = fmaxf(mx1, __shfl_xor_sync(0xffffffffu, mx1, 2));
            float mn0 = fmaxf(m0, mx0), mn1 = fmaxf(m1, mx1);
            float al0 = __expf(m0 - mn0), al1 = __expf(m1 - mn1);
            m0 = mn0; m1 = mn1;

            float ls0 = 0.f, ls1 = 0.f;
            uint32_t pah[4][4], pal[4][4];
#pragma unroll
            for (int nf = 0; nf < 8; nf++) {
                float p0 = __expf(s[nf][0] - mn0);
                float p1 = __expf(s[nf][1] - mn0);
                float p2 = __expf(s[nf][2] - mn1);
                float p3 = __expf(s[nf][3] - mn1);
                ls0 += p0 + p1; ls1 += p2 + p3;
                float h0 = bf_hi_part(p0), h1 = bf_hi_part(p1);
                float h2 = bf_hi_part(p2), h3 = bf_hi_part(p3);
                int q = nf >> 1, base = (nf & 1) * 2;
                pah[q][base]     = pack_bf(h0, h1);
                pah[q][base + 1] = pack_bf(h2, h3);
                pal[q][base]     = pack_bf(p0 - h0, p1 - h1);
                pal[q][base + 1] = pack_bf(p2 - h2, p3 - h3);
            }
            ls0 += __shfl_xor_sync(0xffffffffu, ls0, 1);
            ls0 += __shfl_xor_sync(0xffffffffu, ls0, 2);
            ls1 += __shfl_xor_sync(0xffffffffu, ls1, 1);
            ls1 += __shfl_xor_sync(0xffffffffu, ls1, 2);
            l0 = l0 * al0 + ls0;
            l1 = l1 * al1 + ls1;
#pragma unroll
            for (int df = 0; df < 16; df++) {
                O[df][0] *= al0; O[df][1] *= al0;
                O[df][2] *= al1; O[df][3] *= al1;
            }

#pragma unroll
            for (int q = 0; q < 4; q++) {
#pragma unroll
                for (int ng = 0; ng < 8; ng++) {
                    uint32_t vh[4], vl[4];
                    uint32_t voff = (uint32_t)(ng * 16 + b_row) * VPITCH + q * 32 + b_kh * 16;
                    ldm4(vh, st + OFF_VHI + voff);
                    ldm4(vl, st + OFF_VLO + voff);
                    mma16816(O[2 * ng],     pah[q], &vh[0]);
                    mma16816(O[2 * ng + 1], pah[q], &vh[2]);
                    mma16816(O[2 * ng],     pah[q], &vl[0]);
                    mma16816(O[2 * ng + 1], pah[q], &vl[2]);
                    mma16816(O[2 * ng],     pal[q], &vh[0]);
                    mma16816(O[2 * ng + 1], pal[q], &vh[2]);
                }
            }
        }
        __syncthreads();
    }

    float il0 = 1.0f / l0, il1 = 1.0f / l1;
    size_t r0 = (size_t)(b * T_ + q0 + w * 16 + er);
    __nv_bfloat16* y0 = Ys + r0 * LD2_ + h * HD_;
    __nv_bfloat16* y1 = Ys + (r0 + 8) * LD2_ + h * HD_;
#pragma unroll
    for (int nf = 0; nf < 16; nf++) {
        float v0 = O[nf][0] * il0, v1 = O[nf][1] * il0;
        float v2 = O[nf][2] * il1, v3 = O[nf][3] * il1;
        float h0 = bf_hi_part(v0), h1 = bf_hi_part(v1);
        float h2 = bf_hi_part(v2), h3 = bf_hi_part(v3);
        int co = nf * 8 + ec2;
        *(uint32_t*)(y0 + co)        = pack_bf(h0, h1);
        *(uint32_t*)(y0 + K_ + co)   = pack_bf(v0 - h0, v1 - h1);
        *(uint32_t*)(y1 + co)        = pack_bf(h2, h3);
        *(uint32_t*)(y1 + K_ + co)   = pack_bf(v2 - h2, v3 - h3);
    }
}

// ---------------- launch ----------------
extern "C" void kernel_launch(void* const* d_in, const int* in_sizes, int n_in,
                              void* d_out, int out_size)
{
    const float* x      = (const float*)d_in[0];
    const float* w_qkv  = (const float*)d_in[1];
    const float* w_proj = (const float*)d_in[2];
    const float* qw     = (const float*)d_in[3];
    const float* kw     = (const float*)d_in[4];
    const float* fcos   = (const float*)d_in[5];
    const float* fsin   = (const float*)d_in[6];
    float* out = (float*)d_out;

    float* p_qkv;
    __nv_bfloat16 *p_xs, *p_wqkvs, *p_wprojs, *p_ys, *p_qs, *p_ks, *p_vthi, *p_vtlo;
    cudaGetSymbolAddress((void**)&p_qkv,    g_qkv);
    cudaGetSymbolAddress((void**)&p_xs,     g_xs);
    cudaGetSymbolAddress((void**)&p_wqkvs,  g_wqkvs);
    cudaGetSymbolAddress((void**)&p_wprojs, g_wprojs);
    cudaGetSymbolAddress((void**)&p_ys,     g_ys);
    cudaGetSymbolAddress((void**)&p_qs,     g_qs);
    cudaGetSymbolAddress((void**)&p_ks,     g_ks);
    cudaGetSymbolAddress((void**)&p_vthi,   g_vthi);
    cudaGetSymbolAddress((void**)&p_vtlo,   g_vtlo);

    const int GEMM_SMEM = NSTAGE * GSTAGE;   // 184320
    cudaFuncSetAttribute(gemm_mma, cudaFuncAttributeMaxDynamicSharedMemorySize, GEMM_SMEM);
    cudaFuncSetAttribute(flash_mma, cudaFuncAttributeMaxDynamicSharedMemorySize, FA_SMEM);

    // 0) bf16 hi|lo splits of GEMM inputs
    conv_hilo<<<(BT_ * 512 + 255) / 256, 256>>>(x, p_xs, BT_);
    conv_hilo<<<(QKVD_ * 512 + 255) / 256, 256>>>(w_qkv, p_wqkvs, QKVD_);
    conv_hilo<<<(C_ * 512 + 255) / 256, 256>>>(w_proj, p_wprojs, C_);

    // 1) qkv = x @ w_qkv^T
    gemm_mma<<<dim3(QKVD_ / 256, BT_ / 128), 256, GEMM_SMEM>>>(p_xs, p_wqkvs, p_qkv, QKVD_);

    // 2) RoPE + RMSNorm -> bf16 hi/lo Q (pre-scaled), K, V^T
    qkv_transform<<<dim3(BT_, NH_ + 2 * KVH_), 128>>>(p_qkv, qw, kw, fcos, fsin,
                                                       p_qs, p_ks, p_vthi, p_vtlo);

    // 3) causal flash attention (tensor cores) -> y hi/lo
    flash_mma<<<dim3(T_ / 128, NH_, B_), 256, FA_SMEM>>>(p_qs, p_ks, p_vthi, p_vtlo, p_ys);

    // 4) out = y @ w_proj^T
    gemm_mma<<<dim3(C_ / 256, BT_ / 128), 256, GEMM_SMEM>>>(p_ys, p_wprojs, out, C_);
}

// round 9
// speedup vs baseline: 4.3797x; 1.5674x over previous
#include <cuda_runtime.h>
#include <cuda_bf16.h>
#include <cuda_fp16.h>
#include <cstdint>

typedef unsigned long long ull;

#define B_    2
#define T_    2048
#define C_    2048
#define NH_   16
#define KVH_  4
#define HD_   128
#define QKVD_ 3072
#define BT_   (B_*T_)
#define K_    2048

// ---------------- scratch ----------------
__device__ float g_qkv[(size_t)BT_ * QKVD_];
__device__ __half g_xs[(size_t)BT_ * K_];        // x fp16
__device__ __half g_wqkvs[(size_t)QKVD_ * K_];   // w_qkv fp16
__device__ __half g_wprojs[(size_t)C_ * K_];     // w_proj fp16
__device__ __half g_ysh[(size_t)BT_ * K_];       // y fp16 (flash output)
__device__ __nv_bfloat16 g_qs[(size_t)B_ * NH_ * T_ * 256];   // q rows: hi[128]|lo[128]
__device__ __nv_bfloat16 g_ks[(size_t)B_ * KVH_ * T_ * 256];  // k rows: hi|lo
__device__ __nv_bfloat16 g_vthi[(size_t)B_ * KVH_ * HD_ * T_]; // v^T hi  [d][t]
__device__ __nv_bfloat16 g_vtlo[(size_t)B_ * KVH_ * HD_ * T_]; // v^T lo

// ---------------- PTX helpers ----------------
__device__ __forceinline__ uint32_t smem_u32(const void* p) {
    uint32_t a;
    asm("{ .reg .u64 t; cvta.to.shared.u64 t, %1; cvt.u32.u64 %0, t; }" : "=r"(a) : "l"(p));
    return a;
}
__device__ __forceinline__ void cp16(uint32_t saddr, const void* g) {
    asm volatile("cp.async.cg.shared.global [%0], [%1], 16;" :: "r"(saddr), "l"(g) : "memory");
}
__device__ __forceinline__ void cp_commit() { asm volatile("cp.async.commit_group;" ::: "memory"); }
#define CP_WAIT(n) asm volatile("cp.async.wait_group %0;" :: "n"(n) : "memory")

__device__ __forceinline__ void ldm4(uint32_t* r, uint32_t addr) {
    asm volatile("ldmatrix.sync.aligned.m8n8.x4.shared.b16 {%0,%1,%2,%3}, [%4];"
                 : "=r"(r[0]), "=r"(r[1]), "=r"(r[2]), "=r"(r[3]) : "r"(addr));
}
// bf16 mma (attention)
__device__ __forceinline__ void mma16816(float* c, const uint32_t* a, const uint32_t* b) {
    asm volatile(
        "mma.sync.aligned.m16n8k16.row.col.f32.bf16.bf16.f32 "
        "{%0,%1,%2,%3}, {%4,%5,%6,%7}, {%8,%9}, {%0,%1,%2,%3};"
        : "+f"(c[0]), "+f"(c[1]), "+f"(c[2]), "+f"(c[3])
        : "r"(a[0]), "r"(a[1]), "r"(a[2]), "r"(a[3]), "r"(b[0]), "r"(b[1]));
}
// fp16 mma (GEMMs)
__device__ __forceinline__ void mma16816h(float* c, const uint32_t* a, const uint32_t* b) {
    asm volatile(
        "mma.sync.aligned.m16n8k16.row.col.f32.f16.f16.f32 "
        "{%0,%1,%2,%3}, {%4,%5,%6,%7}, {%8,%9}, {%0,%1,%2,%3};"
        : "+f"(c[0]), "+f"(c[1]), "+f"(c[2]), "+f"(c[3])
        : "r"(a[0]), "r"(a[1]), "r"(a[2]), "r"(a[3]), "r"(b[0]), "r"(b[1]));
}
// pack two fp32 -> bf16x2 ('lo' element in low half)
__device__ __forceinline__ uint32_t pack_bf(float lo, float hi) {
    uint32_t r;
    asm("cvt.rn.bf16x2.f32 %0, %1, %2;" : "=r"(r) : "f"(hi), "f"(lo));
    return r;
}
// pack two fp32 -> f16x2 ('lo' element in low half)
__device__ __forceinline__ uint32_t pack_h2(float lo, float hi) {
    uint32_t r;
    asm("cvt.rn.f16x2.f32 %0, %1, %2;" : "=r"(r) : "f"(hi), "f"(lo));
    return r;
}
__device__ __forceinline__ float bf_hi_part(float v) {
    return __bfloat162float(__float2bfloat16_rn(v));
}

// ---------------- fp32 -> fp16 conversion ----------------
__global__ __launch_bounds__(256) void conv_f16(
    const float* __restrict__ in, __half* __restrict__ out, int R)
{
    int i = blockIdx.x * 256 + threadIdx.x;
    int total = R * 512;
    if (i >= total) return;
    int r = i >> 9, c4 = (i & 511) << 2;
    float4 v = *(const float4*)(in + (size_t)r * K_ + c4);
    uint2 o;
    o.x = pack_h2(v.x, v.y);
    o.y = pack_h2(v.z, v.w);
    *(uint2*)(out + (size_t)r * K_ + c4) = o;
}

// ---------------- fp16 single-pass NT GEMM, 128x256 CTA / 64x64 warp ----------------
// C[M,N] fp32 = A[M,K] x B[N,K]^T, fp16 inputs, fp32 accum.
// 8 warps: wm = (wid&1)*64, wn = (wid>>1)*64. BK=32, 4-stage cp.async pipeline.
#define GT_A 0
#define GT_B 10240
#define GSTAGE  30720
#define NSTAGE  4
#define NCHUNK_G (K_ / 32)

__device__ __forceinline__ void g_load_stage(
    uint32_t st, const __half* Ag, const __half* Bg,
    size_t bm, size_t bn, int kc, int tid)
{
    // A: 128 rows x 32 fp16 (64B = 4 chunks)
#pragma unroll
    for (int j = 0; j < 2; j++) {
        int idx = tid + j * 256;           // 0..511
        int r = idx >> 2, c = idx & 3;
        cp16(st + GT_A + (uint32_t)r * 80 + c * 16, Ag + (bm + r) * K_ + kc + c * 8);
    }
    // B: 256 rows x 32 fp16
#pragma unroll
    for (int j = 0; j < 4; j++) {
        int idx = tid + j * 256;           // 0..1023
        int r = idx >> 2, c = idx & 3;
        cp16(st + GT_B + (uint32_t)r * 80 + c * 16, Bg + (bn + r) * K_ + kc + c * 8);
    }
}

__global__ __launch_bounds__(256, 1) void gemm_mma(
    const __half* __restrict__ Ag, const __half* __restrict__ Bg,
    float* __restrict__ Cm, int N)
{
    extern __shared__ char sm[];
    const uint32_t sb = smem_u32(sm);
    const int tid = threadIdx.x;
    const int wid = tid >> 5, lane = tid & 31;
    const size_t bm = (size_t)blockIdx.y * 128;
    const size_t bn = (size_t)blockIdx.x * 256;
    const int wm = (wid & 1) * 64;
    const int wn = (wid >> 1) * 64;

    float acc[4][8][4];
#pragma unroll
    for (int i = 0; i < 4; i++)
#pragma unroll
        for (int j = 0; j < 8; j++)
#pragma unroll
            for (int q = 0; q < 4; q++) acc[i][j][q] = 0.f;

    // prologue: prefetch 3 stages
#pragma unroll
    for (int s = 0; s < 3; s++) {
        g_load_stage(sb + s * GSTAGE, Ag, Bg, bm, bn, s * 32, tid);
        cp_commit();
    }

    const int a_row = lane & 15, a_kh = lane >> 4;
    const int b_row = (lane & 7) | ((lane >> 1) & 8);
    const int b_kh = (lane >> 3) & 1;

    int stg = 0;
    for (int ch = 0; ch < NCHUNK_G; ch++) {
        CP_WAIT(2);
        __syncthreads();

        // prefetch chunk ch+3 into the stage freed at ch-1
        if (ch + 3 < NCHUNK_G) {
            int ps = stg + 3 >= NSTAGE ? stg + 3 - NSTAGE : stg + 3;
            g_load_stage(sb + ps * GSTAGE, Ag, Bg, bm, bn, (ch + 3) * 32, tid);
        }
        cp_commit();

        const uint32_t st = sb + stg * GSTAGE;
#pragma unroll
        for (int ks = 0; ks < 2; ks++) {
            uint32_t ah[4][4];
#pragma unroll
            for (int mt = 0; mt < 4; mt++) {
                uint32_t off = (uint32_t)(wm + mt * 16 + a_row) * 80 + ks * 32 + a_kh * 16;
                ldm4(ah[mt], st + GT_A + off);
            }
#pragma unroll
            for (int ng = 0; ng < 4; ng++) {
                uint32_t bh[4];
                uint32_t off = (uint32_t)(wn + ng * 16 + b_row) * 80 + ks * 32 + b_kh * 16;
                ldm4(bh, st + GT_B + off);
#pragma unroll
                for (int mt = 0; mt < 4; mt++) {
                    mma16816h(acc[mt][2 * ng],     ah[mt], &bh[0]);
                    mma16816h(acc[mt][2 * ng + 1], ah[mt], &bh[2]);
                }
            }
        }
        stg = stg + 1 >= NSTAGE ? 0 : stg + 1;
    }

    const int er = lane >> 2, ec = (lane & 3) * 2;
#pragma unroll
    for (int mt = 0; mt < 4; mt++)
#pragma unroll
        for (int nf = 0; nf < 8; nf++) {
            size_t row = bm + wm + mt * 16 + er;
            size_t col = bn + wn + nf * 8 + ec;
            *(float2*)(Cm + row * (size_t)N + col) =
                make_float2(acc[mt][nf][0], acc[mt][nf][1]);
            *(float2*)(Cm + (row + 8) * (size_t)N + col) =
                make_float2(acc[mt][nf][2], acc[mt][nf][3]);
        }
}

// ---------------- RoPE + RMSNorm transform -> bf16 hi/lo outputs ----------------
__global__ __launch_bounds__(128) void qkv_transform(
    const float* __restrict__ qkv, const float* __restrict__ qw,
    const float* __restrict__ kw, const float* __restrict__ fcos,
    const float* __restrict__ fsin,
    __nv_bfloat16* __restrict__ Qs, __nv_bfloat16* __restrict__ Ks,
    __nv_bfloat16* __restrict__ VThi, __nv_bfloat16* __restrict__ VTlo)
{
    const int bt = blockIdx.x, hh = blockIdx.y;
    const int b = bt >> 11, t = bt & (T_ - 1);
    const int d = threadIdx.x;
    const size_t rowoff = (size_t)bt * QKVD_;

    if (hh >= NH_ + KVH_) {     // v: transpose + hi/lo split
        int hv = hh - (NH_ + KVH_);
        float val = qkv[rowoff + (size_t)(NH_ + KVH_) * HD_ + hv * HD_ + d];
        __nv_bfloat16 hi = __float2bfloat16_rn(val);
        __nv_bfloat16 lo = __float2bfloat16_rn(val - __bfloat162float(hi));
        size_t off = ((size_t)(b * KVH_ + hv) * HD_ + d) * T_ + t;
        VThi[off] = hi; VTlo[off] = lo;
        return;
    }
    const float* w; __nv_bfloat16* dst; size_t srcoff; float post;
    if (hh < NH_) {
        w = qw; srcoff = (size_t)hh * HD_;
        dst = Qs + (((size_t)(b * NH_ + hh)) * T_ + t) * 256;
        post = 0.08838834764831845f;   // 1/sqrt(128)
    } else {
        int hk = hh - NH_;
        w = kw; srcoff = (size_t)NH_ * HD_ + hk * HD_;
        dst = Ks + (((size_t)(b * KVH_ + hk)) * T_ + t) * 256;
        post = 1.0f;
    }
    float xv = qkv[rowoff + srcoff + d];
    float other = __shfl_xor_sync(0xffffffffu, xv, 1);
    int i = d >> 1;
    float c = fcos[t * (HD_ / 2) + i];
    float s = fsin[t * (HD_ / 2) + i];
    float val = (d & 1) ? (other * s + xv * c) : (xv * c - other * s);

    float ss = val * val;
#pragma unroll
    for (int off = 16; off; off >>= 1) ss += __shfl_xor_sync(0xffffffffu, ss, off);
    __shared__ float wsum[4];
    if ((d & 31) == 0) wsum[d >> 5] = ss;
    __syncthreads();
    ss = wsum[0] + wsum[1] + wsum[2] + wsum[3];
    float rinv = rsqrtf(ss * (1.0f / HD_) + 1e-6f);
    float outv = w[d] * val * rinv * post;
    __nv_bfloat16 hi = __float2bfloat16_rn(outv);
    __nv_bfloat16 lo = __float2bfloat16_rn(outv - __bfloat162float(hi));
    dst[d] = hi;
    dst[128 + d] = lo;
}

// ---------------- flash attention via mma.sync bf16 hi/lo ----------------
#define QPITCH 272        // bytes per 128-bf16 row (+8 pad)
#define VPITCH 144        // bytes per 64-bf16 row (+8 pad)
#define SM_Q_HI 0
#define SM_Q_LO 34816
#define SM_STAGE0 69632
#define KV_STAGE 71680
#define OFF_KHI 0
#define OFF_KLO 17408
#define OFF_VHI 34816
#define OFF_VLO 53248
#define FA_SMEM 212992

__device__ __forceinline__ void fa_load_kv(
    uint32_t st, const __nv_bfloat16* Kg, const __nv_bfloat16* Vhg,
    const __nv_bfloat16* Vlg, int kt, int tid)
{
#pragma unroll
    for (int j = 0; j < 4; j++) {
        int idx = tid + j * 256;            // 0..1023
        int r = idx >> 4, c = idx & 15;     // K: 64 rows x 16 chunks
        const __nv_bfloat16* krow = Kg + ((size_t)(kt * 64 + r)) * 256 + c * 8;
        cp16(st + OFF_KHI + (uint32_t)r * QPITCH + c * 16, krow);
        cp16(st + OFF_KLO + (uint32_t)r * QPITCH + c * 16, krow + 128);
        int rv = idx >> 3, cv = idx & 7;    // V^T: 128 rows x 8 chunks
        cp16(st + OFF_VHI + (uint32_t)rv * VPITCH + cv * 16,
             Vhg + (size_t)rv * T_ + kt * 64 + cv * 8);
        cp16(st + OFF_VLO + (uint32_t)rv * VPITCH + cv * 16,
             Vlg + (size_t)rv * T_ + kt * 64 + cv * 8);
    }
}

__global__ __launch_bounds__(256, 1) void flash_mma(
    const __nv_bfloat16* __restrict__ Qs, const __nv_bfloat16* __restrict__ Ks,
    const __nv_bfloat16* __restrict__ VThi, const __nv_bfloat16* __restrict__ VTlo,
    __half* __restrict__ Ys)
{
    extern __shared__ char sm[];
    const uint32_t sb = smem_u32(sm);
    const int tid = threadIdx.x, w = tid >> 5, lane = tid & 31;
    const int qt = blockIdx.x, h = blockIdx.y, b = blockIdx.z;
    const int q0 = qt * 128;
    const int hk = h >> 2;
    const __nv_bfloat16* Qg = Qs + ((size_t)(b * NH_ + h) * T_ + q0) * 256;
    const __nv_bfloat16* Kg = Ks + (size_t)(b * KVH_ + hk) * T_ * 256;
    const __nv_bfloat16* Vhg = VThi + (size_t)(b * KVH_ + hk) * HD_ * T_;
    const __nv_bfloat16* Vlg = VTlo + (size_t)(b * KVH_ + hk) * HD_ * T_;

#pragma unroll
    for (int j = 0; j < 8; j++) {
        int idx = tid + j * 256;            // 0..2047
        int r = idx >> 4, c = idx & 15;
        const __nv_bfloat16* qrow = Qg + (size_t)r * 256 + c * 8;
        cp16(sb + SM_Q_HI + (uint32_t)r * QPITCH + c * 16, qrow);
        cp16(sb + SM_Q_LO + (uint32_t)r * QPITCH + c * 16, qrow + 128);
    }
    fa_load_kv(sb + SM_STAGE0, Kg, Vhg, Vlg, 0, tid);
    cp_commit();

    float O[16][4];
#pragma unroll
    for (int i = 0; i < 16; i++)
#pragma unroll
        for (int j = 0; j < 4; j++) O[i][j] = 0.f;
    float m0 = -1e30f, m1 = -1e30f, l0 = 0.f, l1 = 0.f;

    const int er = lane >> 2, ec2 = (lane & 3) * 2;
    const int a_row = lane & 15, a_kh = lane >> 4;
    const int b_row = (lane & 7) | ((lane >> 1) & 8), b_kh = (lane >> 3) & 1;
    const int row0 = q0 + w * 16 + er;
    const int nkt = 2 * qt + 2;

    for (int kt = 0; kt < nkt; kt++) {
        if (kt + 1 < nkt) {
            fa_load_kv(sb + SM_STAGE0 + ((kt + 1) & 1) * KV_STAGE, Kg, Vhg, Vlg,
                       kt + 1, tid);
            cp_commit();
            CP_WAIT(1);
        } else {
            CP_WAIT(0);
        }
        __syncthreads();

        const bool full_mask = (kt * 64) > (q0 + w * 16 + 15);   // warp-uniform
        if (!full_mask) {
            const uint32_t st = sb + SM_STAGE0 + (kt & 1) * KV_STAGE;

            float s[8][4];
#pragma unroll
            for (int i = 0; i < 8; i++)
#pragma unroll
                for (int j = 0; j < 4; j++) s[i][j] = 0.f;
#pragma unroll
            for (int ks = 0; ks < 8; ks++) {
                uint32_t ah[4], al[4];
                uint32_t qoff = (uint32_t)(w * 16 + a_row) * QPITCH + ks * 32 + a_kh * 16;
                ldm4(ah, sb + SM_Q_HI + qoff);
                ldm4(al, sb + SM_Q_LO + qoff);
#pragma unroll
                for (int ng = 0; ng < 4; ng++) {
                    uint32_t bh[4], bl[4];
                    uint32_t koff = (uint32_t)(ng * 16 + b_row) * QPITCH + ks * 32 + b_kh * 16;
                    ldm4(bh, st + OFF_KHI + koff);
                    ldm4(bl, st + OFF_KLO + koff);
                    mma16816(s[2 * ng],     ah, &bh[0]);
                    mma16816(s[2 * ng + 1], ah, &bh[2]);
                    mma16816(s[2 * ng],     ah, &bl[0]);
                    mma16816(s[2 * ng + 1], ah, &bl[2]);
                    mma16816(s[2 * ng],     al, &bh[0]);
                    mma16816(s[2 * ng + 1], al, &bh[2]);
                }
            }

            if ((kt * 64 + 63) > (q0 + w * 16)) {
#pragma unroll
                for (int nf = 0; nf < 8; nf++) {
                    int c0 = kt * 64 + nf * 8 + ec2;
                    if (c0     > row0)     s[nf][0] = -1e30f;
                    if (c0 + 1 > row0)     s[nf][1] = -1e30f;
                    if (c0     > row0 + 8) s[nf][2] = -1e30f;
                    if (c0 + 1 > row0 + 8) s[nf][3] = -1e30f;
                }
            }

            float mx0 = -1e30f, mx1 = -1e30f;
#pragma unroll
            for (int nf = 0; nf < 8; nf++) {
                mx0 = fmaxf(mx0, fmaxf(s[nf][0], s[nf][1]));
                mx1 = fmaxf(mx1, fmaxf(s[nf][2], s[nf][3]));
            }
            mx0 = fmaxf(mx0, __shfl_xor_sync(0xffffffffu, mx0, 1));
            mx0 = fmaxf(mx0, __shfl_xor_sync(0xffffffffu, mx0, 2));
            mx1 = fmaxf(mx1, __shfl_xor_sync(0xffffffffu, mx1, 1));
            mx1 = fmaxf(mx1, __shfl_xor_sync(0xffffffffu, mx1, 2));
            float mn0 = fmaxf(m0, mx0), mn1 = fmaxf(m1, mx1);
            float al0 = __expf(m0 - mn0), al1 = __expf(m1 - mn1);
            m0 = mn0; m1 = mn1;

            float ls0 = 0.f, ls1 = 0.f;
            uint32_t pah[4][4], pal[4][4];
#pragma unroll
            for (int nf = 0; nf < 8; nf++) {
                float p0 = __expf(s[nf][0] - mn0);
                float p1 = __expf(s[nf][1] - mn0);
                float p2 = __expf(s[nf][2] - mn1);
                float p3 = __expf(s[nf][3] - mn1);
                ls0 += p0 + p1; ls1 += p2 + p3;
                float h0 = bf_hi_part(p0), h1 = bf_hi_part(p1);
                float h2 = bf_hi_part(p2), h3 = bf_hi_part(p3);
                int q = nf >> 1, base = (nf & 1) * 2;
                pah[q][base]     = pack_bf(h0, h1);
                pah[q][base + 1] = pack_bf(h2, h3);
                pal[q][base]     = pack_bf(p0 - h0, p1 - h1);
                pal[q][base + 1] = pack_bf(p2 - h2, p3 - h3);
            }
            ls0 += __shfl_xor_sync(0xffffffffu, ls0, 1);
            ls0 += __shfl_xor_sync(0xffffffffu, ls0, 2);
            ls1 += __shfl_xor_sync(0xffffffffu, ls1, 1);
            ls1 += __shfl_xor_sync(0xffffffffu, ls1, 2);
            l0 = l0 * al0 + ls0;
            l1 = l1 * al1 + ls1;
#pragma unroll
            for (int df = 0; df < 16; df++) {
                O[df][0] *= al0; O[df][1] *= al0;
                O[df][2] *= al1; O[df][3] *= al1;
            }

#pragma unroll
            for (int q = 0; q < 4; q++) {
#pragma unroll
                for (int ng = 0; ng < 8; ng++) {
                    uint32_t vh[4], vl[4];
                    uint32_t voff = (uint32_t)(ng * 16 + b_row) * VPITCH + q * 32 + b_kh * 16;
                    ldm4(vh, st + OFF_VHI + voff);
                    ldm4(vl, st + OFF_VLO + voff);
                    mma16816(O[2 * ng],     pah[q], &vh[0]);
                    mma16816(O[2 * ng + 1], pah[q], &vh[2]);
                    mma16816(O[2 * ng],     pah[q], &vl[0]);
                    mma16816(O[2 * ng + 1], pah[q], &vl[2]);
                    mma16816(O[2 * ng],     pal[q], &vh[0]);
                    mma16816(O[2 * ng + 1], pal[q], &vh[2]);
                }
            }
        }
        __syncthreads();
    }

    // epilogue: normalize, write y as fp16 (proj GEMM A operand)
    float il0 = 1.0f / l0, il1 = 1.0f / l1;
    size_t r0 = (size_t)(b * T_ + q0 + w * 16 + er);
    __half* y0 = Ys + r0 * K_ + h * HD_;
    __half* y1 = Ys + (r0 + 8) * K_ + h * HD_;
#pragma unroll
    for (int nf = 0; nf < 16; nf++) {
        int co = nf * 8 + ec2;
        *(uint32_t*)(y0 + co) = pack_h2(O[nf][0] * il0, O[nf][1] * il0);
        *(uint32_t*)(y1 + co) = pack_h2(O[nf][2] * il1, O[nf][3] * il1);
    }
}

// ---------------- launch ----------------
extern "C" void kernel_launch(void* const* d_in, const int* in_sizes, int n_in,
                              void* d_out, int out_size)
{
    const float* x      = (const float*)d_in[0];
    const float* w_qkv  = (const float*)d_in[1];
    const float* w_proj = (const float*)d_in[2];
    const float* qw     = (const float*)d_in[3];
    const float* kw     = (const float*)d_in[4];
    const float* fcos   = (const float*)d_in[5];
    const float* fsin   = (const float*)d_in[6];
    float* out = (float*)d_out;

    float* p_qkv;
    __half *p_xs, *p_wqkvs, *p_wprojs, *p_ysh;
    __nv_bfloat16 *p_qs, *p_ks, *p_vthi, *p_vtlo;
    cudaGetSymbolAddress((void**)&p_qkv,    g_qkv);
    cudaGetSymbolAddress((void**)&p_xs,     g_xs);
    cudaGetSymbolAddress((void**)&p_wqkvs,  g_wqkvs);
    cudaGetSymbolAddress((void**)&p_wprojs, g_wprojs);
    cudaGetSymbolAddress((void**)&p_ysh,    g_ysh);
    cudaGetSymbolAddress((void**)&p_qs,     g_qs);
    cudaGetSymbolAddress((void**)&p_ks,     g_ks);
    cudaGetSymbolAddress((void**)&p_vthi,   g_vthi);
    cudaGetSymbolAddress((void**)&p_vtlo,   g_vtlo);

    const int GEMM_SMEM = NSTAGE * GSTAGE;   // 122880
    cudaFuncSetAttribute(gemm_mma, cudaFuncAttributeMaxDynamicSharedMemorySize, GEMM_SMEM);
    cudaFuncSetAttribute(flash_mma, cudaFuncAttributeMaxDynamicSharedMemorySize, FA_SMEM);

    // 0) fp16 conversions of GEMM inputs
    conv_f16<<<(BT_ * 512 + 255) / 256, 256>>>(x, p_xs, BT_);
    conv_f16<<<(QKVD_ * 512 + 255) / 256, 256>>>(w_qkv, p_wqkvs, QKVD_);
    conv_f16<<<(C_ * 512 + 255) / 256, 256>>>(w_proj, p_wprojs, C_);

    // 1) qkv = x @ w_qkv^T
    gemm_mma<<<dim3(QKVD_ / 256, BT_ / 128), 256, GEMM_SMEM>>>(p_xs, p_wqkvs, p_qkv, QKVD_);

    // 2) RoPE + RMSNorm -> bf16 hi/lo Q (pre-scaled), K, V^T
    qkv_transform<<<dim3(BT_, NH_ + 2 * KVH_), 128>>>(p_qkv, qw, kw, fcos, fsin,
                                                       p_qs, p_ks, p_vthi, p_vtlo);

    // 3) causal flash attention (tensor cores, bf16 hi/lo) -> y fp16
    flash_mma<<<dim3(T_ / 128, NH_, B_), 256, FA_SMEM>>>(p_qs, p_ks, p_vthi, p_vtlo, p_ysh);

    // 4) out = y @ w_proj^T
    gemm_mma<<<dim3(C_ / 256, BT_ / 128), 256, GEMM_SMEM>>>(p_ysh, p_wprojs, out, C_);
}

// round 10
// speedup vs baseline: 5.9714x; 1.3634x over previous
#include <cuda_runtime.h>
#include <cuda_bf16.h>
#include <cuda_fp16.h>
#include <cstdint>

#define B_    2
#define T_    2048
#define C_    2048
#define NH_   16
#define KVH_  4
#define HD_   128
#define QKVD_ 3072
#define BT_   (B_*T_)
#define K_    2048

// ---------------- scratch ----------------
__device__ float g_qkv[(size_t)BT_ * QKVD_];
__device__ __half g_xs[(size_t)BT_ * K_];        // x fp16
__device__ __half g_wqkvs[(size_t)QKVD_ * K_];   // w_qkv fp16
__device__ __half g_wprojs[(size_t)C_ * K_];     // w_proj fp16
__device__ __half g_ysh[(size_t)BT_ * K_];       // y fp16 (flash output)
__device__ __half g_qs[(size_t)B_ * NH_ * T_ * HD_];   // q fp16 (pre-scaled)
__device__ __half g_ks[(size_t)B_ * KVH_ * T_ * HD_];  // k fp16
__device__ __half g_vt[(size_t)B_ * KVH_ * HD_ * T_];  // v^T fp16 [d][t]

// ---------------- PTX helpers ----------------
__device__ __forceinline__ uint32_t smem_u32(const void* p) {
    uint32_t a;
    asm("{ .reg .u64 t; cvta.to.shared.u64 t, %1; cvt.u32.u64 %0, t; }" : "=r"(a) : "l"(p));
    return a;
}
__device__ __forceinline__ void cp16(uint32_t saddr, const void* g) {
    asm volatile("cp.async.cg.shared.global [%0], [%1], 16;" :: "r"(saddr), "l"(g) : "memory");
}
__device__ __forceinline__ void cp_commit() { asm volatile("cp.async.commit_group;" ::: "memory"); }
#define CP_WAIT(n) asm volatile("cp.async.wait_group %0;" :: "n"(n) : "memory")

__device__ __forceinline__ void ldm4(uint32_t* r, uint32_t addr) {
    asm volatile("ldmatrix.sync.aligned.m8n8.x4.shared.b16 {%0,%1,%2,%3}, [%4];"
                 : "=r"(r[0]), "=r"(r[1]), "=r"(r[2]), "=r"(r[3]) : "r"(addr));
}
// fp16 mma, fp32 accum
__device__ __forceinline__ void mma16816h(float* c, const uint32_t* a, const uint32_t* b) {
    asm volatile(
        "mma.sync.aligned.m16n8k16.row.col.f32.f16.f16.f32 "
        "{%0,%1,%2,%3}, {%4,%5,%6,%7}, {%8,%9}, {%0,%1,%2,%3};"
        : "+f"(c[0]), "+f"(c[1]), "+f"(c[2]), "+f"(c[3])
        : "r"(a[0]), "r"(a[1]), "r"(a[2]), "r"(a[3]), "r"(b[0]), "r"(b[1]));
}
// pack two fp32 -> f16x2 ('lo' element in low half)
__device__ __forceinline__ uint32_t pack_h2(float lo, float hi) {
    uint32_t r;
    asm("cvt.rn.f16x2.f32 %0, %1, %2;" : "=r"(r) : "f"(hi), "f"(lo));
    return r;
}

// ---------------- fp32 -> fp16 conversion ----------------
__global__ __launch_bounds__(256) void conv_f16(
    const float* __restrict__ in, __half* __restrict__ out, int R)
{
    int i = blockIdx.x * 256 + threadIdx.x;
    int total = R * 512;
    if (i >= total) return;
    int r = i >> 9, c4 = (i & 511) << 2;
    float4 v = *(const float4*)(in + (size_t)r * K_ + c4);
    uint2 o;
    o.x = pack_h2(v.x, v.y);
    o.y = pack_h2(v.z, v.w);
    *(uint2*)(out + (size_t)r * K_ + c4) = o;
}

// ---------------- fp16 NT GEMM, 128x256 CTA / 64x64 warp (R9, unchanged) ----------------
#define GT_A 0
#define GT_B 10240
#define GSTAGE  30720
#define NSTAGE  4
#define NCHUNK_G (K_ / 32)

__device__ __forceinline__ void g_load_stage(
    uint32_t st, const __half* Ag, const __half* Bg,
    size_t bm, size_t bn, int kc, int tid)
{
#pragma unroll
    for (int j = 0; j < 2; j++) {
        int idx = tid + j * 256;
        int r = idx >> 2, c = idx & 3;
        cp16(st + GT_A + (uint32_t)r * 80 + c * 16, Ag + (bm + r) * K_ + kc + c * 8);
    }
#pragma unroll
    for (int j = 0; j < 4; j++) {
        int idx = tid + j * 256;
        int r = idx >> 2, c = idx & 3;
        cp16(st + GT_B + (uint32_t)r * 80 + c * 16, Bg + (bn + r) * K_ + kc + c * 8);
    }
}

__global__ __launch_bounds__(256, 1) void gemm_mma(
    const __half* __restrict__ Ag, const __half* __restrict__ Bg,
    float* __restrict__ Cm, int N)
{
    extern __shared__ char sm[];
    const uint32_t sb = smem_u32(sm);
    const int tid = threadIdx.x;
    const int wid = tid >> 5, lane = tid & 31;
    const size_t bm = (size_t)blockIdx.y * 128;
    const size_t bn = (size_t)blockIdx.x * 256;
    const int wm = (wid & 1) * 64;
    const int wn = (wid >> 1) * 64;

    float acc[4][8][4];
#pragma unroll
    for (int i = 0; i < 4; i++)
#pragma unroll
        for (int j = 0; j < 8; j++)
#pragma unroll
            for (int q = 0; q < 4; q++) acc[i][j][q] = 0.f;

#pragma unroll
    for (int s = 0; s < 3; s++) {
        g_load_stage(sb + s * GSTAGE, Ag, Bg, bm, bn, s * 32, tid);
        cp_commit();
    }

    const int a_row = lane & 15, a_kh = lane >> 4;
    const int b_row = (lane & 7) | ((lane >> 1) & 8);
    const int b_kh = (lane >> 3) & 1;

    int stg = 0;
    for (int ch = 0; ch < NCHUNK_G; ch++) {
        CP_WAIT(2);
        __syncthreads();

        if (ch + 3 < NCHUNK_G) {
            int ps = stg + 3 >= NSTAGE ? stg + 3 - NSTAGE : stg + 3;
            g_load_stage(sb + ps * GSTAGE, Ag, Bg, bm, bn, (ch + 3) * 32, tid);
        }
        cp_commit();

        const uint32_t st = sb + stg * GSTAGE;
#pragma unroll
        for (int ks = 0; ks < 2; ks++) {
            uint32_t ah[4][4];
#pragma unroll
            for (int mt = 0; mt < 4; mt++) {
                uint32_t off = (uint32_t)(wm + mt * 16 + a_row) * 80 + ks * 32 + a_kh * 16;
                ldm4(ah[mt], st + GT_A + off);
            }
#pragma unroll
            for (int ng = 0; ng < 4; ng++) {
                uint32_t bh[4];
                uint32_t off = (uint32_t)(wn + ng * 16 + b_row) * 80 + ks * 32 + b_kh * 16;
                ldm4(bh, st + GT_B + off);
#pragma unroll
                for (int mt = 0; mt < 4; mt++) {
                    mma16816h(acc[mt][2 * ng],     ah[mt], &bh[0]);
                    mma16816h(acc[mt][2 * ng + 1], ah[mt], &bh[2]);
                }
            }
        }
        stg = stg + 1 >= NSTAGE ? 0 : stg + 1;
    }

    const int er = lane >> 2, ec = (lane & 3) * 2;
#pragma unroll
    for (int mt = 0; mt < 4; mt++)
#pragma unroll
        for (int nf = 0; nf < 8; nf++) {
            size_t row = bm + wm + mt * 16 + er;
            size_t col = bn + wn + nf * 8 + ec;
            *(float2*)(Cm + row * (size_t)N + col) =
                make_float2(acc[mt][nf][0], acc[mt][nf][1]);
            *(float2*)(Cm + (row + 8) * (size_t)N + col) =
                make_float2(acc[mt][nf][2], acc[mt][nf][3]);
        }
}

// ---------------- RoPE + RMSNorm transform -> fp16 outputs ----------------
__global__ __launch_bounds__(128) void qkv_transform(
    const float* __restrict__ qkv, const float* __restrict__ qw,
    const float* __restrict__ kw, const float* __restrict__ fcos,
    const float* __restrict__ fsin,
    __half* __restrict__ Qs, __half* __restrict__ Ks,
    __half* __restrict__ VT)
{
    const int bt = blockIdx.x, hh = blockIdx.y;
    const int b = bt >> 11, t = bt & (T_ - 1);
    const int d = threadIdx.x;
    const size_t rowoff = (size_t)bt * QKVD_;

    if (hh >= NH_ + KVH_) {     // v: transpose
        int hv = hh - (NH_ + KVH_);
        float val = qkv[rowoff + (size_t)(NH_ + KVH_) * HD_ + hv * HD_ + d];
        VT[((size_t)(b * KVH_ + hv) * HD_ + d) * T_ + t] = __float2half(val);
        return;
    }
    const float* w; __half* dst; size_t srcoff; float post;
    if (hh < NH_) {
        w = qw; srcoff = (size_t)hh * HD_;
        dst = Qs + (((size_t)(b * NH_ + hh)) * T_ + t) * HD_;
        post = 0.08838834764831845f;   // 1/sqrt(128)
    } else {
        int hk = hh - NH_;
        w = kw; srcoff = (size_t)NH_ * HD_ + hk * HD_;
        dst = Ks + (((size_t)(b * KVH_ + hk)) * T_ + t) * HD_;
        post = 1.0f;
    }
    float xv = qkv[rowoff + srcoff + d];
    float other = __shfl_xor_sync(0xffffffffu, xv, 1);
    int i = d >> 1;
    float c = fcos[t * (HD_ / 2) + i];
    float s = fsin[t * (HD_ / 2) + i];
    float val = (d & 1) ? (other * s + xv * c) : (xv * c - other * s);

    float ss = val * val;
#pragma unroll
    for (int off = 16; off; off >>= 1) ss += __shfl_xor_sync(0xffffffffu, ss, off);
    __shared__ float wsum[4];
    if ((d & 31) == 0) wsum[d >> 5] = ss;
    __syncthreads();
    ss = wsum[0] + wsum[1] + wsum[2] + wsum[3];
    float rinv = rsqrtf(ss * (1.0f / HD_) + 1e-6f);
    dst[d] = __float2half(w[d] * val * rinv * post);
}

// ---------------- flash attention via mma.sync fp16 (single term) ----------------
// CTA: 128 q-rows x (b,h). 8 warps, warp w owns rows [w*16, w*16+16).
// K-tiles of 64, double-buffered. Q frags hoisted to registers.
#define QPITCH 272        // bytes per 128-fp16 row (256B + 16 pad)
#define VPITCH 144        // bytes per 64-fp16 row (128B + 16 pad)
#define SM_Q 0
#define SM_STAGE0 34816
#define KV_STAGE 35840
#define OFF_K 0
#define OFF_V 17408
#define FA_SMEM (34816 + 2 * 35840)   // 106496

__device__ __forceinline__ void fa_load_kv(
    uint32_t st, const __half* Kg, const __half* Vg, int kt, int tid)
{
#pragma unroll
    for (int j = 0; j < 4; j++) {
        int idx = tid + j * 256;            // 0..1023
        int r = idx >> 4, c = idx & 15;     // K: 64 rows x 16 chunks
        cp16(st + OFF_K + (uint32_t)r * QPITCH + c * 16,
             Kg + ((size_t)(kt * 64 + r)) * HD_ + c * 8);
        int rv = idx >> 3, cv = idx & 7;    // V^T: 128 rows x 8 chunks
        cp16(st + OFF_V + (uint32_t)rv * VPITCH + cv * 16,
             Vg + (size_t)rv * T_ + kt * 64 + cv * 8);
    }
}

__global__ __launch_bounds__(256, 1) void flash_mma(
    const __half* __restrict__ Qs, const __half* __restrict__ Ks,
    const __half* __restrict__ VT, __half* __restrict__ Ys)
{
    extern __shared__ char sm[];
    const uint32_t sb = smem_u32(sm);
    const int tid = threadIdx.x, w = tid >> 5, lane = tid & 31;
    const int qt = blockIdx.x, h = blockIdx.y, b = blockIdx.z;
    const int q0 = qt * 128;
    const int hk = h >> 2;
    const __half* Qg = Qs + ((size_t)(b * NH_ + h) * T_ + q0) * HD_;
    const __half* Kg = Ks + (size_t)(b * KVH_ + hk) * T_ * HD_;
    const __half* Vg = VT + (size_t)(b * KVH_ + hk) * HD_ * T_;

    // load Q tile + first KV tile
#pragma unroll
    for (int j = 0; j < 8; j++) {
        int idx = tid + j * 256;            // 0..2047
        int r = idx >> 4, c = idx & 15;
        cp16(sb + SM_Q + (uint32_t)r * QPITCH + c * 16, Qg + (size_t)r * HD_ + c * 8);
    }
    fa_load_kv(sb + SM_STAGE0, Kg, Vg, 0, tid);
    cp_commit();

    float O[16][4];
#pragma unroll
    for (int i = 0; i < 16; i++)
#pragma unroll
        for (int j = 0; j < 4; j++) O[i][j] = 0.f;
    float m0 = -1e30f, m1 = -1e30f, l0 = 0.f, l1 = 0.f;

    const int er = lane >> 2, ec2 = (lane & 3) * 2;
    const int a_row = lane & 15, a_kh = lane >> 4;
    const int b_row = (lane & 7) | ((lane >> 1) & 8), b_kh = (lane >> 3) & 1;
    const int row0 = q0 + w * 16 + er;
    const int nkt = 2 * qt + 2;

    uint32_t qf[8][4];      // hoisted Q fragments (whole 128-d row strip)

    for (int kt = 0; kt < nkt; kt++) {
        if (kt + 1 < nkt) {
            fa_load_kv(sb + SM_STAGE0 + ((kt + 1) & 1) * KV_STAGE, Kg, Vg, kt + 1, tid);
            cp_commit();
            CP_WAIT(1);
        } else {
            CP_WAIT(0);
        }
        __syncthreads();

        if (kt == 0) {
#pragma unroll
            for (int ks = 0; ks < 8; ks++) {
                uint32_t qoff = (uint32_t)(w * 16 + a_row) * QPITCH + ks * 32 + a_kh * 16;
                ldm4(qf[ks], sb + SM_Q + qoff);
            }
        }

        const bool full_mask = (kt * 64) > (q0 + w * 16 + 15);   // warp-uniform
        if (!full_mask) {
            const uint32_t st = sb + SM_STAGE0 + (kt & 1) * KV_STAGE;

            // ---- S = Q K^T ----
            float s[8][4];
#pragma unroll
            for (int i = 0; i < 8; i++)
#pragma unroll
                for (int j = 0; j < 4; j++) s[i][j] = 0.f;
#pragma unroll
            for (int ks = 0; ks < 8; ks++) {
#pragma unroll
                for (int ng = 0; ng < 4; ng++) {
                    uint32_t bh[4];
                    uint32_t koff = (uint32_t)(ng * 16 + b_row) * QPITCH + ks * 32 + b_kh * 16;
                    ldm4(bh, st + OFF_K + koff);
                    mma16816h(s[2 * ng],     qf[ks], &bh[0]);
                    mma16816h(s[2 * ng + 1], qf[ks], &bh[2]);
                }
            }

            // ---- causal mask ----
            if ((kt * 64 + 63) > (q0 + w * 16)) {
#pragma unroll
                for (int nf = 0; nf < 8; nf++) {
                    int c0 = kt * 64 + nf * 8 + ec2;
                    if (c0     > row0)     s[nf][0] = -1e30f;
                    if (c0 + 1 > row0)     s[nf][1] = -1e30f;
                    if (c0     > row0 + 8) s[nf][2] = -1e30f;
                    if (c0 + 1 > row0 + 8) s[nf][3] = -1e30f;
                }
            }

            // ---- streaming softmax (quad-local) ----
            float mx0 = -1e30f, mx1 = -1e30f;
#pragma unroll
            for (int nf = 0; nf < 8; nf++) {
                mx0 = fmaxf(mx0, fmaxf(s[nf][0], s[nf][1]));
                mx1 = fmaxf(mx1, fmaxf(s[nf][2], s[nf][3]));
            }
            mx0 = fmaxf(mx0, __shfl_xor_sync(0xffffffffu, mx0, 1));
            mx0 = fmaxf(mx0, __shfl_xor_sync(0xffffffffu, mx0, 2));
            mx1 = fmaxf(mx1, __shfl_xor_sync(0xffffffffu, mx1, 1));
            mx1 = fmaxf(mx1, __shfl_xor_sync(0xffffffffu, mx1, 2));
            float mn0 = fmaxf(m0, mx0), mn1 = fmaxf(m1, mx1);
            float al0 = __expf(m0 - mn0), al1 = __expf(m1 - mn1);
            m0 = mn0; m1 = mn1;

            float ls0 = 0.f, ls1 = 0.f;
            uint32_t pa[4][4];
#pragma unroll
            for (int nf = 0; nf < 8; nf++) {
                float p0 = __expf(s[nf][0] - mn0);
                float p1 = __expf(s[nf][1] - mn0);
                float p2 = __expf(s[nf][2] - mn1);
                float p3 = __expf(s[nf][3] - mn1);
                ls0 += p0 + p1; ls1 += p2 + p3;
                int q = nf >> 1, base = (nf & 1) * 2;
                pa[q][base]     = pack_h2(p0, p1);
                pa[q][base + 1] = pack_h2(p2, p3);
            }
            ls0 += __shfl_xor_sync(0xffffffffu, ls0, 1);
            ls0 += __shfl_xor_sync(0xffffffffu, ls0, 2);
            ls1 += __shfl_xor_sync(0xffffffffu, ls1, 1);
            ls1 += __shfl_xor_sync(0xffffffffu, ls1, 2);
            l0 = l0 * al0 + ls0;
            l1 = l1 * al1 + ls1;
#pragma unroll
            for (int df = 0; df < 16; df++) {
                O[df][0] *= al0; O[df][1] *= al0;
                O[df][2] *= al1; O[df][3] *= al1;
            }

            // ---- O += P V ----
#pragma unroll
            for (int q = 0; q < 4; q++) {
#pragma unroll
                for (int ng = 0; ng < 8; ng++) {
                    uint32_t vh[4];
                    uint32_t voff = (uint32_t)(ng * 16 + b_row) * VPITCH + q * 32 + b_kh * 16;
                    ldm4(vh, st + OFF_V + voff);
                    mma16816h(O[2 * ng],     pa[q], &vh[0]);
                    mma16816h(O[2 * ng + 1], pa[q], &vh[2]);
                }
            }
        }
        __syncthreads();
    }

    // epilogue: normalize, write y as fp16 (proj GEMM A operand)
    float il0 = 1.0f / l0, il1 = 1.0f / l1;
    size_t r0 = (size_t)(b * T_ + q0 + w * 16 + er);
    __half* y0 = Ys + r0 * K_ + h * HD_;
    __half* y1 = Ys + (r0 + 8) * K_ + h * HD_;
#pragma unroll
    for (int nf = 0; nf < 16; nf++) {
        int co = nf * 8 + ec2;
        *(uint32_t*)(y0 + co) = pack_h2(O[nf][0] * il0, O[nf][1] * il0);
        *(uint32_t*)(y1 + co) = pack_h2(O[nf][2] * il1, O[nf][3] * il1);
    }
}

// ---------------- launch ----------------
extern "C" void kernel_launch(void* const* d_in, const int* in_sizes, int n_in,
                              void* d_out, int out_size)
{
    const float* x      = (const float*)d_in[0];
    const float* w_qkv  = (const float*)d_in[1];
    const float* w_proj = (const float*)d_in[2];
    const float* qw     = (const float*)d_in[3];
    const float* kw     = (const float*)d_in[4];
    const float* fcos   = (const float*)d_in[5];
    const float* fsin   = (const float*)d_in[6];
    float* out = (float*)d_out;

    float* p_qkv;
    __half *p_xs, *p_wqkvs, *p_wprojs, *p_ysh, *p_qs, *p_ks, *p_vt;
    cudaGetSymbolAddress((void**)&p_qkv,    g_qkv);
    cudaGetSymbolAddress((void**)&p_xs,     g_xs);
    cudaGetSymbolAddress((void**)&p_wqkvs,  g_wqkvs);
    cudaGetSymbolAddress((void**)&p_wprojs, g_wprojs);
    cudaGetSymbolAddress((void**)&p_ysh,    g_ysh);
    cudaGetSymbolAddress((void**)&p_qs,     g_qs);
    cudaGetSymbolAddress((void**)&p_ks,     g_ks);
    cudaGetSymbolAddress((void**)&p_vt,     g_vt);

    const int GEMM_SMEM = NSTAGE * GSTAGE;   // 122880
    cudaFuncSetAttribute(gemm_mma, cudaFuncAttributeMaxDynamicSharedMemorySize, GEMM_SMEM);
    cudaFuncSetAttribute(flash_mma, cudaFuncAttributeMaxDynamicSharedMemorySize, FA_SMEM);

    // 0) fp16 conversions of GEMM inputs
    conv_f16<<<(BT_ * 512 + 255) / 256, 256>>>(x, p_xs, BT_);
    conv_f16<<<(QKVD_ * 512 + 255) / 256, 256>>>(w_qkv, p_wqkvs, QKVD_);
    conv_f16<<<(C_ * 512 + 255) / 256, 256>>>(w_proj, p_wprojs, C_);

    // 1) qkv = x @ w_qkv^T
    gemm_mma<<<dim3(QKVD_ / 256, BT_ / 128), 256, GEMM_SMEM>>>(p_xs, p_wqkvs, p_qkv, QKVD_);

    // 2) RoPE + RMSNorm -> fp16 Q (pre-scaled), K, V^T
    qkv_transform<<<dim3(BT_, NH_ + 2 * KVH_), 128>>>(p_qkv, qw, kw, fcos, fsin,
                                                       p_qs, p_ks, p_vt);

    // 3) causal flash attention (fp16 tensor cores) -> y fp16
    flash_mma<<<dim3(T_ / 128, NH_, B_), 256, FA_SMEM>>>(p_qs, p_ks, p_vt, p_ysh);

    // 4) out = y @ w_proj^T
    gemm_mma<<<dim3(C_ / 256, BT_ / 128), 256, GEMM_SMEM>>>(p_ysh, p_wprojs, out, C_);
}

// round 11
// speedup vs baseline: 6.4441x; 1.0792x over previous
#include <cuda_runtime.h>
#include <cuda_bf16.h>
#include <cuda_fp16.h>
#include <cstdint>

#define B_    2
#define T_    2048
#define C_    2048
#define NH_   16
#define KVH_  4
#define HD_   128
#define QKVD_ 3072
#define BT_   (B_*T_)
#define K_    2048

// ---------------- scratch ----------------
__device__ float g_qkv[(size_t)BT_ * QKVD_];
__device__ __half g_xs[(size_t)BT_ * K_];        // x fp16
__device__ __half g_wqkvs[(size_t)QKVD_ * K_];   // w_qkv fp16
__device__ __half g_wprojs[(size_t)C_ * K_];     // w_proj fp16
__device__ __half g_ysh[(size_t)BT_ * K_];       // y fp16 (flash output)
__device__ __half g_qs[(size_t)B_ * NH_ * T_ * HD_];   // q fp16 (pre-scaled)
__device__ __half g_ks[(size_t)B_ * KVH_ * T_ * HD_];  // k fp16
__device__ __half g_vt[(size_t)B_ * KVH_ * HD_ * T_];  // v^T fp16 [d][t]

// ---------------- PTX helpers ----------------
__device__ __forceinline__ uint32_t smem_u32(const void* p) {
    uint32_t a;
    asm("{ .reg .u64 t; cvta.to.shared.u64 t, %1; cvt.u32.u64 %0, t; }" : "=r"(a) : "l"(p));
    return a;
}
__device__ __forceinline__ void cp16(uint32_t saddr, const void* g) {
    asm volatile("cp.async.cg.shared.global [%0], [%1], 16;" :: "r"(saddr), "l"(g) : "memory");
}
__device__ __forceinline__ void cp_commit() { asm volatile("cp.async.commit_group;" ::: "memory"); }
#define CP_WAIT(n) asm volatile("cp.async.wait_group %0;" :: "n"(n) : "memory")

__device__ __forceinline__ void ldm4(uint32_t* r, uint32_t addr) {
    asm volatile("ldmatrix.sync.aligned.m8n8.x4.shared.b16 {%0,%1,%2,%3}, [%4];"
                 : "=r"(r[0]), "=r"(r[1]), "=r"(r[2]), "=r"(r[3]) : "r"(addr));
}
// fp16 mma, fp32 accum
__device__ __forceinline__ void mma16816h(float* c, const uint32_t* a, const uint32_t* b) {
    asm volatile(
        "mma.sync.aligned.m16n8k16.row.col.f32.f16.f16.f32 "
        "{%0,%1,%2,%3}, {%4,%5,%6,%7}, {%8,%9}, {%0,%1,%2,%3};"
        : "+f"(c[0]), "+f"(c[1]), "+f"(c[2]), "+f"(c[3])
        : "r"(a[0]), "r"(a[1]), "r"(a[2]), "r"(a[3]), "r"(b[0]), "r"(b[1]));
}
// pack two fp32 -> f16x2 ('lo' element in low half)
__device__ __forceinline__ uint32_t pack_h2(float lo, float hi) {
    uint32_t r;
    asm("cvt.rn.f16x2.f32 %0, %1, %2;" : "=r"(r) : "f"(hi), "f"(lo));
    return r;
}

// ---------------- fp32 -> fp16 conversion ----------------
__global__ __launch_bounds__(256) void conv_f16(
    const float* __restrict__ in, __half* __restrict__ out, int R)
{
    int i = blockIdx.x * 256 + threadIdx.x;
    int total = R * 512;
    if (i >= total) return;
    int r = i >> 9, c4 = (i & 511) << 2;
    float4 v = *(const float4*)(in + (size_t)r * K_ + c4);
    uint2 o;
    o.x = pack_h2(v.x, v.y);
    o.y = pack_h2(v.z, v.w);
    *(uint2*)(out + (size_t)r * K_ + c4) = o;
}

// ---------------- fp16 NT GEMM, 128x256 CTA / 64x64 warp, BK=64, 3-stage ----------------
// Row pitch 144B (128B data + 16 pad): 16-row ldm4 groups land on distinct 16B bank
// groups (144 mod 128 walks 0,16,...,112).
#define GT_A 0
#define GT_B 18432
#define GSTAGE  55296
#define NSTAGE  3
#define NCHUNK_G (K_ / 64)

__device__ __forceinline__ void g_load_stage(
    uint32_t st, const __half* Ag, const __half* Bg,
    size_t bm, size_t bn, int kc, int tid)
{
    // A: 128 rows x 64 fp16 = 8 chunks of 16B per row
#pragma unroll
    for (int j = 0; j < 4; j++) {
        int idx = tid + j * 256;           // 0..1023
        int r = idx >> 3, c = idx & 7;
        cp16(st + GT_A + (uint32_t)r * 144 + c * 16, Ag + (bm + r) * K_ + kc + c * 8);
    }
    // B: 256 rows x 64 fp16
#pragma unroll
    for (int j = 0; j < 8; j++) {
        int idx = tid + j * 256;           // 0..2047
        int r = idx >> 3, c = idx & 7;
        cp16(st + GT_B + (uint32_t)r * 144 + c * 16, Bg + (bn + r) * K_ + kc + c * 8);
    }
}

__global__ __launch_bounds__(256, 1) void gemm_mma(
    const __half* __restrict__ Ag, const __half* __restrict__ Bg,
    float* __restrict__ Cm, int N)
{
    extern __shared__ char sm[];
    const uint32_t sb = smem_u32(sm);
    const int tid = threadIdx.x;
    const int wid = tid >> 5, lane = tid & 31;
    const size_t bm = (size_t)blockIdx.y * 128;
    const size_t bn = (size_t)blockIdx.x * 256;
    const int wm = (wid & 1) * 64;
    const int wn = (wid >> 1) * 64;

    float acc[4][8][4];
#pragma unroll
    for (int i = 0; i < 4; i++)
#pragma unroll
        for (int j = 0; j < 8; j++)
#pragma unroll
            for (int q = 0; q < 4; q++) acc[i][j][q] = 0.f;

    // prologue: 2 stages in flight
    g_load_stage(sb, Ag, Bg, bm, bn, 0, tid);
    cp_commit();
    g_load_stage(sb + GSTAGE, Ag, Bg, bm, bn, 64, tid);
    cp_commit();

    const int a_row = lane & 15, a_kh = lane >> 4;
    const int b_row = (lane & 7) | ((lane >> 1) & 8);
    const int b_kh = (lane >> 3) & 1;
    const uint32_t a_base = (uint32_t)(wm + a_row) * 144 + a_kh * 16;
    const uint32_t b_base = (uint32_t)(wn + b_row) * 144 + b_kh * 16;

    uint32_t ah[2][4][4], bh[2][4][4];

    int stg = 0;
    for (int ch = 0; ch < NCHUNK_G; ch++) {
        CP_WAIT(1);
        __syncthreads();

        // prefetch chunk ch+2 into the stage freed at ch-1
        if (ch + 2 < NCHUNK_G) {
            int ps = stg + 2 >= NSTAGE ? stg + 2 - NSTAGE : stg + 2;
            g_load_stage(sb + ps * GSTAGE, Ag, Bg, bm, bn, (ch + 2) * 64, tid);
        }
        cp_commit();

        const uint32_t st = sb + stg * GSTAGE;

        // load ks=0 fragments into buffer 0
#pragma unroll
        for (int mt = 0; mt < 4; mt++)
            ldm4(ah[0][mt], st + GT_A + a_base + mt * (16 * 144));
#pragma unroll
        for (int ng = 0; ng < 4; ng++)
            ldm4(bh[0][ng], st + GT_B + b_base + ng * (16 * 144));

#pragma unroll
        for (int ks = 0; ks < 4; ks++) {
            const int cur = ks & 1, nxt = cur ^ 1;
            if (ks < 3) {
                uint32_t ko = (uint32_t)(ks + 1) * 32;
#pragma unroll
                for (int mt = 0; mt < 4; mt++)
                    ldm4(ah[nxt][mt], st + GT_A + a_base + ko + mt * (16 * 144));
#pragma unroll
                for (int ng = 0; ng < 4; ng++)
                    ldm4(bh[nxt][ng], st + GT_B + b_base + ko + ng * (16 * 144));
            }
#pragma unroll
            for (int ng = 0; ng < 4; ng++)
#pragma unroll
                for (int mt = 0; mt < 4; mt++) {
                    mma16816h(acc[mt][2 * ng],     ah[cur][mt], &bh[cur][ng][0]);
                    mma16816h(acc[mt][2 * ng + 1], ah[cur][mt], &bh[cur][ng][2]);
                }
        }
        stg = stg + 1 >= NSTAGE ? 0 : stg + 1;
    }

    const int er = lane >> 2, ec = (lane & 3) * 2;
#pragma unroll
    for (int mt = 0; mt < 4; mt++)
#pragma unroll
        for (int nf = 0; nf < 8; nf++) {
            size_t row = bm + wm + mt * 16 + er;
            size_t col = bn + wn + nf * 8 + ec;
            *(float2*)(Cm + row * (size_t)N + col) =
                make_float2(acc[mt][nf][0], acc[mt][nf][1]);
            *(float2*)(Cm + (row + 8) * (size_t)N + col) =
                make_float2(acc[mt][nf][2], acc[mt][nf][3]);
        }
}

// ---------------- RoPE + RMSNorm transform -> fp16 outputs ----------------
__global__ __launch_bounds__(128) void qkv_transform(
    const float* __restrict__ qkv, const float* __restrict__ qw,
    const float* __restrict__ kw, const float* __restrict__ fcos,
    const float* __restrict__ fsin,
    __half* __restrict__ Qs, __half* __restrict__ Ks,
    __half* __restrict__ VT)
{
    const int bt = blockIdx.x, hh = blockIdx.y;
    const int b = bt >> 11, t = bt & (T_ - 1);
    const int d = threadIdx.x;
    const size_t rowoff = (size_t)bt * QKVD_;

    if (hh >= NH_ + KVH_) {     // v: transpose
        int hv = hh - (NH_ + KVH_);
        float val = qkv[rowoff + (size_t)(NH_ + KVH_) * HD_ + hv * HD_ + d];
        VT[((size_t)(b * KVH_ + hv) * HD_ + d) * T_ + t] = __float2half(val);
        return;
    }
    const float* w; __half* dst; size_t srcoff; float post;
    if (hh < NH_) {
        w = qw; srcoff = (size_t)hh * HD_;
        dst = Qs + (((size_t)(b * NH_ + hh)) * T_ + t) * HD_;
        post = 0.08838834764831845f;   // 1/sqrt(128)
    } else {
        int hk = hh - NH_;
        w = kw; srcoff = (size_t)NH_ * HD_ + hk * HD_;
        dst = Ks + (((size_t)(b * KVH_ + hk)) * T_ + t) * HD_;
        post = 1.0f;
    }
    float xv = qkv[rowoff + srcoff + d];
    float other = __shfl_xor_sync(0xffffffffu, xv, 1);
    int i = d >> 1;
    float c = fcos[t * (HD_ / 2) + i];
    float s = fsin[t * (HD_ / 2) + i];
    float val = (d & 1) ? (other * s + xv * c) : (xv * c - other * s);

    float ss = val * val;
#pragma unroll
    for (int off = 16; off; off >>= 1) ss += __shfl_xor_sync(0xffffffffu, ss, off);
    __shared__ float wsum[4];
    if ((d & 31) == 0) wsum[d >> 5] = ss;
    __syncthreads();
    ss = wsum[0] + wsum[1] + wsum[2] + wsum[3];
    float rinv = rsqrtf(ss * (1.0f / HD_) + 1e-6f);
    dst[d] = __float2half(w[d] * val * rinv * post);
}

// ---------------- flash attention via mma.sync fp16 (single term, R10) ----------------
#define QPITCH 272        // bytes per 128-fp16 row (256B + 16 pad)
#define VPITCH 144        // bytes per 64-fp16 row (128B + 16 pad)
#define SM_Q 0
#define SM_STAGE0 34816
#define KV_STAGE 35840
#define OFF_K 0
#define OFF_V 17408
#define FA_SMEM (34816 + 2 * 35840)   // 106496

__device__ __forceinline__ void fa_load_kv(
    uint32_t st, const __half* Kg, const __half* Vg, int kt, int tid)
{
#pragma unroll
    for (int j = 0; j < 4; j++) {
        int idx = tid + j * 256;            // 0..1023
        int r = idx >> 4, c = idx & 15;     // K: 64 rows x 16 chunks
        cp16(st + OFF_K + (uint32_t)r * QPITCH + c * 16,
             Kg + ((size_t)(kt * 64 + r)) * HD_ + c * 8);
        int rv = idx >> 3, cv = idx & 7;    // V^T: 128 rows x 8 chunks
        cp16(st + OFF_V + (uint32_t)rv * VPITCH + cv * 16,
             Vg + (size_t)rv * T_ + kt * 64 + cv * 8);
    }
}

__global__ __launch_bounds__(256, 1) void flash_mma(
    const __half* __restrict__ Qs, const __half* __restrict__ Ks,
    const __half* __restrict__ VT, __half* __restrict__ Ys)
{
    extern __shared__ char sm[];
    const uint32_t sb = smem_u32(sm);
    const int tid = threadIdx.x, w = tid >> 5, lane = tid & 31;
    const int qt = blockIdx.x, h = blockIdx.y, b = blockIdx.z;
    const int q0 = qt * 128;
    const int hk = h >> 2;
    const __half* Qg = Qs + ((size_t)(b * NH_ + h) * T_ + q0) * HD_;
    const __half* Kg = Ks + (size_t)(b * KVH_ + hk) * T_ * HD_;
    const __half* Vg = VT + (size_t)(b * KVH_ + hk) * HD_ * T_;

#pragma unroll
    for (int j = 0; j < 8; j++) {
        int idx = tid + j * 256;            // 0..2047
        int r = idx >> 4, c = idx & 15;
        cp16(sb + SM_Q + (uint32_t)r * QPITCH + c * 16, Qg + (size_t)r * HD_ + c * 8);
    }
    fa_load_kv(sb + SM_STAGE0, Kg, Vg, 0, tid);
    cp_commit();

    float O[16][4];
#pragma unroll
    for (int i = 0; i < 16; i++)
#pragma unroll
        for (int j = 0; j < 4; j++) O[i][j] = 0.f;
    float m0 = -1e30f, m1 = -1e30f, l0 = 0.f, l1 = 0.f;

    const int er = lane >> 2, ec2 = (lane & 3) * 2;
    const int a_row = lane & 15, a_kh = lane >> 4;
    const int b_row = (lane & 7) | ((lane >> 1) & 8), b_kh = (lane >> 3) & 1;
    const int row0 = q0 + w * 16 + er;
    const int nkt = 2 * qt + 2;

    uint32_t qf[8][4];      // hoisted Q fragments

    for (int kt = 0; kt < nkt; kt++) {
        if (kt + 1 < nkt) {
            fa_load_kv(sb + SM_STAGE0 + ((kt + 1) & 1) * KV_STAGE, Kg, Vg, kt + 1, tid);
            cp_commit();
            CP_WAIT(1);
        } else {
            CP_WAIT(0);
        }
        __syncthreads();

        if (kt == 0) {
#pragma unroll
            for (int ks = 0; ks < 8; ks++) {
                uint32_t qoff = (uint32_t)(w * 16 + a_row) * QPITCH + ks * 32 + a_kh * 16;
                ldm4(qf[ks], sb + SM_Q + qoff);
            }
        }

        const bool full_mask = (kt * 64) > (q0 + w * 16 + 15);   // warp-uniform
        if (!full_mask) {
            const uint32_t st = sb + SM_STAGE0 + (kt & 1) * KV_STAGE;

            float s[8][4];
#pragma unroll
            for (int i = 0; i < 8; i++)
#pragma unroll
                for (int j = 0; j < 4; j++) s[i][j] = 0.f;
#pragma unroll
            for (int ks = 0; ks < 8; ks++) {
#pragma unroll
                for (int ng = 0; ng < 4; ng++) {
                    uint32_t bh[4];
                    uint32_t koff = (uint32_t)(ng * 16 + b_row) * QPITCH + ks * 32 + b_kh * 16;
                    ldm4(bh, st + OFF_K + koff);
                    mma16816h(s[2 * ng],     qf[ks], &bh[0]);
                    mma16816h(s[2 * ng + 1], qf[ks], &bh[2]);
                }
            }

            if ((kt * 64 + 63) > (q0 + w * 16)) {
#pragma unroll
                for (int nf = 0; nf < 8; nf++) {
                    int c0 = kt * 64 + nf * 8 + ec2;
                    if (c0     > row0)     s[nf][0] = -1e30f;
                    if (c0 + 1 > row0)     s[nf][1] = -1e30f;
                    if (c0     > row0 + 8) s[nf][2] = -1e30f;
                    if (c0 + 1 > row0 + 8) s[nf][3] = -1e30f;
                }
            }

            float mx0 = -1e30f, mx1 = -1e30f;
#pragma unroll
            for (int nf = 0; nf < 8; nf++) {
                mx0 = fmaxf(mx0, fmaxf(s[nf][0], s[nf][1]));
                mx1 = fmaxf(mx1, fmaxf(s[nf][2], s[nf][3]));
            }
            mx0 = fmaxf(mx0, __shfl_xor_sync(0xffffffffu, mx0, 1));
            mx0 = fmaxf(mx0, __shfl_xor_sync(0xffffffffu, mx0, 2));
            mx1 = fmaxf(mx1, __shfl_xor_sync(0xffffffffu, mx1, 1));
            mx1 = fmaxf(mx1, __shfl_xor_sync(0xffffffffu, mx1, 2));
            float mn0 = fmaxf(m0, mx0), mn1 = fmaxf(m1, mx1);
            float al0 = __expf(m0 - mn0), al1 = __expf(m1 - mn1);
            m0 = mn0; m1 = mn1;

            float ls0 = 0.f, ls1 = 0.f;
            uint32_t pa[4][4];
#pragma unroll
            for (int nf = 0; nf < 8; nf++) {
                float p0 = __expf(s[nf][0] - mn0);
                float p1 = __expf(s[nf][1] - mn0);
                float p2 = __expf(s[nf][2] - mn1);
                float p3 = __expf(s[nf][3] - mn1);
                ls0 += p0 + p1; ls1 += p2 + p3;
                int q = nf >> 1, base = (nf & 1) * 2;
                pa[q][base]     = pack_h2(p0, p1);
                pa[q][base + 1] = pack_h2(p2, p3);
            }
            ls0 += __shfl_xor_sync(0xffffffffu, ls0, 1);
            ls0 += __shfl_xor_sync(0xffffffffu, ls0, 2);
            ls1 += __shfl_xor_sync(0xffffffffu, ls1, 1);
            ls1 += __shfl_xor_sync(0xffffffffu, ls1, 2);
            l0 = l0 * al0 + ls0;
            l1 = l1 * al1 + ls1;
#pragma unroll
            for (int df = 0; df < 16; df++) {
                O[df][0] *= al0; O[df][1] *= al0;
                O[df][2] *= al1; O[df][3] *= al1;
            }

#pragma unroll
            for (int q = 0; q < 4; q++) {
#pragma unroll
                for (int ng = 0; ng < 8; ng++) {
                    uint32_t vh[4];
                    uint32_t voff = (uint32_t)(ng * 16 + b_row) * VPITCH + q * 32 + b_kh * 16;
                    ldm4(vh, st + OFF_V + voff);
                    mma16816h(O[2 * ng],     pa[q], &vh[0]);
                    mma16816h(O[2 * ng + 1], pa[q], &vh[2]);
                }
            }
        }
        __syncthreads();
    }

    float il0 = 1.0f / l0, il1 = 1.0f / l1;
    size_t r0 = (size_t)(b * T_ + q0 + w * 16 + er);
    __half* y0 = Ys + r0 * K_ + h * HD_;
    __half* y1 = Ys + (r0 + 8) * K_ + h * HD_;
#pragma unroll
    for (int nf = 0; nf < 16; nf++) {
        int co = nf * 8 + ec2;
        *(uint32_t*)(y0 + co) = pack_h2(O[nf][0] * il0, O[nf][1] * il0);
        *(uint32_t*)(y1 + co) = pack_h2(O[nf][2] * il1, O[nf][3] * il1);
    }
}

// ---------------- launch ----------------
extern "C" void kernel_launch(void* const* d_in, const int* in_sizes, int n_in,
                              void* d_out, int out_size)
{
    const float* x      = (const float*)d_in[0];
    const float* w_qkv  = (const float*)d_in[1];
    const float* w_proj = (const float*)d_in[2];
    const float* qw     = (const float*)d_in[3];
    const float* kw     = (const float*)d_in[4];
    const float* fcos   = (const float*)d_in[5];
    const float* fsin   = (const float*)d_in[6];
    float* out = (float*)d_out;

    float* p_qkv;
    __half *p_xs, *p_wqkvs, *p_wprojs, *p_ysh, *p_qs, *p_ks, *p_vt;
    cudaGetSymbolAddress((void**)&p_qkv,    g_qkv);
    cudaGetSymbolAddress((void**)&p_xs,     g_xs);
    cudaGetSymbolAddress((void**)&p_wqkvs,  g_wqkvs);
    cudaGetSymbolAddress((void**)&p_wprojs, g_wprojs);
    cudaGetSymbolAddress((void**)&p_ysh,    g_ysh);
    cudaGetSymbolAddress((void**)&p_qs,     g_qs);
    cudaGetSymbolAddress((void**)&p_ks,     g_ks);
    cudaGetSymbolAddress((void**)&p_vt,     g_vt);

    const int GEMM_SMEM = NSTAGE * GSTAGE;   // 165888
    cudaFuncSetAttribute(gemm_mma, cudaFuncAttributeMaxDynamicSharedMemorySize, GEMM_SMEM);
    cudaFuncSetAttribute(flash_mma, cudaFuncAttributeMaxDynamicSharedMemorySize, FA_SMEM);

    // 0) fp16 conversions of GEMM inputs
    conv_f16<<<(BT_ * 512 + 255) / 256, 256>>>(x, p_xs, BT_);
    conv_f16<<<(QKVD_ * 512 + 255) / 256, 256>>>(w_qkv, p_wqkvs, QKVD_);
    conv_f16<<<(C_ * 512 + 255) / 256, 256>>>(w_proj, p_wprojs, C_);

    // 1) qkv = x @ w_qkv^T
    gemm_mma<<<dim3(QKVD_ / 256, BT_ / 128), 256, GEMM_SMEM>>>(p_xs, p_wqkvs, p_qkv, QKVD_);

    // 2) RoPE + RMSNorm -> fp16 Q (pre-scaled), K, V^T
    qkv_transform<<<dim3(BT_, NH_ + 2 * KVH_), 128>>>(p_qkv, qw, kw, fcos, fsin,
                                                       p_qs, p_ks, p_vt);

    // 3) causal flash attention (fp16 tensor cores) -> y fp16
    flash_mma<<<dim3(T_ / 128, NH_, B_), 256, FA_SMEM>>>(p_qs, p_ks, p_vt, p_ysh);

    // 4) out = y @ w_proj^T
    gemm_mma<<<dim3(C_ / 256, BT_ / 128), 256, GEMM_SMEM>>>(p_ysh, p_wprojs, out, C_);
}

// round 12
// speedup vs baseline: 7.0515x; 1.0943x over previous
#include <cuda_runtime.h>
#include <cuda_bf16.h>
#include <cuda_fp16.h>
#include <cstdint>

#define B_    2
#define T_    2048
#define C_    2048
#define NH_   16
#define KVH_  4
#define HD_   128
#define QKVD_ 3072
#define BT_   (B_*T_)
#define K_    2048

// ---------------- scratch ----------------
__device__ float g_qkv[(size_t)BT_ * QKVD_];
__device__ __half g_xs[(size_t)BT_ * K_];        // x fp16
__device__ __half g_wqkvs[(size_t)QKVD_ * K_];   // w_qkv fp16
__device__ __half g_wprojs[(size_t)C_ * K_];     // w_proj fp16
__device__ __half g_ysh[(size_t)BT_ * K_];       // y fp16 (flash output)
__device__ __half g_qs[(size_t)B_ * NH_ * T_ * HD_];   // q fp16 (pre-scaled)
__device__ __half g_ks[(size_t)B_ * KVH_ * T_ * HD_];  // k fp16
__device__ __half g_vt[(size_t)B_ * KVH_ * HD_ * T_];  // v^T fp16 [d][t]

// ---------------- PTX helpers ----------------
__device__ __forceinline__ uint32_t smem_u32(const void* p) {
    uint32_t a;
    asm("{ .reg .u64 t; cvta.to.shared.u64 t, %1; cvt.u32.u64 %0, t; }" : "=r"(a) : "l"(p));
    return a;
}
__device__ __forceinline__ void cp16(uint32_t saddr, const void* g) {
    asm volatile("cp.async.cg.shared.global [%0], [%1], 16;" :: "r"(saddr), "l"(g) : "memory");
}
__device__ __forceinline__ void cp_commit() { asm volatile("cp.async.commit_group;" ::: "memory"); }
#define CP_WAIT(n) asm volatile("cp.async.wait_group %0;" :: "n"(n) : "memory")

__device__ __forceinline__ void ldm4(uint32_t* r, uint32_t addr) {
    asm volatile("ldmatrix.sync.aligned.m8n8.x4.shared.b16 {%0,%1,%2,%3}, [%4];"
                 : "=r"(r[0]), "=r"(r[1]), "=r"(r[2]), "=r"(r[3]) : "r"(addr));
}
// fp16 mma, fp32 accum
__device__ __forceinline__ void mma16816h(float* c, const uint32_t* a, const uint32_t* b) {
    asm volatile(
        "mma.sync.aligned.m16n8k16.row.col.f32.f16.f16.f32 "
        "{%0,%1,%2,%3}, {%4,%5,%6,%7}, {%8,%9}, {%0,%1,%2,%3};"
        : "+f"(c[0]), "+f"(c[1]), "+f"(c[2]), "+f"(c[3])
        : "r"(a[0]), "r"(a[1]), "r"(a[2]), "r"(a[3]), "r"(b[0]), "r"(b[1]));
}
// pack two fp32 -> f16x2 ('lo' element in low half)
__device__ __forceinline__ uint32_t pack_h2(float lo, float hi) {
    uint32_t r;
    asm("cvt.rn.f16x2.f32 %0, %1, %2;" : "=r"(r) : "f"(hi), "f"(lo));
    return r;
}

// ---------------- fp32 -> fp16 conversion ----------------
__global__ __launch_bounds__(256) void conv_f16(
    const float* __restrict__ in, __half* __restrict__ out, int R)
{
    int i = blockIdx.x * 256 + threadIdx.x;
    int total = R * 512;
    if (i >= total) return;
    int r = i >> 9, c4 = (i & 511) << 2;
    float4 v = *(const float4*)(in + (size_t)r * K_ + c4);
    uint2 o;
    o.x = pack_h2(v.x, v.y);
    o.y = pack_h2(v.z, v.w);
    *(uint2*)(out + (size_t)r * K_ + c4) = o;
}

// ---------------- fp16 NT GEMM, 128x256 CTA / 64x64 warp, BK=64, 4-stage ----------------
#define GT_A 0
#define GT_B 18432
#define GSTAGE  55296
#define NSTAGE  4
#define NCHUNK_G (K_ / 64)

__device__ __forceinline__ void g_load_stage(
    uint32_t st, const __half* Ag, const __half* Bg,
    size_t bm, size_t bn, int kc, int tid)
{
#pragma unroll
    for (int j = 0; j < 4; j++) {
        int idx = tid + j * 256;           // 0..1023
        int r = idx >> 3, c = idx & 7;
        cp16(st + GT_A + (uint32_t)r * 144 + c * 16, Ag + (bm + r) * K_ + kc + c * 8);
    }
#pragma unroll
    for (int j = 0; j < 8; j++) {
        int idx = tid + j * 256;           // 0..2047
        int r = idx >> 3, c = idx & 7;
        cp16(st + GT_B + (uint32_t)r * 144 + c * 16, Bg + (bn + r) * K_ + kc + c * 8);
    }
}

__global__ __launch_bounds__(256, 1) void gemm_mma(
    const __half* __restrict__ Ag, const __half* __restrict__ Bg,
    float* __restrict__ Cm, int N)
{
    extern __shared__ char sm[];
    const uint32_t sb = smem_u32(sm);
    const int tid = threadIdx.x;
    const int wid = tid >> 5, lane = tid & 31;
    const size_t bm = (size_t)blockIdx.y * 128;
    const size_t bn = (size_t)blockIdx.x * 256;
    const int wm = (wid & 1) * 64;
    const int wn = (wid >> 1) * 64;

    float acc[4][8][4];
#pragma unroll
    for (int i = 0; i < 4; i++)
#pragma unroll
        for (int j = 0; j < 8; j++)
#pragma unroll
            for (int q = 0; q < 4; q++) acc[i][j][q] = 0.f;

    // prologue: 3 stages in flight
#pragma unroll
    for (int s = 0; s < 3; s++) {
        g_load_stage(sb + s * GSTAGE, Ag, Bg, bm, bn, s * 64, tid);
        cp_commit();
    }

    const int a_row = lane & 15, a_kh = lane >> 4;
    const int b_row = (lane & 7) | ((lane >> 1) & 8);
    const int b_kh = (lane >> 3) & 1;
    const uint32_t a_base = (uint32_t)(wm + a_row) * 144 + a_kh * 16;
    const uint32_t b_base = (uint32_t)(wn + b_row) * 144 + b_kh * 16;

    uint32_t ah[2][4][4], bh[2][4][4];

    int stg = 0;
    for (int ch = 0; ch < NCHUNK_G; ch++) {
        CP_WAIT(2);
        __syncthreads();

        if (ch + 3 < NCHUNK_G) {
            int ps = stg + 3 >= NSTAGE ? stg + 3 - NSTAGE : stg + 3;
            g_load_stage(sb + ps * GSTAGE, Ag, Bg, bm, bn, (ch + 3) * 64, tid);
        }
        cp_commit();

        const uint32_t st = sb + stg * GSTAGE;

#pragma unroll
        for (int mt = 0; mt < 4; mt++)
            ldm4(ah[0][mt], st + GT_A + a_base + mt * (16 * 144));
#pragma unroll
        for (int ng = 0; ng < 4; ng++)
            ldm4(bh[0][ng], st + GT_B + b_base + ng * (16 * 144));

#pragma unroll
        for (int ks = 0; ks < 4; ks++) {
            const int cur = ks & 1, nxt = cur ^ 1;
            if (ks < 3) {
                uint32_t ko = (uint32_t)(ks + 1) * 32;
#pragma unroll
                for (int mt = 0; mt < 4; mt++)
                    ldm4(ah[nxt][mt], st + GT_A + a_base + ko + mt * (16 * 144));
#pragma unroll
                for (int ng = 0; ng < 4; ng++)
                    ldm4(bh[nxt][ng], st + GT_B + b_base + ko + ng * (16 * 144));
            }
#pragma unroll
            for (int ng = 0; ng < 4; ng++)
#pragma unroll
                for (int mt = 0; mt < 4; mt++) {
                    mma16816h(acc[mt][2 * ng],     ah[cur][mt], &bh[cur][ng][0]);
                    mma16816h(acc[mt][2 * ng + 1], ah[cur][mt], &bh[cur][ng][2]);
                }
        }
        stg = stg + 1 >= NSTAGE ? 0 : stg + 1;
    }

    const int er = lane >> 2, ec = (lane & 3) * 2;
#pragma unroll
    for (int mt = 0; mt < 4; mt++)
#pragma unroll
        for (int nf = 0; nf < 8; nf++) {
            size_t row = bm + wm + mt * 16 + er;
            size_t col = bn + wn + nf * 8 + ec;
            *(float2*)(Cm + row * (size_t)N + col) =
                make_float2(acc[mt][nf][0], acc[mt][nf][1]);
            *(float2*)(Cm + (row + 8) * (size_t)N + col) =
                make_float2(acc[mt][nf][2], acc[mt][nf][3]);
        }
}

// ---------------- RoPE + RMSNorm for Q/K: one warp per head-row ----------------
// grid (BT, 5), block 128 (4 warps). hh = blockIdx.y*4 + wid: 0..15 q, 16..19 k.
__global__ __launch_bounds__(128) void qk_transform(
    const float* __restrict__ qkv, const float* __restrict__ qw,
    const float* __restrict__ kw, const float* __restrict__ fcos,
    const float* __restrict__ fsin,
    __half* __restrict__ Qs, __half* __restrict__ Ks)
{
    const int bt = blockIdx.x;
    const int b = bt >> 11, t = bt & (T_ - 1);
    const int wid = threadIdx.x >> 5, lane = threadIdx.x & 31;
    const int hh = blockIdx.y * 4 + wid;
    const int d4 = lane * 4;

    const float* w; __half* dst; float post;
    if (hh < NH_) {
        w = qw;
        dst = Qs + (((size_t)(b * NH_ + hh)) * T_ + t) * HD_;
        post = 0.08838834764831845f;   // 1/sqrt(128)
    } else {
        int hk = hh - NH_;
        w = kw;
        dst = Ks + (((size_t)(b * KVH_ + hk)) * T_ + t) * HD_;
        post = 1.0f;
    }

    float4 v = *(const float4*)(qkv + (size_t)bt * QKVD_ + hh * HD_ + d4);
    float2 cs0 = *(const float2*)(fcos + t * (HD_ / 2) + lane * 2);
    float2 sn0 = *(const float2*)(fsin + t * (HD_ / 2) + lane * 2);

    float o0 = v.x * cs0.x - v.y * sn0.x;
    float o1 = v.x * sn0.x + v.y * cs0.x;
    float o2 = v.z * cs0.y - v.w * sn0.y;
    float o3 = v.z * sn0.y + v.w * cs0.y;

    float ss = o0 * o0 + o1 * o1 + o2 * o2 + o3 * o3;
#pragma unroll
    for (int off = 16; off; off >>= 1) ss += __shfl_xor_sync(0xffffffffu, ss, off);
    float rinv = rsqrtf(ss * (1.0f / HD_) + 1e-6f) * post;

    float4 wv = *(const float4*)(w + d4);
    uint2 o;
    o.x = pack_h2(o0 * wv.x * rinv, o1 * wv.y * rinv);
    o.y = pack_h2(o2 * wv.z * rinv, o3 * wv.w * rinv);
    *(uint2*)(dst + d4) = o;
}

// ---------------- V transpose: [t][d] fp32 -> [d][t] fp16, smem-tiled ----------------
// grid (T/64, HD/32, B*KVH), block 256. Tile 64 t x 32 d.
__global__ __launch_bounds__(256) void v_transpose(
    const float* __restrict__ qkv, __half* __restrict__ VT)
{
    __shared__ float tile[32][65];
    const int t0 = blockIdx.x * 64;
    const int d0 = blockIdx.y * 32;
    const int bh = blockIdx.z;              // b*KVH + hv
    const int b = bh >> 2, hv = bh & 3;
    const int tid = threadIdx.x;

    const size_t voff = (size_t)(NH_ + KVH_) * HD_ + hv * HD_;
    // read 64 t-rows x 32 d-cols (coalesced along d)
#pragma unroll
    for (int it = 0; it < 8; it++) {
        int idx = tid + it * 256;           // 0..2047
        int r = idx >> 5, c = idx & 31;     // r: t-local, c: d-local
        tile[c][r] = qkv[((size_t)(b * T_ + t0 + r)) * QKVD_ + voff + d0 + c];
    }
    __syncthreads();
    // write 32 d-rows x 64 t-cols (coalesced along t)
#pragma unroll
    for (int it = 0; it < 4; it++) {
        int idx = tid + it * 256;           // 0..1023... need 2048? 32*64=2048/2-per-thread
        int dr = idx >> 6, tc2 = (idx & 63);
        // two halves: handle 2048 elems with 4 iters of 256 threads x 2 elems
        int dr0 = (idx * 2) >> 7;           // 0..31
        int tc = (idx * 2) & 127;           // even positions 0..126 step 2
        (void)dr; (void)tc2;
        __half h0 = __float2half(tile[dr0][tc >> 1]);
        // simpler: recompute directly below
    }
    // simple correct write loop: 2048 elems, 8 iters
#pragma unroll
    for (int it = 0; it < 8; it++) {
        int idx = tid + it * 256;           // 0..2047
        int dr = idx >> 6, tc = idx & 63;
        VT[((size_t)(bh) * HD_ + d0 + dr) * T_ + t0 + tc] = __float2half(tile[dr][tc]);
    }
}

// ---------------- flash attention via mma.sync fp16 (single term) ----------------
#define QPITCH 272        // bytes per 128-fp16 row (256B + 16 pad)
#define VPITCH 144        // bytes per 64-fp16 row (128B + 16 pad)
#define SM_Q 0
#define SM_STAGE0 34816
#define KV_STAGE 35840
#define OFF_K 0
#define OFF_V 17408
#define FA_SMEM (34816 + 2 * 35840)   // 106496

__device__ __forceinline__ void fa_load_kv(
    uint32_t st, const __half* Kg, const __half* Vg, int kt, int tid)
{
#pragma unroll
    for (int j = 0; j < 4; j++) {
        int idx = tid + j * 256;            // 0..1023
        int r = idx >> 4, c = idx & 15;     // K: 64 rows x 16 chunks
        cp16(st + OFF_K + (uint32_t)r * QPITCH + c * 16,
             Kg + ((size_t)(kt * 64 + r)) * HD_ + c * 8);
        int rv = idx >> 3, cv = idx & 7;    // V^T: 128 rows x 8 chunks
        cp16(st + OFF_V + (uint32_t)rv * VPITCH + cv * 16,
             Vg + (size_t)rv * T_ + kt * 64 + cv * 8);
    }
}

__global__ __launch_bounds__(256, 1) void flash_mma(
    const __half* __restrict__ Qs, const __half* __restrict__ Ks,
    const __half* __restrict__ VT, __half* __restrict__ Ys)
{
    extern __shared__ char sm[];
    const uint32_t sb = smem_u32(sm);
    const int tid = threadIdx.x, w = tid >> 5, lane = tid & 31;
    // heavy tiles (large qt) first: reverse the x mapping
    const int qt = gridDim.x - 1 - blockIdx.x;
    const int h = blockIdx.y, b = blockIdx.z;
    const int q0 = qt * 128;
    const int hk = h >> 2;
    const __half* Qg = Qs + ((size_t)(b * NH_ + h) * T_ + q0) * HD_;
    const __half* Kg = Ks + (size_t)(b * KVH_ + hk) * T_ * HD_;
    const __half* Vg = VT + (size_t)(b * KVH_ + hk) * HD_ * T_;

#pragma unroll
    for (int j = 0; j < 8; j++) {
        int idx = tid + j * 256;            // 0..2047
        int r = idx >> 4, c = idx & 15;
        cp16(sb + SM_Q + (uint32_t)r * QPITCH + c * 16, Qg + (size_t)r * HD_ + c * 8);
    }
    fa_load_kv(sb + SM_STAGE0, Kg, Vg, 0, tid);
    cp_commit();

    float O[16][4];
#pragma unroll
    for (int i = 0; i < 16; i++)
#pragma unroll
        for (int j = 0; j < 4; j++) O[i][j] = 0.f;
    float m0 = -1e30f, m1 = -1e30f, l0 = 0.f, l1 = 0.f;

    const int er = lane >> 2, ec2 = (lane & 3) * 2;
    const int a_row = lane & 15, a_kh = lane >> 4;
    const int b_row = (lane & 7) | ((lane >> 1) & 8), b_kh = (lane >> 3) & 1;
    const int row0 = q0 + w * 16 + er;
    const int nkt = 2 * qt + 2;

    uint32_t qf[8][4];      // hoisted Q fragments

    for (int kt = 0; kt < nkt; kt++) {
        if (kt + 1 < nkt) {
            fa_load_kv(sb + SM_STAGE0 + ((kt + 1) & 1) * KV_STAGE, Kg, Vg, kt + 1, tid);
            cp_commit();
            CP_WAIT(1);
        } else {
            CP_WAIT(0);
        }
        __syncthreads();

        if (kt == 0) {
#pragma unroll
            for (int ks = 0; ks < 8; ks++) {
                uint32_t qoff = (uint32_t)(w * 16 + a_row) * QPITCH + ks * 32 + a_kh * 16;
                ldm4(qf[ks], sb + SM_Q + qoff);
            }
        }

        const bool full_mask = (kt * 64) > (q0 + w * 16 + 15);   // warp-uniform
        if (!full_mask) {
            const uint32_t st = sb + SM_STAGE0 + (kt & 1) * KV_STAGE;

            float s[8][4];
#pragma unroll
            for (int i = 0; i < 8; i++)
#pragma unroll
                for (int j = 0; j < 4; j++) s[i][j] = 0.f;
#pragma unroll
            for (int ks = 0; ks < 8; ks++) {
#pragma unroll
                for (int ng = 0; ng < 4; ng++) {
                    uint32_t bh[4];
                    uint32_t koff = (uint32_t)(ng * 16 + b_row) * QPITCH + ks * 32 + b_kh * 16;
                    ldm4(bh, st + OFF_K + koff);
                    mma16816h(s[2 * ng],     qf[ks], &bh[0]);
                    mma16816h(s[2 * ng + 1], qf[ks], &bh[2]);
                }
            }

            if ((kt * 64 + 63) > (q0 + w * 16)) {
#pragma unroll
                for (int nf = 0; nf < 8; nf++) {
                    int c0 = kt * 64 + nf * 8 + ec2;
                    if (c0     > row0)     s[nf][0] = -1e30f;
                    if (c0 + 1 > row0)     s[nf][1] = -1e30f;
                    if (c0     > row0 + 8) s[nf][2] = -1e30f;
                    if (c0 + 1 > row0 + 8) s[nf][3] = -1e30f;
                }
            }

            float mx0 = -1e30f, mx1 = -1e30f;
#pragma unroll
            for (int nf = 0; nf < 8; nf++) {
                mx0 = fmaxf(mx0, fmaxf(s[nf][0], s[nf][1]));
                mx1 = fmaxf(mx1, fmaxf(s[nf][2], s[nf][3]));
            }
            mx0 = fmaxf(mx0, __shfl_xor_sync(0xffffffffu, mx0, 1));
            mx0 = fmaxf(mx0, __shfl_xor_sync(0xffffffffu, mx0, 2));
            mx1 = fmaxf(mx1, __shfl_xor_sync(0xffffffffu, mx1, 1));
            mx1 = fmaxf(mx1, __shfl_xor_sync(0xffffffffu, mx1, 2));
            float mn0 = fmaxf(m0, mx0), mn1 = fmaxf(m1, mx1);
            float al0 = __expf(m0 - mn0), al1 = __expf(m1 - mn1);
            m0 = mn0; m1 = mn1;

            float ls0 = 0.f, ls1 = 0.f;
            uint32_t pa[4][4];
#pragma unroll
            for (int nf = 0; nf < 8; nf++) {
                float p0 = __expf(s[nf][0] - mn0);
                float p1 = __expf(s[nf][1] - mn0);
                float p2 = __expf(s[nf][2] - mn1);
                float p3 = __expf(s[nf][3] - mn1);
                ls0 += p0 + p1; ls1 += p2 + p3;
                int q = nf >> 1, base = (nf & 1) * 2;
                pa[q][base]     = pack_h2(p0, p1);
                pa[q][base + 1] = pack_h2(p2, p3);
            }
            ls0 += __shfl_xor_sync(0xffffffffu, ls0, 1);
            ls0 += __shfl_xor_sync(0xffffffffu, ls0, 2);
            ls1 += __shfl_xor_sync(0xffffffffu, ls1, 1);
            ls1 += __shfl_xor_sync(0xffffffffu, ls1, 2);
            l0 = l0 * al0 + ls0;
            l1 = l1 * al1 + ls1;
#pragma unroll
            for (int df = 0; df < 16; df++) {
                O[df][0] *= al0; O[df][1] *= al0;
                O[df][2] *= al1; O[df][3] *= al1;
            }

#pragma unroll
            for (int q = 0; q < 4; q++) {
#pragma unroll
                for (int ng = 0; ng < 8; ng++) {
                    uint32_t vh[4];
                    uint32_t voff = (uint32_t)(ng * 16 + b_row) * VPITCH + q * 32 + b_kh * 16;
                    ldm4(vh, st + OFF_V + voff);
                    mma16816h(O[2 * ng],     pa[q], &vh[0]);
                    mma16816h(O[2 * ng + 1], pa[q], &vh[2]);
                }
            }
        }
        __syncthreads();
    }

    float il0 = 1.0f / l0, il1 = 1.0f / l1;
    size_t r0 = (size_t)(b * T_ + q0 + w * 16 + er);
    __half* y0 = Ys + r0 * K_ + h * HD_;
    __half* y1 = Ys + (r0 + 8) * K_ + h * HD_;
#pragma unroll
    for (int nf = 0; nf < 16; nf++) {
        int co = nf * 8 + ec2;
        *(uint32_t*)(y0 + co) = pack_h2(O[nf][0] * il0, O[nf][1] * il0);
        *(uint32_t*)(y1 + co) = pack_h2(O[nf][2] * il1, O[nf][3] * il1);
    }
}

// ---------------- launch ----------------
extern "C" void kernel_launch(void* const* d_in, const int* in_sizes, int n_in,
                              void* d_out, int out_size)
{
    const float* x      = (const float*)d_in[0];
    const float* w_qkv  = (const float*)d_in[1];
    const float* w_proj = (const float*)d_in[2];
    const float* qw     = (const float*)d_in[3];
    const float* kw     = (const float*)d_in[4];
    const float* fcos   = (const float*)d_in[5];
    const float* fsin   = (const float*)d_in[6];
    float* out = (float*)d_out;

    float* p_qkv;
    __half *p_xs, *p_wqkvs, *p_wprojs, *p_ysh, *p_qs, *p_ks, *p_vt;
    cudaGetSymbolAddress((void**)&p_qkv,    g_qkv);
    cudaGetSymbolAddress((void**)&p_xs,     g_xs);
    cudaGetSymbolAddress((void**)&p_wqkvs,  g_wqkvs);
    cudaGetSymbolAddress((void**)&p_wprojs, g_wprojs);
    cudaGetSymbolAddress((void**)&p_ysh,    g_ysh);
    cudaGetSymbolAddress((void**)&p_qs,     g_qs);
    cudaGetSymbolAddress((void**)&p_ks,     g_ks);
    cudaGetSymbolAddress((void**)&p_vt,     g_vt);

    const int GEMM_SMEM = NSTAGE * GSTAGE;   // 221184
    cudaFuncSetAttribute(gemm_mma, cudaFuncAttributeMaxDynamicSharedMemorySize, GEMM_SMEM);
    cudaFuncSetAttribute(flash_mma, cudaFuncAttributeMaxDynamicSharedMemorySize, FA_SMEM);

    // 0) fp16 conversions of GEMM inputs
    conv_f16<<<(BT_ * 512 + 255) / 256, 256>>>(x, p_xs, BT_);
    conv_f16<<<(QKVD_ * 512 + 255) / 256, 256>>>(w_qkv, p_wqkvs, QKVD_);
    conv_f16<<<(C_ * 512 + 255) / 256, 256>>>(w_proj, p_wprojs, C_);

    // 1) qkv = x @ w_qkv^T
    gemm_mma<<<dim3(QKVD_ / 256, BT_ / 128), 256, GEMM_SMEM>>>(p_xs, p_wqkvs, p_qkv, QKVD_);

    // 2) RoPE + RMSNorm -> fp16 Q (pre-scaled), K; V transpose
    qk_transform<<<dim3(BT_, 5), 128>>>(p_qkv, qw, kw, fcos, fsin, p_qs, p_ks);
    v_transpose<<<dim3(T_ / 64, HD_ / 32, B_ * KVH_), 256>>>(p_qkv, p_vt);

    // 3) causal flash attention (fp16 tensor cores) -> y fp16
    flash_mma<<<dim3(T_ / 128, NH_, B_), 256, FA_SMEM>>>(p_qs, p_ks, p_vt, p_ysh);

    // 4) out = y @ w_proj^T
    gemm_mma<<<dim3(C_ / 256, BT_ / 128), 256, GEMM_SMEM>>>(p_ysh, p_wprojs, out, C_);
}

// round 13
// speedup vs baseline: 7.2432x; 1.0272x over previous
#include <cuda_runtime.h>
#include <cuda_bf16.h>
#include <cuda_fp16.h>
#include <cstdint>

#define B_    2
#define T_    2048
#define C_    2048
#define NH_   16
#define KVH_  4
#define HD_   128
#define QKVD_ 3072
#define BT_   (B_*T_)
#define K_    2048

// ---------------- scratch ----------------
__device__ float g_qkv[(size_t)BT_ * QKVD_];
__device__ __half g_xs[(size_t)BT_ * K_];        // x fp16
__device__ __half g_wqkvs[(size_t)QKVD_ * K_];   // w_qkv fp16
__device__ __half g_wprojs[(size_t)C_ * K_];     // w_proj fp16
__device__ __half g_ysh[(size_t)BT_ * K_];       // y fp16 (flash output)
__device__ __half g_qs[(size_t)B_ * NH_ * T_ * HD_];   // q fp16 (pre-scaled)
__device__ __half g_ks[(size_t)B_ * KVH_ * T_ * HD_];  // k fp16
__device__ __half g_vt[(size_t)B_ * KVH_ * HD_ * T_];  // v^T fp16 [d][t]

// ---------------- PTX helpers ----------------
__device__ __forceinline__ uint32_t smem_u32(const void* p) {
    uint32_t a;
    asm("{ .reg .u64 t; cvta.to.shared.u64 t, %1; cvt.u32.u64 %0, t; }" : "=r"(a) : "l"(p));
    return a;
}
__device__ __forceinline__ void cp16(uint32_t saddr, const void* g) {
    asm volatile("cp.async.cg.shared.global [%0], [%1], 16;" :: "r"(saddr), "l"(g) : "memory");
}
__device__ __forceinline__ void cp_commit() { asm volatile("cp.async.commit_group;" ::: "memory"); }
#define CP_WAIT(n) asm volatile("cp.async.wait_group %0;" :: "n"(n) : "memory")

__device__ __forceinline__ void ldm4(uint32_t* r, uint32_t addr) {
    asm volatile("ldmatrix.sync.aligned.m8n8.x4.shared.b16 {%0,%1,%2,%3}, [%4];"
                 : "=r"(r[0]), "=r"(r[1]), "=r"(r[2]), "=r"(r[3]) : "r"(addr));
}
// fp16 mma, fp32 accum
__device__ __forceinline__ void mma16816h(float* c, const uint32_t* a, const uint32_t* b) {
    asm volatile(
        "mma.sync.aligned.m16n8k16.row.col.f32.f16.f16.f32 "
        "{%0,%1,%2,%3}, {%4,%5,%6,%7}, {%8,%9}, {%0,%1,%2,%3};"
        : "+f"(c[0]), "+f"(c[1]), "+f"(c[2]), "+f"(c[3])
        : "r"(a[0]), "r"(a[1]), "r"(a[2]), "r"(a[3]), "r"(b[0]), "r"(b[1]));
}
// pack two fp32 -> f16x2 ('lo' element in low half)
__device__ __forceinline__ uint32_t pack_h2(float lo, float hi) {
    uint32_t r;
    asm("cvt.rn.f16x2.f32 %0, %1, %2;" : "=r"(r) : "f"(hi), "f"(lo));
    return r;
}

// ---------------- merged fp32 -> fp16 conversion (x, w_qkv, w_proj) ----------------
#define CN1 (BT_ * 512)              // x       float4 count
#define CN2 (QKVD_ * 512)            // w_qkv
#define CN3 (C_ * 512)               // w_proj
#define CTOT (CN1 + CN2 + CN3)

__global__ __launch_bounds__(256) void conv_all(
    const float* __restrict__ x, const float* __restrict__ wq,
    const float* __restrict__ wp, __half* __restrict__ ox,
    __half* __restrict__ owq, __half* __restrict__ owp)
{
    int i = blockIdx.x * 256 + threadIdx.x;
    if (i >= CTOT) return;
    const float4* src; uint2* dst; int loc;
    if (i < CN1)            { src = (const float4*)x;  dst = (uint2*)ox;  loc = i; }
    else if (i < CN1 + CN2) { src = (const float4*)wq; dst = (uint2*)owq; loc = i - CN1; }
    else                    { src = (const float4*)wp; dst = (uint2*)owp; loc = i - CN1 - CN2; }
    float4 v = src[loc];
    uint2 o;
    o.x = pack_h2(v.x, v.y);
    o.y = pack_h2(v.z, v.w);
    dst[loc] = o;
}

// ---------------- fp16 NT GEMM, 128x256 CTA / 64x64 warp, BK=64, 4-stage ----------------
#define GT_A 0
#define GT_B 18432
#define GSTAGE  55296
#define NSTAGE  4
#define NCHUNK_G (K_ / 64)

__device__ __forceinline__ void g_load_stage(
    uint32_t st, const __half* Ag, const __half* Bg,
    size_t bm, size_t bn, int kc, int tid)
{
#pragma unroll
    for (int j = 0; j < 4; j++) {
        int idx = tid + j * 256;           // 0..1023
        int r = idx >> 3, c = idx & 7;
        cp16(st + GT_A + (uint32_t)r * 144 + c * 16, Ag + (bm + r) * K_ + kc + c * 8);
    }
#pragma unroll
    for (int j = 0; j < 8; j++) {
        int idx = tid + j * 256;           // 0..2047
        int r = idx >> 3, c = idx & 7;
        cp16(st + GT_B + (uint32_t)r * 144 + c * 16, Bg + (bn + r) * K_ + kc + c * 8);
    }
}

__global__ __launch_bounds__(256, 1) void gemm_mma(
    const __half* __restrict__ Ag, const __half* __restrict__ Bg,
    float* __restrict__ Cm, int N)
{
    extern __shared__ char sm[];
    const uint32_t sb = smem_u32(sm);
    const int tid = threadIdx.x;
    const int wid = tid >> 5, lane = tid & 31;
    const size_t bm = (size_t)blockIdx.y * 128;
    const size_t bn = (size_t)blockIdx.x * 256;
    const int wm = (wid & 1) * 64;
    const int wn = (wid >> 1) * 64;

    float acc[4][8][4];
#pragma unroll
    for (int i = 0; i < 4; i++)
#pragma unroll
        for (int j = 0; j < 8; j++)
#pragma unroll
            for (int q = 0; q < 4; q++) acc[i][j][q] = 0.f;

#pragma unroll
    for (int s = 0; s < 3; s++) {
        g_load_stage(sb + s * GSTAGE, Ag, Bg, bm, bn, s * 64, tid);
        cp_commit();
    }

    const int a_row = lane & 15, a_kh = lane >> 4;
    const int b_row = (lane & 7) | ((lane >> 1) & 8);
    const int b_kh = (lane >> 3) & 1;
    const uint32_t a_base = (uint32_t)(wm + a_row) * 144 + a_kh * 16;
    const uint32_t b_base = (uint32_t)(wn + b_row) * 144 + b_kh * 16;

    uint32_t ah[2][4][4], bh[2][4][4];

    int stg = 0;
    for (int ch = 0; ch < NCHUNK_G; ch++) {
        CP_WAIT(2);
        __syncthreads();

        if (ch + 3 < NCHUNK_G) {
            int ps = stg + 3 >= NSTAGE ? stg + 3 - NSTAGE : stg + 3;
            g_load_stage(sb + ps * GSTAGE, Ag, Bg, bm, bn, (ch + 3) * 64, tid);
        }
        cp_commit();

        const uint32_t st = sb + stg * GSTAGE;

#pragma unroll
        for (int mt = 0; mt < 4; mt++)
            ldm4(ah[0][mt], st + GT_A + a_base + mt * (16 * 144));
#pragma unroll
        for (int ng = 0; ng < 4; ng++)
            ldm4(bh[0][ng], st + GT_B + b_base + ng * (16 * 144));

#pragma unroll
        for (int ks = 0; ks < 4; ks++) {
            const int cur = ks & 1, nxt = cur ^ 1;
            if (ks < 3) {
                uint32_t ko = (uint32_t)(ks + 1) * 32;
#pragma unroll
                for (int mt = 0; mt < 4; mt++)
                    ldm4(ah[nxt][mt], st + GT_A + a_base + ko + mt * (16 * 144));
#pragma unroll
                for (int ng = 0; ng < 4; ng++)
                    ldm4(bh[nxt][ng], st + GT_B + b_base + ko + ng * (16 * 144));
            }
#pragma unroll
            for (int ng = 0; ng < 4; ng++)
#pragma unroll
                for (int mt = 0; mt < 4; mt++) {
                    mma16816h(acc[mt][2 * ng],     ah[cur][mt], &bh[cur][ng][0]);
                    mma16816h(acc[mt][2 * ng + 1], ah[cur][mt], &bh[cur][ng][2]);
                }
        }
        stg = stg + 1 >= NSTAGE ? 0 : stg + 1;
    }

    const int er = lane >> 2, ec = (lane & 3) * 2;
#pragma unroll
    for (int mt = 0; mt < 4; mt++)
#pragma unroll
        for (int nf = 0; nf < 8; nf++) {
            size_t row = bm + wm + mt * 16 + er;
            size_t col = bn + wn + nf * 8 + ec;
            *(float2*)(Cm + row * (size_t)N + col) =
                make_float2(acc[mt][nf][0], acc[mt][nf][1]);
            *(float2*)(Cm + (row + 8) * (size_t)N + col) =
                make_float2(acc[mt][nf][2], acc[mt][nf][3]);
        }
}

// ---------------- RoPE + RMSNorm for Q/K: one warp per head-row ----------------
__global__ __launch_bounds__(128) void qk_transform(
    const float* __restrict__ qkv, const float* __restrict__ qw,
    const float* __restrict__ kw, const float* __restrict__ fcos,
    const float* __restrict__ fsin,
    __half* __restrict__ Qs, __half* __restrict__ Ks)
{
    const int bt = blockIdx.x;
    const int b = bt >> 11, t = bt & (T_ - 1);
    const int wid = threadIdx.x >> 5, lane = threadIdx.x & 31;
    const int hh = blockIdx.y * 4 + wid;
    const int d4 = lane * 4;

    const float* w; __half* dst; float post;
    if (hh < NH_) {
        w = qw;
        dst = Qs + (((size_t)(b * NH_ + hh)) * T_ + t) * HD_;
        post = 0.08838834764831845f;   // 1/sqrt(128)
    } else {
        int hk = hh - NH_;
        w = kw;
        dst = Ks + (((size_t)(b * KVH_ + hk)) * T_ + t) * HD_;
        post = 1.0f;
    }

    float4 v = *(const float4*)(qkv + (size_t)bt * QKVD_ + hh * HD_ + d4);
    float2 cs0 = *(const float2*)(fcos + t * (HD_ / 2) + lane * 2);
    float2 sn0 = *(const float2*)(fsin + t * (HD_ / 2) + lane * 2);

    float o0 = v.x * cs0.x - v.y * sn0.x;
    float o1 = v.x * sn0.x + v.y * cs0.x;
    float o2 = v.z * cs0.y - v.w * sn0.y;
    float o3 = v.z * sn0.y + v.w * cs0.y;

    float ss = o0 * o0 + o1 * o1 + o2 * o2 + o3 * o3;
#pragma unroll
    for (int off = 16; off; off >>= 1) ss += __shfl_xor_sync(0xffffffffu, ss, off);
    float rinv = rsqrtf(ss * (1.0f / HD_) + 1e-6f) * post;

    float4 wv = *(const float4*)(w + d4);
    uint2 o;
    o.x = pack_h2(o0 * wv.x * rinv, o1 * wv.y * rinv);
    o.y = pack_h2(o2 * wv.z * rinv, o3 * wv.w * rinv);
    *(uint2*)(dst + d4) = o;
}

// ---------------- V transpose: [t][d] fp32 -> [d][t] fp16, smem-tiled ----------------
__global__ __launch_bounds__(256) void v_transpose(
    const float* __restrict__ qkv, __half* __restrict__ VT)
{
    __shared__ float tile[32][65];
    const int t0 = blockIdx.x * 64;
    const int d0 = blockIdx.y * 32;
    const int bh = blockIdx.z;              // b*KVH + hv
    const int b = bh >> 2, hv = bh & 3;
    const int tid = threadIdx.x;

    const size_t voff = (size_t)(NH_ + KVH_) * HD_ + hv * HD_;
#pragma unroll
    for (int it = 0; it < 8; it++) {
        int idx = tid + it * 256;           // 0..2047
        int r = idx >> 5, c = idx & 31;     // r: t-local, c: d-local
        tile[c][r] = qkv[((size_t)(b * T_ + t0 + r)) * QKVD_ + voff + d0 + c];
    }
    __syncthreads();
#pragma unroll
    for (int it = 0; it < 8; it++) {
        int idx = tid + it * 256;           // 0..2047
        int dr = idx >> 6, tc = idx & 63;
        VT[((size_t)(bh) * HD_ + d0 + dr) * T_ + t0 + tc] = __float2half(tile[dr][tc]);
    }
}

// ---------------- flash attention via mma.sync fp16, K-tile = 128 ----------------
#define QPITCH 272        // bytes per 128-fp16 row (256B + 16 pad)
#define SM_Q 0
#define SM_STAGE0 34816
#define OFF_K 0
#define OFF_V 34816
#define KV_STAGE 69632
#define FA_SMEM (34816 + 2 * 69632)   // 174080

__device__ __forceinline__ void fa_load_kv(
    uint32_t st, const __half* Kg, const __half* Vg, int kt, int tid)
{
#pragma unroll
    for (int j = 0; j < 8; j++) {
        int idx = tid + j * 256;            // 0..2047
        int r = idx >> 4, c = idx & 15;
        // K: 128 rows x 16 chunks of 16B
        cp16(st + OFF_K + (uint32_t)r * QPITCH + c * 16,
             Kg + ((size_t)(kt * 128 + r)) * HD_ + c * 8);
        // V^T: 128 d-rows x 16 chunks of 16B (128 t-cols)
        cp16(st + OFF_V + (uint32_t)r * QPITCH + c * 16,
             Vg + (size_t)r * T_ + kt * 128 + c * 8);
    }
}

__global__ __launch_bounds__(256, 1) void flash_mma(
    const __half* __restrict__ Qs, const __half* __restrict__ Ks,
    const __half* __restrict__ VT, __half* __restrict__ Ys)
{
    extern __shared__ char sm[];
    const uint32_t sb = smem_u32(sm);
    const int tid = threadIdx.x, w = tid >> 5, lane = tid & 31;
    // heavy tiles first
    const int qt = gridDim.x - 1 - blockIdx.x;
    const int h = blockIdx.y, b = blockIdx.z;
    const int q0 = qt * 128;
    const int hk = h >> 2;
    const __half* Qg = Qs + ((size_t)(b * NH_ + h) * T_ + q0) * HD_;
    const __half* Kg = Ks + (size_t)(b * KVH_ + hk) * T_ * HD_;
    const __half* Vg = VT + (size_t)(b * KVH_ + hk) * HD_ * T_;

#pragma unroll
    for (int j = 0; j < 8; j++) {
        int idx = tid + j * 256;            // 0..2047
        int r = idx >> 4, c = idx & 15;
        cp16(sb + SM_Q + (uint32_t)r * QPITCH + c * 16, Qg + (size_t)r * HD_ + c * 8);
    }
    fa_load_kv(sb + SM_STAGE0, Kg, Vg, 0, tid);
    cp_commit();

    float O[16][4];
#pragma unroll
    for (int i = 0; i < 16; i++)
#pragma unroll
        for (int j = 0; j < 4; j++) O[i][j] = 0.f;
    float m0 = -1e30f, m1 = -1e30f, l0 = 0.f, l1 = 0.f;

    const int er = lane >> 2, ec2 = (lane & 3) * 2;
    const int a_row = lane & 15, a_kh = lane >> 4;
    const int b_row = (lane & 7) | ((lane >> 1) & 8), b_kh = (lane >> 3) & 1;
    const int row0 = q0 + w * 16 + er;
    const int nkt = qt + 1;

    uint32_t qf[8][4];      // hoisted Q fragments

    for (int kt = 0; kt < nkt; kt++) {
        if (kt + 1 < nkt) {
            fa_load_kv(sb + SM_STAGE0 + ((kt + 1) & 1) * KV_STAGE, Kg, Vg, kt + 1, tid);
            cp_commit();
            CP_WAIT(1);
        } else {
            CP_WAIT(0);
        }
        __syncthreads();

        if (kt == 0) {
#pragma unroll
            for (int ks = 0; ks < 8; ks++) {
                uint32_t qoff = (uint32_t)(w * 16 + a_row) * QPITCH + ks * 32 + a_kh * 16;
                ldm4(qf[ks], sb + SM_Q + qoff);
            }
        }

        const uint32_t st = sb + SM_STAGE0 + (kt & 1) * KV_STAGE;

        // ---- S = Q K^T over 128 k-cols ----
        float s[16][4];
#pragma unroll
        for (int i = 0; i < 16; i++)
#pragma unroll
            for (int j = 0; j < 4; j++) s[i][j] = 0.f;
#pragma unroll
        for (int ks = 0; ks < 8; ks++) {
#pragma unroll
            for (int ng = 0; ng < 8; ng++) {
                uint32_t bh[4];
                uint32_t koff = (uint32_t)(ng * 16 + b_row) * QPITCH + ks * 32 + b_kh * 16;
                ldm4(bh, st + OFF_K + koff);
                mma16816h(s[2 * ng],     qf[ks], &bh[0]);
                mma16816h(s[2 * ng + 1], qf[ks], &bh[2]);
            }
        }

        // ---- causal mask (only the diagonal tile needs it) ----
        if (kt == qt) {
#pragma unroll
            for (int nf = 0; nf < 16; nf++) {
                int c0 = kt * 128 + nf * 8 + ec2;
                if (c0     > row0)     s[nf][0] = -1e30f;
                if (c0 + 1 > row0)     s[nf][1] = -1e30f;
                if (c0     > row0 + 8) s[nf][2] = -1e30f;
                if (c0 + 1 > row0 + 8) s[nf][3] = -1e30f;
            }
        }

        // ---- streaming softmax (quad-local) ----
        float mx0 = -1e30f, mx1 = -1e30f;
#pragma unroll
        for (int nf = 0; nf < 16; nf++) {
            mx0 = fmaxf(mx0, fmaxf(s[nf][0], s[nf][1]));
            mx1 = fmaxf(mx1, fmaxf(s[nf][2], s[nf][3]));
        }
        mx0 = fmaxf(mx0, __shfl_xor_sync(0xffffffffu, mx0, 1));
        mx0 = fmaxf(mx0, __shfl_xor_sync(0xffffffffu, mx0, 2));
        mx1 = fmaxf(mx1, __shfl_xor_sync(0xffffffffu, mx1, 1));
        mx1 = fmaxf(mx1, __shfl_xor_sync(0xffffffffu, mx1, 2));
        float mn0 = fmaxf(m0, mx0), mn1 = fmaxf(m1, mx1);
        float al0 = __expf(m0 - mn0), al1 = __expf(m1 - mn1);
        m0 = mn0; m1 = mn1;

        float ls0 = 0.f, ls1 = 0.f;
        uint32_t pa[8][4];
#pragma unroll
        for (int nf = 0; nf < 16; nf++) {
            float p0 = __expf(s[nf][0] - mn0);
            float p1 = __expf(s[nf][1] - mn0);
            float p2 = __expf(s[nf][2] - mn1);
            float p3 = __expf(s[nf][3] - mn1);
            ls0 += p0 + p1; ls1 += p2 + p3;
            int q = nf >> 1, base = (nf & 1) * 2;
            pa[q][base]     = pack_h2(p0, p1);
            pa[q][base + 1] = pack_h2(p2, p3);
        }
        ls0 += __shfl_xor_sync(0xffffffffu, ls0, 1);
        ls0 += __shfl_xor_sync(0xffffffffu, ls0, 2);
        ls1 += __shfl_xor_sync(0xffffffffu, ls1, 1);
        ls1 += __shfl_xor_sync(0xffffffffu, ls1, 2);
        l0 = l0 * al0 + ls0;
        l1 = l1 * al1 + ls1;
#pragma unroll
        for (int df = 0; df < 16; df++) {
            O[df][0] *= al0; O[df][1] *= al0;
            O[df][2] *= al1; O[df][3] *= al1;
        }

        // ---- O += P V over 128 k-rows ----
#pragma unroll
        for (int q = 0; q < 8; q++) {
#pragma unroll
            for (int ng = 0; ng < 8; ng++) {
                uint32_t vh[4];
                uint32_t voff = (uint32_t)(ng * 16 + b_row) * QPITCH + q * 32 + b_kh * 16;
                ldm4(vh, st + OFF_V + voff);
                mma16816h(O[2 * ng],     pa[q], &vh[0]);
                mma16816h(O[2 * ng + 1], pa[q], &vh[2]);
            }
        }
        __syncthreads();
    }

    float il0 = 1.0f / l0, il1 = 1.0f / l1;
    size_t r0 = (size_t)(b * T_ + q0 + w * 16 + er);
    __half* y0 = Ys + r0 * K_ + h * HD_;
    __half* y1 = Ys + (r0 + 8) * K_ + h * HD_;
#pragma unroll
    for (int nf = 0; nf < 16; nf++) {
        int co = nf * 8 + ec2;
        *(uint32_t*)(y0 + co) = pack_h2(O[nf][0] * il0, O[nf][1] * il0);
        *(uint32_t*)(y1 + co) = pack_h2(O[nf][2] * il1, O[nf][3] * il1);
    }
}

// ---------------- launch ----------------
extern "C" void kernel_launch(void* const* d_in, const int* in_sizes, int n_in,
                              void* d_out, int out_size)
{
    const float* x      = (const float*)d_in[0];
    const float* w_qkv  = (const float*)d_in[1];
    const float* w_proj = (const float*)d_in[2];
    const float* qw     = (const float*)d_in[3];
    const float* kw     = (const float*)d_in[4];
    const float* fcos   = (const float*)d_in[5];
    const float* fsin   = (const float*)d_in[6];
    float* out = (float*)d_out;

    float* p_qkv;
    __half *p_xs, *p_wqkvs, *p_wprojs, *p_ysh, *p_qs, *p_ks, *p_vt;
    cudaGetSymbolAddress((void**)&p_qkv,    g_qkv);
    cudaGetSymbolAddress((void**)&p_xs,     g_xs);
    cudaGetSymbolAddress((void**)&p_wqkvs,  g_wqkvs);
    cudaGetSymbolAddress((void**)&p_wprojs, g_wprojs);
    cudaGetSymbolAddress((void**)&p_ysh,    g_ysh);
    cudaGetSymbolAddress((void**)&p_qs,     g_qs);
    cudaGetSymbolAddress((void**)&p_ks,     g_ks);
    cudaGetSymbolAddress((void**)&p_vt,     g_vt);

    const int GEMM_SMEM = NSTAGE * GSTAGE;   // 221184
    cudaFuncSetAttribute(gemm_mma, cudaFuncAttributeMaxDynamicSharedMemorySize, GEMM_SMEM);
    cudaFuncSetAttribute(flash_mma, cudaFuncAttributeMaxDynamicSharedMemorySize, FA_SMEM);

    // 0) fp16 conversions (single kernel)
    conv_all<<<(CTOT + 255) / 256, 256>>>(x, w_qkv, w_proj, p_xs, p_wqkvs, p_wprojs);

    // 1) qkv = x @ w_qkv^T
    gemm_mma<<<dim3(QKVD_ / 256, BT_ / 128), 256, GEMM_SMEM>>>(p_xs, p_wqkvs, p_qkv, QKVD_);

    // 2) RoPE + RMSNorm -> fp16 Q (pre-scaled), K; V transpose
    qk_transform<<<dim3(BT_, 5), 128>>>(p_qkv, qw, kw, fcos, fsin, p_qs, p_ks);
    v_transpose<<<dim3(T_ / 64, HD_ / 32, B_ * KVH_), 256>>>(p_qkv, p_vt);

    // 3) causal flash attention (fp16 tensor cores, KT=128) -> y fp16
    flash_mma<<<dim3(T_ / 128, NH_, B_), 256, FA_SMEM>>>(p_qs, p_ks, p_vt, p_ysh);

    // 4) out = y @ w_proj^T
    gemm_mma<<<dim3(C_ / 256, BT_ / 128), 256, GEMM_SMEM>>>(p_ysh, p_wprojs, out, C_);
}

// round 14
// speedup vs baseline: 7.4643x; 1.0305x over previous
#include <cuda_runtime.h>
#include <cuda_bf16.h>
#include <cuda_fp16.h>
#include <cstdint>

#define B_    2
#define T_    2048
#define C_    2048
#define NH_   16
#define KVH_  4
#define HD_   128
#define QKVD_ 3072
#define BT_   (B_*T_)
#define K_    2048

// ---------------- scratch ----------------
__device__ float g_qkv[(size_t)BT_ * QKVD_];
__device__ __half g_xs[(size_t)BT_ * K_];        // x fp16
__device__ __half g_wqkvs[(size_t)QKVD_ * K_];   // w_qkv fp16
__device__ __half g_wprojs[(size_t)C_ * K_];     // w_proj fp16
__device__ __half g_ysh[(size_t)BT_ * K_];       // y fp16 (flash output)
__device__ __half g_qs[(size_t)B_ * NH_ * T_ * HD_];   // q fp16 (pre-scaled)
__device__ __half g_ks[(size_t)B_ * KVH_ * T_ * HD_];  // k fp16
__device__ __half g_vt[(size_t)B_ * KVH_ * HD_ * T_];  // v^T fp16 [d][t]

// ---------------- PTX helpers ----------------
__device__ __forceinline__ uint32_t smem_u32(const void* p) {
    uint32_t a;
    asm("{ .reg .u64 t; cvta.to.shared.u64 t, %1; cvt.u32.u64 %0, t; }" : "=r"(a) : "l"(p));
    return a;
}
__device__ __forceinline__ void cp16(uint32_t saddr, const void* g) {
    asm volatile("cp.async.cg.shared.global [%0], [%1], 16;" :: "r"(saddr), "l"(g) : "memory");
}
__device__ __forceinline__ void cp_commit() { asm volatile("cp.async.commit_group;" ::: "memory"); }
#define CP_WAIT(n) asm volatile("cp.async.wait_group %0;" :: "n"(n) : "memory")

__device__ __forceinline__ void ldm4(uint32_t* r, uint32_t addr) {
    asm volatile("ldmatrix.sync.aligned.m8n8.x4.shared.b16 {%0,%1,%2,%3}, [%4];"
                 : "=r"(r[0]), "=r"(r[1]), "=r"(r[2]), "=r"(r[3]) : "r"(addr));
}
// fp16 mma, fp32 accum
__device__ __forceinline__ void mma16816h(float* c, const uint32_t* a, const uint32_t* b) {
    asm volatile(
        "mma.sync.aligned.m16n8k16.row.col.f32.f16.f16.f32 "
        "{%0,%1,%2,%3}, {%4,%5,%6,%7}, {%8,%9}, {%0,%1,%2,%3};"
        : "+f"(c[0]), "+f"(c[1]), "+f"(c[2]), "+f"(c[3])
        : "r"(a[0]), "r"(a[1]), "r"(a[2]), "r"(a[3]), "r"(b[0]), "r"(b[1]));
}
// pack two fp32 -> f16x2 ('lo' element in low half)
__device__ __forceinline__ uint32_t pack_h2(float lo, float hi) {
    uint32_t r;
    asm("cvt.rn.f16x2.f32 %0, %1, %2;" : "=r"(r) : "f"(hi), "f"(lo));
    return r;
}

// ---------------- merged fp32 -> fp16 conversion (x, w_qkv, w_proj) ----------------
#define CN1 (BT_ * 512)              // x       float4 count
#define CN2 (QKVD_ * 512)            // w_qkv
#define CN3 (C_ * 512)               // w_proj
#define CTOT (CN1 + CN2 + CN3)

__global__ __launch_bounds__(256) void conv_all(
    const float* __restrict__ x, const float* __restrict__ wq,
    const float* __restrict__ wp, __half* __restrict__ ox,
    __half* __restrict__ owq, __half* __restrict__ owp)
{
    int i = blockIdx.x * 256 + threadIdx.x;
    if (i >= CTOT) return;
    const float4* src; uint2* dst; int loc;
    if (i < CN1)            { src = (const float4*)x;  dst = (uint2*)ox;  loc = i; }
    else if (i < CN1 + CN2) { src = (const float4*)wq; dst = (uint2*)owq; loc = i - CN1; }
    else                    { src = (const float4*)wp; dst = (uint2*)owp; loc = i - CN1 - CN2; }
    float4 v = src[loc];
    uint2 o;
    o.x = pack_h2(v.x, v.y);
    o.y = pack_h2(v.z, v.w);
    dst[loc] = o;
}

// ---------------- fp16 NT GEMM, 128x256 CTA / 64x64 warp, K-region = 128 ----------------
// 2 region buffers; ONE barrier + ONE cp.async wait per 128-K region.
// Row pitch 272 B (256 data + 16 pad): conflict-free ldmatrix (272 mod 128 = 16).
#define GPITCH  272
#define GT_A    0
#define GT_B    34816                // 128 * 272
#define GREGION 104448               // 34816 + 256*272
#define NREG    (K_ / 128)           // 16

__device__ __forceinline__ void g_load_region(
    uint32_t st, const __half* Ag, const __half* Bg,
    size_t bm, size_t bn, int kc, int tid)
{
    // A: 128 rows x 128 fp16 = 16 chunks of 16B per row
#pragma unroll
    for (int j = 0; j < 8; j++) {
        int idx = tid + j * 256;           // 0..2047
        int r = idx >> 4, c = idx & 15;
        cp16(st + GT_A + (uint32_t)r * GPITCH + c * 16, Ag + (bm + r) * K_ + kc + c * 8);
    }
    // B: 256 rows x 128 fp16
#pragma unroll
    for (int j = 0; j < 16; j++) {
        int idx = tid + j * 256;           // 0..4095
        int r = idx >> 4, c = idx & 15;
        cp16(st + GT_B + (uint32_t)r * GPITCH + c * 16, Bg + (bn + r) * K_ + kc + c * 8);
    }
}

__global__ __launch_bounds__(256, 1) void gemm_mma(
    const __half* __restrict__ Ag, const __half* __restrict__ Bg,
    float* __restrict__ Cm, int N)
{
    extern __shared__ char sm[];
    const uint32_t sb = smem_u32(sm);
    const int tid = threadIdx.x;
    const int wid = tid >> 5, lane = tid & 31;
    const size_t bm = (size_t)blockIdx.y * 128;
    const size_t bn = (size_t)blockIdx.x * 256;
    const int wm = (wid & 1) * 64;
    const int wn = (wid >> 1) * 64;

    float acc[4][8][4];
#pragma unroll
    for (int i = 0; i < 4; i++)
#pragma unroll
        for (int j = 0; j < 8; j++)
#pragma unroll
            for (int q = 0; q < 4; q++) acc[i][j][q] = 0.f;

    // prologue: region 0
    g_load_region(sb, Ag, Bg, bm, bn, 0, tid);
    cp_commit();

    const int a_row = lane & 15, a_kh = lane >> 4;
    const int b_row = (lane & 7) | ((lane >> 1) & 8);
    const int b_kh = (lane >> 3) & 1;
    const uint32_t a_base = (uint32_t)(wm + a_row) * GPITCH + a_kh * 16;
    const uint32_t b_base = (uint32_t)(wn + b_row) * GPITCH + b_kh * 16;

    uint32_t ah[2][4][4], bh[2][4][4];

    for (int r = 0; r < NREG; r++) {
        CP_WAIT(0);             // region r resident (loads issued at iter r-1)
        __syncthreads();        // visibility + all warps done reading buf[(r-1)&1]

        // issue loads for region r+1 into the other buffer (overlaps compute of r)
        if (r + 1 < NREG)
            g_load_region(sb + ((r + 1) & 1) * GREGION, Ag, Bg, bm, bn,
                          (r + 1) * 128, tid);
        cp_commit();

        const uint32_t st = sb + (r & 1) * GREGION;

        // ks=0 fragments into buffer 0
#pragma unroll
        for (int mt = 0; mt < 4; mt++)
            ldm4(ah[0][mt], st + GT_A + a_base + mt * (16 * GPITCH));
#pragma unroll
        for (int ng = 0; ng < 4; ng++)
            ldm4(bh[0][ng], st + GT_B + b_base + ng * (16 * GPITCH));

#pragma unroll
        for (int ks = 0; ks < 8; ks++) {
            const int cur = ks & 1, nxt = cur ^ 1;
            if (ks < 7) {
                uint32_t ko = (uint32_t)(ks + 1) * 32;
#pragma unroll
                for (int mt = 0; mt < 4; mt++)
                    ldm4(ah[nxt][mt], st + GT_A + a_base + ko + mt * (16 * GPITCH));
#pragma unroll
                for (int ng = 0; ng < 4; ng++)
                    ldm4(bh[nxt][ng], st + GT_B + b_base + ko + ng * (16 * GPITCH));
            }
#pragma unroll
            for (int ng = 0; ng < 4; ng++)
#pragma unroll
                for (int mt = 0; mt < 4; mt++) {
                    mma16816h(acc[mt][2 * ng],     ah[cur][mt], &bh[cur][ng][0]);
                    mma16816h(acc[mt][2 * ng + 1], ah[cur][mt], &bh[cur][ng][2]);
                }
        }
    }

    const int er = lane >> 2, ec = (lane & 3) * 2;
#pragma unroll
    for (int mt = 0; mt < 4; mt++)
#pragma unroll
        for (int nf = 0; nf < 8; nf++) {
            size_t row = bm + wm + mt * 16 + er;
            size_t col = bn + wn + nf * 8 + ec;
            *(float2*)(Cm + row * (size_t)N + col) =
                make_float2(acc[mt][nf][0], acc[mt][nf][1]);
            *(float2*)(Cm + (row + 8) * (size_t)N + col) =
                make_float2(acc[mt][nf][2], acc[mt][nf][3]);
        }
}

// ---------------- RoPE + RMSNorm for Q/K: one warp per head-row ----------------
__global__ __launch_bounds__(128) void qk_transform(
    const float* __restrict__ qkv, const float* __restrict__ qw,
    const float* __restrict__ kw, const float* __restrict__ fcos,
    const float* __restrict__ fsin,
    __half* __restrict__ Qs, __half* __restrict__ Ks)
{
    const int bt = blockIdx.x;
    const int b = bt >> 11, t = bt & (T_ - 1);
    const int wid = threadIdx.x >> 5, lane = threadIdx.x & 31;
    const int hh = blockIdx.y * 4 + wid;
    const int d4 = lane * 4;

    const float* w; __half* dst; float post;
    if (hh < NH_) {
        w = qw;
        dst = Qs + (((size_t)(b * NH_ + hh)) * T_ + t) * HD_;
        post = 0.08838834764831845f;   // 1/sqrt(128)
    } else {
        int hk = hh - NH_;
        w = kw;
        dst = Ks + (((size_t)(b * KVH_ + hk)) * T_ + t) * HD_;
        post = 1.0f;
    }

    float4 v = *(const float4*)(qkv + (size_t)bt * QKVD_ + hh * HD_ + d4);
    float2 cs0 = *(const float2*)(fcos + t * (HD_ / 2) + lane * 2);
    float2 sn0 = *(const float2*)(fsin + t * (HD_ / 2) + lane * 2);

    float o0 = v.x * cs0.x - v.y * sn0.x;
    float o1 = v.x * sn0.x + v.y * cs0.x;
    float o2 = v.z * cs0.y - v.w * sn0.y;
    float o3 = v.z * sn0.y + v.w * cs0.y;

    float ss = o0 * o0 + o1 * o1 + o2 * o2 + o3 * o3;
#pragma unroll
    for (int off = 16; off; off >>= 1) ss += __shfl_xor_sync(0xffffffffu, ss, off);
    float rinv = rsqrtf(ss * (1.0f / HD_) + 1e-6f) * post;

    float4 wv = *(const float4*)(w + d4);
    uint2 o;
    o.x = pack_h2(o0 * wv.x * rinv, o1 * wv.y * rinv);
    o.y = pack_h2(o2 * wv.z * rinv, o3 * wv.w * rinv);
    *(uint2*)(dst + d4) = o;
}

// ---------------- V transpose: [t][d] fp32 -> [d][t] fp16, smem-tiled ----------------
__global__ __launch_bounds__(256) void v_transpose(
    const float* __restrict__ qkv, __half* __restrict__ VT)
{
    __shared__ float tile[32][65];
    const int t0 = blockIdx.x * 64;
    const int d0 = blockIdx.y * 32;
    const int bh = blockIdx.z;              // b*KVH + hv
    const int b = bh >> 2, hv = bh & 3;
    const int tid = threadIdx.x;

    const size_t voff = (size_t)(NH_ + KVH_) * HD_ + hv * HD_;
#pragma unroll
    for (int it = 0; it < 8; it++) {
        int idx = tid + it * 256;           // 0..2047
        int r = idx >> 5, c = idx & 31;     // r: t-local, c: d-local
        tile[c][r] = qkv[((size_t)(b * T_ + t0 + r)) * QKVD_ + voff + d0 + c];
    }
    __syncthreads();
#pragma unroll
    for (int it = 0; it < 8; it++) {
        int idx = tid + it * 256;           // 0..2047
        int dr = idx >> 6, tc = idx & 63;
        VT[((size_t)(bh) * HD_ + d0 + dr) * T_ + t0 + tc] = __float2half(tile[dr][tc]);
    }
}

// ---------------- flash attention via mma.sync fp16, K-tile = 128 ----------------
#define QPITCH 272        // bytes per 128-fp16 row (256B + 16 pad)
#define SM_Q 0
#define SM_STAGE0 34816
#define OFF_K 0
#define OFF_V 34816
#define KV_STAGE 69632
#define FA_SMEM (34816 + 2 * 69632)   // 174080

__device__ __forceinline__ void fa_load_kv(
    uint32_t st, const __half* Kg, const __half* Vg, int kt, int tid)
{
#pragma unroll
    for (int j = 0; j < 8; j++) {
        int idx = tid + j * 256;            // 0..2047
        int r = idx >> 4, c = idx & 15;
        cp16(st + OFF_K + (uint32_t)r * QPITCH + c * 16,
             Kg + ((size_t)(kt * 128 + r)) * HD_ + c * 8);
        cp16(st + OFF_V + (uint32_t)r * QPITCH + c * 16,
             Vg + (size_t)r * T_ + kt * 128 + c * 8);
    }
}

__global__ __launch_bounds__(256, 1) void flash_mma(
    const __half* __restrict__ Qs, const __half* __restrict__ Ks,
    const __half* __restrict__ VT, __half* __restrict__ Ys)
{
    extern __shared__ char sm[];
    const uint32_t sb = smem_u32(sm);
    const int tid = threadIdx.x, w = tid >> 5, lane = tid & 31;
    // heavy tiles first
    const int qt = gridDim.x - 1 - blockIdx.x;
    const int h = blockIdx.y, b = blockIdx.z;
    const int q0 = qt * 128;
    const int hk = h >> 2;
    const __half* Qg = Qs + ((size_t)(b * NH_ + h) * T_ + q0) * HD_;
    const __half* Kg = Ks + (size_t)(b * KVH_ + hk) * T_ * HD_;
    const __half* Vg = VT + (size_t)(b * KVH_ + hk) * HD_ * T_;

#pragma unroll
    for (int j = 0; j < 8; j++) {
        int idx = tid + j * 256;            // 0..2047
        int r = idx >> 4, c = idx & 15;
        cp16(sb + SM_Q + (uint32_t)r * QPITCH + c * 16, Qg + (size_t)r * HD_ + c * 8);
    }
    fa_load_kv(sb + SM_STAGE0, Kg, Vg, 0, tid);
    cp_commit();

    float O[16][4];
#pragma unroll
    for (int i = 0; i < 16; i++)
#pragma unroll
        for (int j = 0; j < 4; j++) O[i][j] = 0.f;
    float m0 = -1e30f, m1 = -1e30f, l0 = 0.f, l1 = 0.f;

    const int er = lane >> 2, ec2 = (lane & 3) * 2;
    const int a_row = lane & 15, a_kh = lane >> 4;
    const int b_row = (lane & 7) | ((lane >> 1) & 8), b_kh = (lane >> 3) & 1;
    const int row0 = q0 + w * 16 + er;
    const int nkt = qt + 1;

    uint32_t qf[8][4];      // hoisted Q fragments

    for (int kt = 0; kt < nkt; kt++) {
        if (kt + 1 < nkt) {
            fa_load_kv(sb + SM_STAGE0 + ((kt + 1) & 1) * KV_STAGE, Kg, Vg, kt + 1, tid);
            cp_commit();
            CP_WAIT(1);
        } else {
            CP_WAIT(0);
        }
        __syncthreads();

        if (kt == 0) {
#pragma unroll
            for (int ks = 0; ks < 8; ks++) {
                uint32_t qoff = (uint32_t)(w * 16 + a_row) * QPITCH + ks * 32 + a_kh * 16;
                ldm4(qf[ks], sb + SM_Q + qoff);
            }
        }

        const uint32_t st = sb + SM_STAGE0 + (kt & 1) * KV_STAGE;

        // ---- S = Q K^T over 128 k-cols ----
        float s[16][4];
#pragma unroll
        for (int i = 0; i < 16; i++)
#pragma unroll
            for (int j = 0; j < 4; j++) s[i][j] = 0.f;
#pragma unroll
        for (int ks = 0; ks < 8; ks++) {
#pragma unroll
            for (int ng = 0; ng < 8; ng++) {
                uint32_t bh[4];
                uint32_t koff = (uint32_t)(ng * 16 + b_row) * QPITCH + ks * 32 + b_kh * 16;
                ldm4(bh, st + OFF_K + koff);
                mma16816h(s[2 * ng],     qf[ks], &bh[0]);
                mma16816h(s[2 * ng + 1], qf[ks], &bh[2]);
            }
        }

        // ---- causal mask (only the diagonal tile needs it) ----
        if (kt == qt) {
#pragma unroll
            for (int nf = 0; nf < 16; nf++) {
                int c0 = kt * 128 + nf * 8 + ec2;
                if (c0     > row0)     s[nf][0] = -1e30f;
                if (c0 + 1 > row0)     s[nf][1] = -1e30f;
                if (c0     > row0 + 8) s[nf][2] = -1e30f;
                if (c0 + 1 > row0 + 8) s[nf][3] = -1e30f;
            }
        }

        // ---- streaming softmax (quad-local) ----
        float mx0 = -1e30f, mx1 = -1e30f;
#pragma unroll
        for (int nf = 0; nf < 16; nf++) {
            mx0 = fmaxf(mx0, fmaxf(s[nf][0], s[nf][1]));
            mx1 = fmaxf(mx1, fmaxf(s[nf][2], s[nf][3]));
        }
        mx0 = fmaxf(mx0, __shfl_xor_sync(0xffffffffu, mx0, 1));
        mx0 = fmaxf(mx0, __shfl_xor_sync(0xffffffffu, mx0, 2));
        mx1 = fmaxf(mx1, __shfl_xor_sync(0xffffffffu, mx1, 1));
        mx1 = fmaxf(mx1, __shfl_xor_sync(0xffffffffu, mx1, 2));
        float mn0 = fmaxf(m0, mx0), mn1 = fmaxf(m1, mx1);
        float al0 = __expf(m0 - mn0), al1 = __expf(m1 - mn1);
        m0 = mn0; m1 = mn1;

        float ls0 = 0.f, ls1 = 0.f;
        uint32_t pa[8][4];
#pragma unroll
        for (int nf = 0; nf < 16; nf++) {
            float p0 = __expf(s[nf][0] - mn0);
            float p1 = __expf(s[nf][1] - mn0);
            float p2 = __expf(s[nf][2] - mn1);
            float p3 = __expf(s[nf][3] - mn1);
            ls0 += p0 + p1; ls1 += p2 + p3;
            int q = nf >> 1, base = (nf & 1) * 2;
            pa[q][base]     = pack_h2(p0, p1);
            pa[q][base + 1] = pack_h2(p2, p3);
        }
        ls0 += __shfl_xor_sync(0xffffffffu, ls0, 1);
        ls0 += __shfl_xor_sync(0xffffffffu, ls0, 2);
        ls1 += __shfl_xor_sync(0xffffffffu, ls1, 1);
        ls1 += __shfl_xor_sync(0xffffffffu, ls1, 2);
        l0 = l0 * al0 + ls0;
        l1 = l1 * al1 + ls1;
#pragma unroll
        for (int df = 0; df < 16; df++) {
            O[df][0] *= al0; O[df][1] *= al0;
            O[df][2] *= al1; O[df][3] *= al1;
        }

        // ---- O += P V over 128 k-rows ----
#pragma unroll
        for (int q = 0; q < 8; q++) {
#pragma unroll
            for (int ng = 0; ng < 8; ng++) {
                uint32_t vh[4];
                uint32_t voff = (uint32_t)(ng * 16 + b_row) * QPITCH + q * 32 + b_kh * 16;
                ldm4(vh, st + OFF_V + voff);
                mma16816h(O[2 * ng],     pa[q], &vh[0]);
                mma16816h(O[2 * ng + 1], pa[q], &vh[2]);
            }
        }
        __syncthreads();
    }

    float il0 = 1.0f / l0, il1 = 1.0f / l1;
    size_t r0 = (size_t)(b * T_ + q0 + w * 16 + er);
    __half* y0 = Ys + r0 * K_ + h * HD_;
    __half* y1 = Ys + (r0 + 8) * K_ + h * HD_;
#pragma unroll
    for (int nf = 0; nf < 16; nf++) {
        int co = nf * 8 + ec2;
        *(uint32_t*)(y0 + co) = pack_h2(O[nf][0] * il0, O[nf][1] * il0);
        *(uint32_t*)(y1 + co) = pack_h2(O[nf][2] * il1, O[nf][3] * il1);
    }
}

// ---------------- launch ----------------
extern "C" void kernel_launch(void* const* d_in, const int* in_sizes, int n_in,
                              void* d_out, int out_size)
{
    const float* x      = (const float*)d_in[0];
    const float* w_qkv  = (const float*)d_in[1];
    const float* w_proj = (const float*)d_in[2];
    const float* qw     = (const float*)d_in[3];
    const float* kw     = (const float*)d_in[4];
    const float* fcos   = (const float*)d_in[5];
    const float* fsin   = (const float*)d_in[6];
    float* out = (float*)d_out;

    float* p_qkv;
    __half *p_xs, *p_wqkvs, *p_wprojs, *p_ysh, *p_qs, *p_ks, *p_vt;
    cudaGetSymbolAddress((void**)&p_qkv,    g_qkv);
    cudaGetSymbolAddress((void**)&p_xs,     g_xs);
    cudaGetSymbolAddress((void**)&p_wqkvs,  g_wqkvs);
    cudaGetSymbolAddress((void**)&p_wprojs, g_wprojs);
    cudaGetSymbolAddress((void**)&p_ysh,    g_ysh);
    cudaGetSymbolAddress((void**)&p_qs,     g_qs);
    cudaGetSymbolAddress((void**)&p_ks,     g_ks);
    cudaGetSymbolAddress((void**)&p_vt,     g_vt);

    const int GEMM_SMEM = 2 * GREGION;   // 208896
    cudaFuncSetAttribute(gemm_mma, cudaFuncAttributeMaxDynamicSharedMemorySize, GEMM_SMEM);
    cudaFuncSetAttribute(flash_mma, cudaFuncAttributeMaxDynamicSharedMemorySize, FA_SMEM);

    // 0) fp16 conversions (single kernel)
    conv_all<<<(CTOT + 255) / 256, 256>>>(x, w_qkv, w_proj, p_xs, p_wqkvs, p_wprojs);

    // 1) qkv = x @ w_qkv^T
    gemm_mma<<<dim3(QKVD_ / 256, BT_ / 128), 256, GEMM_SMEM>>>(p_xs, p_wqkvs, p_qkv, QKVD_);

    // 2) RoPE + RMSNorm -> fp16 Q (pre-scaled), K; V transpose
    qk_transform<<<dim3(BT_, 5), 128>>>(p_qkv, qw, kw, fcos, fsin, p_qs, p_ks);
    v_transpose<<<dim3(T_ / 64, HD_ / 32, B_ * KVH_), 256>>>(p_qkv, p_vt);

    // 3) causal flash attention (fp16 tensor cores, KT=128) -> y fp16
    flash_mma<<<dim3(T_ / 128, NH_, B_), 256, FA_SMEM>>>(p_qs, p_ks, p_vt, p_ysh);

    // 4) out = y @ w_proj^T
    gemm_mma<<<dim3(C_ / 256, BT_ / 128), 256, GEMM_SMEM>>>(p_ysh, p_wprojs, out, C_);
}